// round 11
// baseline (speedup 1.0000x reference)
#include <cuda_runtime.h>
#include <cuda_bf16.h>
#include <cstdint>

#define NN   65536
#define EE   524288
#define DIN  128
#define HD   256
#define NB   8
#define MROW 2048   // NB * HD

// ======================= helpers =======================
__device__ __forceinline__ void split_bf16(float v, __nv_bfloat16& h, __nv_bfloat16& l) {
    h = __float2bfloat16(v);
    l = __float2bfloat16(v - __bfloat162float(h));
}

__device__ __forceinline__ void mma16816(float* c, const uint32_t* a, const uint32_t* b) {
    asm volatile(
        "mma.sync.aligned.m16n8k16.row.col.f32.bf16.bf16.f32 "
        "{%0,%1,%2,%3}, {%4,%5,%6,%7}, {%8,%9}, {%0,%1,%2,%3};"
        : "+f"(c[0]), "+f"(c[1]), "+f"(c[2]), "+f"(c[3])
        : "r"(a[0]), "r"(a[1]), "r"(a[2]), "r"(a[3]), "r"(b[0]), "r"(b[1]));
}

__device__ __forceinline__ void ldsm4(uint32_t* r, uint32_t addr) {
    asm volatile("ldmatrix.sync.aligned.m8n8.x4.shared.b16 {%0,%1,%2,%3}, [%4];"
        : "=r"(r[0]), "=r"(r[1]), "=r"(r[2]), "=r"(r[3]) : "r"(addr));
}

__device__ __forceinline__ uint32_t smem_u32(const void* p) {
    uint32_t a;
    asm("{ .reg .u64 t; cvta.to.shared.u64 t, %1; cvt.u32.u64 %0, t; }" : "=r"(a) : "l"(p));
    return a;
}

__device__ __forceinline__ void cpa16(uint32_t dst, const void* src) {
    asm volatile("cp.async.cg.shared.global [%0], [%1], 16;" :: "r"(dst), "l"(src));
}
#define CPA_COMMIT() asm volatile("cp.async.commit_group;" ::: "memory")
#define CPA_WAIT1()  asm volatile("cp.async.wait_group 1;" ::: "memory")
#define CPA_WAIT0()  asm volatile("cp.async.wait_group 0;" ::: "memory")

// smem tiling: 4 tiles (Ah, Al, Bh, Bl), each 128 rows x 40 bf16
#define TSTRIDE 40
#define TE (128 * TSTRIDE)
#define BUFE (4 * TE)
#define STAGE_BYTES (BUFE * 2)              // 40960
#define GEMM_SMEM_BYTES (2 * STAGE_BYTES)   // 81920
#define OFFB_AH 0
#define OFFB_AL (TE * 2)
#define OFFB_BH (2 * TE * 2)
#define OFFB_BL (3 * TE * 2)

// ======================= static device scratch =======================
__device__ __nv_bfloat16 d_h02[NN * 256];
__device__ __nv_bfloat16 d_agg2[NN * 512];
__device__ __nv_bfloat16 d_h2A[NN * 512];
__device__ __nv_bfloat16 d_h2B[NN * 512];
__device__ __nv_bfloat16 d_m1A2[(size_t)MROW * 16384];
__device__ __nv_bfloat16 d_w2[8][256 * 512];
__device__ __nv_bfloat16 d_m1w2[(size_t)256 * 16384];
__device__ int   d_cnt[NN];
__device__ int   d_off[NN + 1];
__device__ int   d_cur[NN];
__device__ int   d_csr[EE];
__device__ float d_invcnt[NN];
__device__ float d_m1[MROW * HD];
__device__ float d_y[MROW];

// ======================= small kernels =======================
__global__ void zero_f(float* __restrict__ p, int n) {
    int i = blockIdx.x * blockDim.x + threadIdx.x;
    if (i < n) p[i] = 0.0f;
}
__global__ void zero_i(int* __restrict__ p, int n) {
    int i = blockIdx.x * blockDim.x + threadIdx.x;
    if (i < n) p[i] = 0;
}

__global__ void concat2_kernel(const float* __restrict__ x, const float* __restrict__ g0,
                               const float* __restrict__ g1, const float* __restrict__ g2) {
    int i = blockIdx.x * blockDim.x + threadIdx.x;
    if (i >= NN * 128) return;
    int n = i >> 7, j = i & 127;
    float v;
    if (j < 32)       v = x[n * 32 + j];
    else if (j < 64)  v = g0[n * 32 + (j - 32)];
    else if (j < 96)  v = g1[n * 32 + (j - 64)];
    else              v = g2[n * 32 + (j - 96)];
    __nv_bfloat16 h, l; split_bf16(v, h, l);
    d_h02[n * 256 + j]       = h;
    d_h02[n * 256 + 128 + j] = l;
}

__global__ void conv_w(const float* __restrict__ W, __nv_bfloat16* __restrict__ out, int K) {
    int i = blockIdx.x * blockDim.x + threadIdx.x;
    if (i >= K * 256) return;
    int n = i & 255, k = i >> 8;
    float v = W[k * 256 + n];
    __nv_bfloat16 h, l; split_bf16(v, h, l);
    out[(size_t)n * 2 * K + k]     = h;
    out[(size_t)n * 2 * K + K + k] = l;
}

__global__ void count_kernel(const int* __restrict__ dst) {
    int e = blockIdx.x * blockDim.x + threadIdx.x;
    if (e < EE) atomicAdd(&d_cnt[dst[e]], 1);
}

// exclusive scan of d_cnt -> d_off; also emits invcnt and zeroes cur (verified in R8)
__global__ void scan_kernel() {
    __shared__ int s[1024];
    int t = threadIdx.x;
    int base = t * 64;
    int sum = 0;
    for (int i = 0; i < 64; i++) sum += d_cnt[base + i];
    s[t] = sum;
    __syncthreads();
    for (int o = 1; o < 1024; o <<= 1) {
        int v = (t >= o) ? s[t - o] : 0;
        __syncthreads();
        s[t] += v;
        __syncthreads();
    }
    int run = s[t] - sum;
    for (int i = 0; i < 64; i++) {
        int c = d_cnt[base + i];
        d_off[base + i] = run;
        run += c;
        d_cur[base + i] = 0;
        d_invcnt[base + i] = 1.0f / fmaxf((float)c, 1.0f);
    }
    if (t == 1023) d_off[NN] = run;
}

__global__ void fill_kernel(const int* __restrict__ src, const int* __restrict__ dst) {
    int e = blockIdx.x * blockDim.x + threadIdx.x;
    if (e >= EE) return;
    int d = dst[e];
    int p = atomicAdd(&d_cur[d], 1);
    d_csr[d_off[d] + p] = src[e];
}

// CSR mean-aggregation: warp per node, neighbor loop unrolled x2.
// Rows are [hi(D) | lo(D)] bf16; coalesced bf16x2 loads.
template <int D>
__global__ void agg_csr(const __nv_bfloat16* __restrict__ H2,
                        __nv_bfloat16* __restrict__ out2) {
    int w = (blockIdx.x * blockDim.x + threadIdx.x) >> 5;
    int lane = threadIdx.x & 31;
    if (w >= NN) return;
    int s0 = __ldg(&d_off[w]), s1 = __ldg(&d_off[w + 1]);
    constexpr int R = D / 64;
    float a0[R], a1[R];
#pragma unroll
    for (int r = 0; r < R; r++) { a0[r] = 0.0f; a1[r] = 0.0f; }

    int p = s0;
    for (; p + 2 <= s1; p += 2) {
        int nbA = __ldg(&d_csr[p]);
        int nbB = __ldg(&d_csr[p + 1]);
        const __nv_bfloat16* baseA = H2 + (size_t)nbA * (2 * D);
        const __nv_bfloat16* baseB = H2 + (size_t)nbB * (2 * D);
#pragma unroll
        for (int r = 0; r < R; r++) {
            int c2 = (lane + r * 32) * 2;
            __nv_bfloat162 hA = *reinterpret_cast<const __nv_bfloat162*>(baseA + c2);
            __nv_bfloat162 lA = *reinterpret_cast<const __nv_bfloat162*>(baseA + D + c2);
            __nv_bfloat162 hB = *reinterpret_cast<const __nv_bfloat162*>(baseB + c2);
            __nv_bfloat162 lB = *reinterpret_cast<const __nv_bfloat162*>(baseB + D + c2);
            float2 hfA = __bfloat1622float2(hA);
            float2 lfA = __bfloat1622float2(lA);
            float2 hfB = __bfloat1622float2(hB);
            float2 lfB = __bfloat1622float2(lB);
            a0[r] += (hfA.x + lfA.x) + (hfB.x + lfB.x);
            a1[r] += (hfA.y + lfA.y) + (hfB.y + lfB.y);
        }
    }
    if (p < s1) {
        int nb = __ldg(&d_csr[p]);
        const __nv_bfloat16* base = H2 + (size_t)nb * (2 * D);
#pragma unroll
        for (int r = 0; r < R; r++) {
            int c2 = (lane + r * 32) * 2;
            __nv_bfloat162 hv = *reinterpret_cast<const __nv_bfloat162*>(base + c2);
            __nv_bfloat162 lv = *reinterpret_cast<const __nv_bfloat162*>(base + D + c2);
            float2 hf = __bfloat1622float2(hv);
            float2 lf = __bfloat1622float2(lv);
            a0[r] += hf.x + lf.x;
            a1[r] += hf.y + lf.y;
        }
    }

    float ic = d_invcnt[w];
    __nv_bfloat16* ob = out2 + (size_t)w * (2 * D);
#pragma unroll
    for (int r = 0; r < R; r++) {
        float v0 = a0[r] * ic, v1 = a1[r] * ic;
        __nv_bfloat16 h0, l0, h1, l1;
        split_bf16(v0, h0, l0);
        split_bf16(v1, h1, l1);
        int c2 = (lane + r * 32) * 2;
        *reinterpret_cast<__nv_bfloat162*>(ob + c2)     = __nv_bfloat162{h0, h1};
        *reinterpret_cast<__nv_bfloat162*>(ob + D + c2) = __nv_bfloat162{l0, l1};
    }
}

// ======================= GEMM compute core (ldmatrix, 3-term split) ===============
// Block: 256 threads, 8 warps (4m x 2n). Warp tile 32 x 64. Chunk = 32 K-cols.
__device__ __forceinline__ void gemm_chunk(uint32_t stage, int wm, int wn, int lane,
                                           float acc[2][8][4]) {
    const uint32_t aBase = stage + OFFB_AH +
        (uint32_t)(((wm * 32 + (lane & 15)) * TSTRIDE + (lane >> 4) * 8) * 2);
    const uint32_t bBase = stage + OFFB_BH +
        (uint32_t)(((wn * 64 + (lane >> 4) * 8 + (lane & 7)) * TSTRIDE + ((lane >> 3) & 1) * 8) * 2);
    const uint32_t loA = OFFB_AL - OFFB_AH;
    const uint32_t loB = OFFB_BL - OFFB_BH;

#pragma unroll
    for (int kk = 0; kk < 32; kk += 16) {
        uint32_t afh[2][4], afl[2][4];
#pragma unroll
        for (int mt = 0; mt < 2; mt++) {
            uint32_t a = aBase + (uint32_t)((mt * 16 * TSTRIDE + kk) * 2);
            ldsm4(afh[mt], a);
            ldsm4(afl[mt], a + loA);
        }
#pragma unroll
        for (int np = 0; np < 4; np++) {
            uint32_t b = bBase + (uint32_t)((np * 16 * TSTRIDE + kk) * 2);
            uint32_t bh[4], bl[4];
            ldsm4(bh, b);
            ldsm4(bl, b + loB);
#pragma unroll
            for (int mt = 0; mt < 2; mt++) {
                mma16816(acc[mt][np * 2],     afh[mt], &bh[0]);
                mma16816(acc[mt][np * 2 + 1], afh[mt], &bh[2]);
                mma16816(acc[mt][np * 2],     afl[mt], &bh[0]);
                mma16816(acc[mt][np * 2 + 1], afl[mt], &bh[2]);
                mma16816(acc[mt][np * 2],     afh[mt], &bl[0]);
                mma16816(acc[mt][np * 2 + 1], afh[mt], &bl[2]);
            }
        }
    }
}

// ======================= SAGE layer GEMM (cp.async double-buffered) ===============
template <int K>
__global__ __launch_bounds__(256, 2)
void sage_mma(const __nv_bfloat16* __restrict__ agg2, const __nv_bfloat16* __restrict__ h2,
              const __nv_bfloat16* __restrict__ Wl2, const __nv_bfloat16* __restrict__ Wr2,
              const float* __restrict__ bias, __nv_bfloat16* __restrict__ out2, int mode) {
    extern __shared__ __nv_bfloat16 smdyn[];
    const uint32_t smbase = smem_u32(smdyn);

    const int tid = threadIdx.x;
    const int wid = tid >> 5, lane = tid & 31;
    const int wm = wid & 3, wn = wid >> 2;
    const int lr = lane >> 2, lq = lane & 3;
    const int bm = blockIdx.x * 128;
    const int bn = blockIdx.y * 128;
    constexpr int K2 = 2 * K;
    constexpr int CPS = K / 32;
    constexpr int NCH = 2 * CPS;

    const int r0 = tid >> 2;
    const int cb = (tid & 3) * 8;

    float acc[2][8][4];
#pragma unroll
    for (int i = 0; i < 2; i++)
#pragma unroll
        for (int j = 0; j < 8; j++)
#pragma unroll
            for (int t = 0; t < 4; t++) acc[i][j][t] = 0.0f;

    auto prefetch = [&](int ci, int b) {
        const __nv_bfloat16* Asrc = (ci < CPS) ? agg2 : h2;
        const __nv_bfloat16* Bsrc = (ci < CPS) ? Wl2 : Wr2;
        int c = ci & (CPS - 1);
        uint32_t sb = smbase + (uint32_t)b * STAGE_BYTES;
#pragma unroll
        for (int half = 0; half < 2; half++) {
            int r = r0 + half * 64;
            uint32_t so = (uint32_t)(r * TSTRIDE + cb) * 2;
            const __nv_bfloat16* Ap = Asrc + (size_t)(bm + r) * K2 + c * 32 + cb;
            const __nv_bfloat16* Bp = Bsrc + (size_t)(bn + r) * K2 + c * 32 + cb;
            cpa16(sb + OFFB_AH + so, Ap);
            cpa16(sb + OFFB_AL + so, Ap + K);
            cpa16(sb + OFFB_BH + so, Bp);
            cpa16(sb + OFFB_BL + so, Bp + K);
        }
        CPA_COMMIT();
    };

    prefetch(0, 0);
    for (int i = 0; i < NCH; i++) {
        int b = i & 1;
        if (i + 1 < NCH) { prefetch(i + 1, b ^ 1); CPA_WAIT1(); }
        else             { CPA_WAIT0(); }
        __syncthreads();
        gemm_chunk(smbase + (uint32_t)b * STAGE_BYTES, wm, wn, lane, acc);
        __syncthreads();
    }

    // epilogue: bias + relu + hi/lo split
#pragma unroll
    for (int mt = 0; mt < 2; mt++) {
#pragma unroll
        for (int nt = 0; nt < 8; nt++) {
            int col = bn + wn * 64 + nt * 8 + lq * 2;
            float bs0 = __ldg(&bias[col]), bs1 = __ldg(&bias[col + 1]);
#pragma unroll
            for (int half = 0; half < 2; half++) {
                int grow = bm + wm * 32 + mt * 16 + lr + half * 8;
                float v0 = fmaxf(acc[mt][nt][half * 2 + 0] + bs0, 0.0f);
                float v1 = fmaxf(acc[mt][nt][half * 2 + 1] + bs1, 0.0f);
                __nv_bfloat16 h0, l0, h1, l1;
                split_bf16(v0, h0, l0);
                split_bf16(v1, h1, l1);
                if (mode == 0) {
                    *reinterpret_cast<__nv_bfloat162*>(&out2[(size_t)grow * 512 + col]) =
                        __nv_bfloat162{h0, h1};
                    *reinterpret_cast<__nv_bfloat162*>(&out2[(size_t)grow * 512 + 256 + col]) =
                        __nv_bfloat162{l0, l1};
                } else {
                    int R = grow >> 5;
                    int m = ((grow & 31) << 8) + col;
                    *reinterpret_cast<__nv_bfloat162*>(&out2[(size_t)R * 16384 + m]) =
                        __nv_bfloat162{h0, h1};
                    *reinterpret_cast<__nv_bfloat162*>(&out2[(size_t)R * 16384 + 8192 + m]) =
                        __nv_bfloat162{l0, l1};
                }
            }
        }
    }
}

// ======================= mlp1 GEMM (split-K=8, cp.async, atomic accum) ============
__global__ __launch_bounds__(256, 2)
void mlp1_mma(const __nv_bfloat16* __restrict__ A2, const __nv_bfloat16* __restrict__ W2t,
              float* __restrict__ C) {
    extern __shared__ __nv_bfloat16 smdyn[];
    const uint32_t smbase = smem_u32(smdyn);

    const int tid = threadIdx.x;
    const int wid = tid >> 5, lane = tid & 31;
    const int wm = wid & 3, wn = wid >> 2;
    const int lr = lane >> 2, lq = lane & 3;
    const int bm = blockIdx.x * 128;
    const int bn = blockIdx.y * 128;
    const int g0 = blockIdx.z * 32;
    const int NCH = 32;

    const int r0 = tid >> 2;
    const int cb = (tid & 3) * 8;

    float acc[2][8][4];
#pragma unroll
    for (int i = 0; i < 2; i++)
#pragma unroll
        for (int j = 0; j < 8; j++)
#pragma unroll
            for (int t = 0; t < 4; t++) acc[i][j][t] = 0.0f;

    auto prefetch = [&](int i, int b) {
        int c = g0 + i;
        uint32_t sb = smbase + (uint32_t)b * STAGE_BYTES;
#pragma unroll
        for (int half = 0; half < 2; half++) {
            int r = r0 + half * 64;
            uint32_t so = (uint32_t)(r * TSTRIDE + cb) * 2;
            const __nv_bfloat16* Ap = A2 + (size_t)(bm + r) * 16384 + c * 32 + cb;
            const __nv_bfloat16* Bp = W2t + (size_t)(bn + r) * 16384 + c * 32 + cb;
            cpa16(sb + OFFB_AH + so, Ap);
            cpa16(sb + OFFB_AL + so, Ap + 8192);
            cpa16(sb + OFFB_BH + so, Bp);
            cpa16(sb + OFFB_BL + so, Bp + 8192);
        }
        CPA_COMMIT();
    };

    prefetch(0, 0);
    for (int i = 0; i < NCH; i++) {
        int b = i & 1;
        if (i + 1 < NCH) { prefetch(i + 1, b ^ 1); CPA_WAIT1(); }
        else             { CPA_WAIT0(); }
        __syncthreads();
        gemm_chunk(smbase + (uint32_t)b * STAGE_BYTES, wm, wn, lane, acc);
        __syncthreads();
    }

#pragma unroll
    for (int mt = 0; mt < 2; mt++) {
#pragma unroll
        for (int nt = 0; nt < 8; nt++) {
            int col = bn + wn * 64 + nt * 8 + lq * 2;
#pragma unroll
            for (int half = 0; half < 2; half++) {
                int row = bm + wm * 32 + mt * 16 + lr + half * 8;
                atomicAdd(&C[(size_t)row * 256 + col],     acc[mt][nt][half * 2 + 0]);
                atomicAdd(&C[(size_t)row * 256 + col + 1], acc[mt][nt][half * 2 + 1]);
            }
        }
    }
}

// ======================= tail kernels =======================
__global__ void mlp1_finalize(const float* __restrict__ M1, const float* __restrict__ b1,
                              const float* __restrict__ W2, const float* __restrict__ b2,
                              float* __restrict__ y) {
    int row = (blockIdx.x * blockDim.x + threadIdx.x) >> 5;
    int lane = threadIdx.x & 31;
    if (row >= MROW) return;
    float s = 0.0f;
    for (int c = lane; c < HD; c += 32)
        s += fmaxf(M1[row * HD + c] + b1[c], 0.0f) * W2[c];
#pragma unroll
    for (int o = 16; o; o >>= 1) s += __shfl_xor_sync(0xffffffffu, s, o);
    if (lane == 0) y[row] = s + b2[0];
}

// fused batchnorm + relu + mlp2 (single block, 256 threads; verified in R8)
__global__ void tail_kernel(const float* __restrict__ y, const float* __restrict__ gamma,
                            const float* __restrict__ beta,
                            const float* __restrict__ W1, const float* __restrict__ b1,
                            const float* __restrict__ W2, const float* __restrict__ b2,
                            float* __restrict__ out) {
    __shared__ float ybn[NB][HD];
    __shared__ float zs[NB][HD];
    int j = threadIdx.x;
    float v[NB];
    float m = 0.0f;
#pragma unroll
    for (int b = 0; b < NB; b++) { v[b] = y[b * HD + j]; m += v[b]; }
    m *= (1.0f / NB);
    float var = 0.0f;
#pragma unroll
    for (int b = 0; b < NB; b++) { float d = v[b] - m; var += d * d; }
    var *= (1.0f / NB);
    float inv = rsqrtf(var + 1e-5f) * gamma[j];
    float be = beta[j];
#pragma unroll
    for (int b = 0; b < NB; b++)
        ybn[b][j] = fmaxf((v[b] - m) * inv + be, 0.0f);
    __syncthreads();

    float z[NB];
#pragma unroll
    for (int b = 0; b < NB; b++) z[b] = b1[j];
    for (int hh = 0; hh < HD; hh++) {
        float w = W1[hh * HD + j];
#pragma unroll
        for (int b = 0; b < NB; b++) z[b] += ybn[b][hh] * w;
    }
#pragma unroll
    for (int b = 0; b < NB; b++) zs[b][j] = fmaxf(z[b], 0.0f);
    __syncthreads();

    if (j < NB * 8) {
        int b = j >> 3, o = j & 7;
        float s = b2[o];
        for (int jj = 0; jj < HD; jj++) s += zs[b][jj] * W2[jj * 8 + o];
        out[j] = s;
    }
}

// ======================= host launch =======================
extern "C" void kernel_launch(void* const* d_in, const int* in_sizes, int n_in,
                              void* d_out, int out_size) {
    const float* x    = (const float*)d_in[0];
    const float* g0   = (const float*)d_in[1];
    const float* g1   = (const float*)d_in[2];
    const float* g2   = (const float*)d_in[3];
    const int*   esrc = (const int*)d_in[4];
    const int*   edst = (const int*)d_in[5];
    const float* Wl0  = (const float*)d_in[6];
    const float* Wr0  = (const float*)d_in[7];
    const float* b0   = (const float*)d_in[8];
    const float* Wl1  = (const float*)d_in[9];
    const float* Wr1  = (const float*)d_in[10];
    const float* b1   = (const float*)d_in[11];
    const float* Wl2  = (const float*)d_in[12];
    const float* Wr2  = (const float*)d_in[13];
    const float* b2   = (const float*)d_in[14];
    const float* Wl3  = (const float*)d_in[15];
    const float* Wr3  = (const float*)d_in[16];
    const float* b3   = (const float*)d_in[17];
    const float* m1W1 = (const float*)d_in[18];
    const float* m1b1 = (const float*)d_in[19];
    const float* m1W2 = (const float*)d_in[20];
    const float* m1b2 = (const float*)d_in[21];
    const float* gam  = (const float*)d_in[22];
    const float* bet  = (const float*)d_in[23];
    const float* m2W1 = (const float*)d_in[24];
    const float* m2b1 = (const float*)d_in[25];
    const float* m2W2 = (const float*)d_in[26];
    const float* m2b2 = (const float*)d_in[27];

    __nv_bfloat16 *h02, *agg2, *h2A, *h2B, *m1A2, *w2, *m1w2;
    int *cnt;
    float *m1, *y;
    cudaGetSymbolAddress((void**)&h02, d_h02);
    cudaGetSymbolAddress((void**)&agg2, d_agg2);
    cudaGetSymbolAddress((void**)&h2A, d_h2A);
    cudaGetSymbolAddress((void**)&h2B, d_h2B);
    cudaGetSymbolAddress((void**)&m1A2, d_m1A2);
    cudaGetSymbolAddress((void**)&w2, d_w2);
    cudaGetSymbolAddress((void**)&m1w2, d_m1w2);
    cudaGetSymbolAddress((void**)&cnt, d_cnt);
    cudaGetSymbolAddress((void**)&m1, d_m1);
    cudaGetSymbolAddress((void**)&y, d_y);

    cudaFuncSetAttribute(sage_mma<128>, cudaFuncAttributeMaxDynamicSharedMemorySize, GEMM_SMEM_BYTES);
    cudaFuncSetAttribute(sage_mma<256>, cudaFuncAttributeMaxDynamicSharedMemorySize, GEMM_SMEM_BYTES);
    cudaFuncSetAttribute(mlp1_mma,      cudaFuncAttributeMaxDynamicSharedMemorySize, GEMM_SMEM_BYTES);

    __nv_bfloat16* wl[4] = {w2 + 0 * 256 * 512, w2 + 2 * 256 * 512, w2 + 4 * 256 * 512, w2 + 6 * 256 * 512};
    __nv_bfloat16* wr[4] = {w2 + 1 * 256 * 512, w2 + 3 * 256 * 512, w2 + 5 * 256 * 512, w2 + 7 * 256 * 512};

    // --- CSR build + layer-0 aggregation first: launch #6 = agg_csr<128> for ncu ---
    concat2_kernel<<<(NN * 128) / 256, 256>>>(x, g0, g1, g2);   // 1
    zero_i<<<NN / 256, 256>>>(cnt, NN);                          // 2
    count_kernel<<<EE / 256, 256>>>(edst);                       // 3
    scan_kernel<<<1, 1024>>>();                                  // 4 (off + invcnt + cur)
    fill_kernel<<<EE / 256, 256>>>(esrc, edst);                  // 5
    agg_csr<128><<<NN / 8, 256>>>(h02, agg2);                    // 6  <-- ncu capture

    // weight conversion (needed from launch #16 onward)
    conv_w<<<128, 256>>>(Wl0, wl[0], 128);
    conv_w<<<128, 256>>>(Wr0, wr[0], 128);
    conv_w<<<256, 256>>>(Wl1, wl[1], 256);
    conv_w<<<256, 256>>>(Wr1, wr[1], 256);
    conv_w<<<256, 256>>>(Wl2, wl[2], 256);
    conv_w<<<256, 256>>>(Wr2, wr[2], 256);
    conv_w<<<256, 256>>>(Wl3, wl[3], 256);
    conv_w<<<256, 256>>>(Wr3, wr[3], 256);
    conv_w<<<8192, 256>>>(m1W1, m1w2, 8192);

    sage_mma<128><<<dim3(NN / 128, 2), 256, GEMM_SMEM_BYTES>>>(agg2, h02, wl[0], wr[0], b0, h2A, 0);
    agg_csr<256><<<NN / 8, 256>>>(h2A, agg2);
    sage_mma<256><<<dim3(NN / 128, 2), 256, GEMM_SMEM_BYTES>>>(agg2, h2A, wl[1], wr[1], b1, h2B, 0);
    agg_csr<256><<<NN / 8, 256>>>(h2B, agg2);
    sage_mma<256><<<dim3(NN / 128, 2), 256, GEMM_SMEM_BYTES>>>(agg2, h2B, wl[2], wr[2], b2, h2A, 0);
    agg_csr<256><<<NN / 8, 256>>>(h2A, agg2);
    sage_mma<256><<<dim3(NN / 128, 2), 256, GEMM_SMEM_BYTES>>>(agg2, h2A, wl[3], wr[3], b3, m1A2, 1);

    zero_f<<<(MROW * HD) / 256, 256>>>(m1, MROW * HD);
    mlp1_mma<<<dim3(MROW / 128, 2, 8), 256, GEMM_SMEM_BYTES>>>(m1A2, m1w2, m1);
    mlp1_finalize<<<MROW / 8, 256>>>(m1, m1b1, m1W2, m1b2, y);

    tail_kernel<<<1, 256>>>(y, gam, bet, m2W1, m2b1, m2W2, m2b2, (float*)d_out);
}

// round 12
// speedup vs baseline: 1.2145x; 1.2145x over previous
#include <cuda_runtime.h>
#include <cuda_bf16.h>
#include <cstdint>

#define NN   65536
#define EE   524288
#define DIN  128
#define HD   256
#define NB   8
#define MROW 2048   // NB * HD

// ======================= helpers =======================
__device__ __forceinline__ void split_bf16(float v, __nv_bfloat16& h, __nv_bfloat16& l) {
    h = __float2bfloat16(v);
    l = __float2bfloat16(v - __bfloat162float(h));
}

__device__ __forceinline__ void mma16816(float* c, const uint32_t* a, const uint32_t* b) {
    asm volatile(
        "mma.sync.aligned.m16n8k16.row.col.f32.bf16.bf16.f32 "
        "{%0,%1,%2,%3}, {%4,%5,%6,%7}, {%8,%9}, {%0,%1,%2,%3};"
        : "+f"(c[0]), "+f"(c[1]), "+f"(c[2]), "+f"(c[3])
        : "r"(a[0]), "r"(a[1]), "r"(a[2]), "r"(a[3]), "r"(b[0]), "r"(b[1]));
}

__device__ __forceinline__ void ldsm4(uint32_t* r, uint32_t addr) {
    asm volatile("ldmatrix.sync.aligned.m8n8.x4.shared.b16 {%0,%1,%2,%3}, [%4];"
        : "=r"(r[0]), "=r"(r[1]), "=r"(r[2]), "=r"(r[3]) : "r"(addr));
}

__device__ __forceinline__ uint32_t smem_u32(const void* p) {
    uint32_t a;
    asm("{ .reg .u64 t; cvta.to.shared.u64 t, %1; cvt.u32.u64 %0, t; }" : "=r"(a) : "l"(p));
    return a;
}

__device__ __forceinline__ void cpa16(uint32_t dst, const void* src) {
    asm volatile("cp.async.cg.shared.global [%0], [%1], 16;" :: "r"(dst), "l"(src));
}
#define CPA_COMMIT() asm volatile("cp.async.commit_group;" ::: "memory")
#define CPA_WAIT1()  asm volatile("cp.async.wait_group 1;" ::: "memory")
#define CPA_WAIT0()  asm volatile("cp.async.wait_group 0;" ::: "memory")

// smem tiling: 4 tiles (Ah, Al, Bh, Bl), each 128 rows x 40 bf16
#define TSTRIDE 40
#define TE (128 * TSTRIDE)
#define BUFE (4 * TE)
#define STAGE_BYTES (BUFE * 2)              // 40960
#define GEMM_SMEM_BYTES (2 * STAGE_BYTES)   // 81920
#define OFFB_AH 0
#define OFFB_AL (TE * 2)
#define OFFB_BH (2 * TE * 2)
#define OFFB_BL (3 * TE * 2)

// ======================= static device scratch =======================
__device__ __nv_bfloat16 d_h02[NN * 256];
__device__ __nv_bfloat16 d_agg2[NN * 512];
__device__ __nv_bfloat16 d_h2A[NN * 512];
__device__ __nv_bfloat16 d_h2B[NN * 512];
__device__ __nv_bfloat16 d_m1A2[(size_t)MROW * 16384];
__device__ __nv_bfloat16 d_w2[8][256 * 512];
__device__ __nv_bfloat16 d_m1w2[(size_t)256 * 16384];
__device__ int   d_cnt[NN];
__device__ int   d_off[NN + 1];
__device__ int   d_cur[NN];
__device__ int   d_csr[EE];
__device__ int   d_bsum[64];
__device__ int   d_boff[64];
__device__ float d_invcnt[NN];
__device__ float d_m1[MROW * HD];
__device__ float d_y[MROW];

// ======================= small kernels =======================
__global__ void zero_f(float* __restrict__ p, int n) {
    int i = blockIdx.x * blockDim.x + threadIdx.x;
    if (i < n) p[i] = 0.0f;
}
__global__ void zero_i(int* __restrict__ p, int n) {
    int i = blockIdx.x * blockDim.x + threadIdx.x;
    if (i < n) p[i] = 0;
}

__global__ void concat2_kernel(const float* __restrict__ x, const float* __restrict__ g0,
                               const float* __restrict__ g1, const float* __restrict__ g2) {
    int i = blockIdx.x * blockDim.x + threadIdx.x;
    if (i >= NN * 128) return;
    int n = i >> 7, j = i & 127;
    float v;
    if (j < 32)       v = x[n * 32 + j];
    else if (j < 64)  v = g0[n * 32 + (j - 32)];
    else if (j < 96)  v = g1[n * 32 + (j - 64)];
    else              v = g2[n * 32 + (j - 96)];
    __nv_bfloat16 h, l; split_bf16(v, h, l);
    d_h02[n * 256 + j]       = h;
    d_h02[n * 256 + 128 + j] = l;
}

__global__ void conv_w(const float* __restrict__ W, __nv_bfloat16* __restrict__ out, int K) {
    int i = blockIdx.x * blockDim.x + threadIdx.x;
    if (i >= K * 256) return;
    int n = i & 255, k = i >> 8;
    float v = W[k * 256 + n];
    __nv_bfloat16 h, l; split_bf16(v, h, l);
    out[(size_t)n * 2 * K + k]     = h;
    out[(size_t)n * 2 * K + K + k] = l;
}

__global__ void count_kernel(const int* __restrict__ dst) {
    int e = blockIdx.x * blockDim.x + threadIdx.x;
    if (e < EE) atomicAdd(&d_cnt[dst[e]], 1);
}

// -------- parallel 3-phase scan (replaces 220us single-block scan) --------
// scanA: 64 blocks x 1024 thr. Coalesced load, block-wide exclusive scan,
// local prefix -> d_off, block total -> d_bsum. invcnt + cur fused (coalesced).
__global__ void scanA() {
    __shared__ int s[1024];
    int b = blockIdx.x, t = threadIdx.x;
    int i = b * 1024 + t;
    int c = d_cnt[i];
    s[t] = c;
    __syncthreads();
    for (int o = 1; o < 1024; o <<= 1) {
        int v = (t >= o) ? s[t - o] : 0;
        __syncthreads();
        s[t] += v;
        __syncthreads();
    }
    d_off[i] = s[t] - c;              // local exclusive prefix
    if (t == 1023) d_bsum[b] = s[t];
    d_invcnt[i] = 1.0f / fmaxf((float)c, 1.0f);
    d_cur[i] = 0;
}

// scanB: 1 block x 64 thr: exclusive scan of block sums
__global__ void scanB() {
    __shared__ int s[64];
    int t = threadIdx.x;
    int v = d_bsum[t];
    s[t] = v;
    __syncthreads();
    for (int o = 1; o < 64; o <<= 1) {
        int x = (t >= o) ? s[t - o] : 0;
        __syncthreads();
        s[t] += x;
        __syncthreads();
    }
    d_boff[t] = s[t] - v;
    if (t == 63) d_off[NN] = s[t];
}

// scanC: add block offsets (coalesced RMW)
__global__ void scanC() {
    int i = blockIdx.x * blockDim.x + threadIdx.x;
    if (i < NN) d_off[i] += d_boff[i >> 10];
}

__global__ void fill_kernel(const int* __restrict__ src, const int* __restrict__ dst) {
    int e = blockIdx.x * blockDim.x + threadIdx.x;
    if (e >= EE) return;
    int d = dst[e];
    int p = atomicAdd(&d_cur[d], 1);
    d_csr[d_off[d] + p] = src[e];
}

// CSR mean-aggregation: warp per node, neighbor loop unrolled x2.
// Rows are [hi(D) | lo(D)] bf16; coalesced bf16x2 loads.
template <int D>
__global__ void agg_csr(const __nv_bfloat16* __restrict__ H2,
                        __nv_bfloat16* __restrict__ out2) {
    int w = (blockIdx.x * blockDim.x + threadIdx.x) >> 5;
    int lane = threadIdx.x & 31;
    if (w >= NN) return;
    int s0 = __ldg(&d_off[w]), s1 = __ldg(&d_off[w + 1]);
    constexpr int R = D / 64;
    float a0[R], a1[R];
#pragma unroll
    for (int r = 0; r < R; r++) { a0[r] = 0.0f; a1[r] = 0.0f; }

    int p = s0;
    for (; p + 2 <= s1; p += 2) {
        int nbA = __ldg(&d_csr[p]);
        int nbB = __ldg(&d_csr[p + 1]);
        const __nv_bfloat16* baseA = H2 + (size_t)nbA * (2 * D);
        const __nv_bfloat16* baseB = H2 + (size_t)nbB * (2 * D);
#pragma unroll
        for (int r = 0; r < R; r++) {
            int c2 = (lane + r * 32) * 2;
            __nv_bfloat162 hA = *reinterpret_cast<const __nv_bfloat162*>(baseA + c2);
            __nv_bfloat162 lA = *reinterpret_cast<const __nv_bfloat162*>(baseA + D + c2);
            __nv_bfloat162 hB = *reinterpret_cast<const __nv_bfloat162*>(baseB + c2);
            __nv_bfloat162 lB = *reinterpret_cast<const __nv_bfloat162*>(baseB + D + c2);
            float2 hfA = __bfloat1622float2(hA);
            float2 lfA = __bfloat1622float2(lA);
            float2 hfB = __bfloat1622float2(hB);
            float2 lfB = __bfloat1622float2(lB);
            a0[r] += (hfA.x + lfA.x) + (hfB.x + lfB.x);
            a1[r] += (hfA.y + lfA.y) + (hfB.y + lfB.y);
        }
    }
    if (p < s1) {
        int nb = __ldg(&d_csr[p]);
        const __nv_bfloat16* base = H2 + (size_t)nb * (2 * D);
#pragma unroll
        for (int r = 0; r < R; r++) {
            int c2 = (lane + r * 32) * 2;
            __nv_bfloat162 hv = *reinterpret_cast<const __nv_bfloat162*>(base + c2);
            __nv_bfloat162 lv = *reinterpret_cast<const __nv_bfloat162*>(base + D + c2);
            float2 hf = __bfloat1622float2(hv);
            float2 lf = __bfloat1622float2(lv);
            a0[r] += hf.x + lf.x;
            a1[r] += hf.y + lf.y;
        }
    }

    float ic = d_invcnt[w];
    __nv_bfloat16* ob = out2 + (size_t)w * (2 * D);
#pragma unroll
    for (int r = 0; r < R; r++) {
        float v0 = a0[r] * ic, v1 = a1[r] * ic;
        __nv_bfloat16 h0, l0, h1, l1;
        split_bf16(v0, h0, l0);
        split_bf16(v1, h1, l1);
        int c2 = (lane + r * 32) * 2;
        *reinterpret_cast<__nv_bfloat162*>(ob + c2)     = __nv_bfloat162{h0, h1};
        *reinterpret_cast<__nv_bfloat162*>(ob + D + c2) = __nv_bfloat162{l0, l1};
    }
}

// ======================= GEMM compute core (ldmatrix, 3-term split) ===============
// Block: 256 threads, 8 warps (4m x 2n). Warp tile 32 x 64. Chunk = 32 K-cols.
__device__ __forceinline__ void gemm_chunk(uint32_t stage, int wm, int wn, int lane,
                                           float acc[2][8][4]) {
    const uint32_t aBase = stage + OFFB_AH +
        (uint32_t)(((wm * 32 + (lane & 15)) * TSTRIDE + (lane >> 4) * 8) * 2);
    const uint32_t bBase = stage + OFFB_BH +
        (uint32_t)(((wn * 64 + (lane >> 4) * 8 + (lane & 7)) * TSTRIDE + ((lane >> 3) & 1) * 8) * 2);
    const uint32_t loA = OFFB_AL - OFFB_AH;
    const uint32_t loB = OFFB_BL - OFFB_BH;

#pragma unroll
    for (int kk = 0; kk < 32; kk += 16) {
        uint32_t afh[2][4], afl[2][4];
#pragma unroll
        for (int mt = 0; mt < 2; mt++) {
            uint32_t a = aBase + (uint32_t)((mt * 16 * TSTRIDE + kk) * 2);
            ldsm4(afh[mt], a);
            ldsm4(afl[mt], a + loA);
        }
#pragma unroll
        for (int np = 0; np < 4; np++) {
            uint32_t b = bBase + (uint32_t)((np * 16 * TSTRIDE + kk) * 2);
            uint32_t bh[4], bl[4];
            ldsm4(bh, b);
            ldsm4(bl, b + loB);
#pragma unroll
            for (int mt = 0; mt < 2; mt++) {
                mma16816(acc[mt][np * 2],     afh[mt], &bh[0]);
                mma16816(acc[mt][np * 2 + 1], afh[mt], &bh[2]);
                mma16816(acc[mt][np * 2],     afl[mt], &bh[0]);
                mma16816(acc[mt][np * 2 + 1], afl[mt], &bh[2]);
                mma16816(acc[mt][np * 2],     afh[mt], &bl[0]);
                mma16816(acc[mt][np * 2 + 1], afh[mt], &bl[2]);
            }
        }
    }
}

// ======================= SAGE layer GEMM (cp.async double-buffered) ===============
template <int K>
__global__ __launch_bounds__(256, 2)
void sage_mma(const __nv_bfloat16* __restrict__ agg2, const __nv_bfloat16* __restrict__ h2,
              const __nv_bfloat16* __restrict__ Wl2, const __nv_bfloat16* __restrict__ Wr2,
              const float* __restrict__ bias, __nv_bfloat16* __restrict__ out2, int mode) {
    extern __shared__ __nv_bfloat16 smdyn[];
    const uint32_t smbase = smem_u32(smdyn);

    const int tid = threadIdx.x;
    const int wid = tid >> 5, lane = tid & 31;
    const int wm = wid & 3, wn = wid >> 2;
    const int lr = lane >> 2, lq = lane & 3;
    const int bm = blockIdx.x * 128;
    const int bn = blockIdx.y * 128;
    constexpr int K2 = 2 * K;
    constexpr int CPS = K / 32;
    constexpr int NCH = 2 * CPS;

    const int r0 = tid >> 2;
    const int cb = (tid & 3) * 8;

    float acc[2][8][4];
#pragma unroll
    for (int i = 0; i < 2; i++)
#pragma unroll
        for (int j = 0; j < 8; j++)
#pragma unroll
            for (int t = 0; t < 4; t++) acc[i][j][t] = 0.0f;

    auto prefetch = [&](int ci, int b) {
        const __nv_bfloat16* Asrc = (ci < CPS) ? agg2 : h2;
        const __nv_bfloat16* Bsrc = (ci < CPS) ? Wl2 : Wr2;
        int c = ci & (CPS - 1);
        uint32_t sb = smbase + (uint32_t)b * STAGE_BYTES;
#pragma unroll
        for (int half = 0; half < 2; half++) {
            int r = r0 + half * 64;
            uint32_t so = (uint32_t)(r * TSTRIDE + cb) * 2;
            const __nv_bfloat16* Ap = Asrc + (size_t)(bm + r) * K2 + c * 32 + cb;
            const __nv_bfloat16* Bp = Bsrc + (size_t)(bn + r) * K2 + c * 32 + cb;
            cpa16(sb + OFFB_AH + so, Ap);
            cpa16(sb + OFFB_AL + so, Ap + K);
            cpa16(sb + OFFB_BH + so, Bp);
            cpa16(sb + OFFB_BL + so, Bp + K);
        }
        CPA_COMMIT();
    };

    prefetch(0, 0);
    for (int i = 0; i < NCH; i++) {
        int b = i & 1;
        if (i + 1 < NCH) { prefetch(i + 1, b ^ 1); CPA_WAIT1(); }
        else             { CPA_WAIT0(); }
        __syncthreads();
        gemm_chunk(smbase + (uint32_t)b * STAGE_BYTES, wm, wn, lane, acc);
        __syncthreads();
    }

    // epilogue: bias + relu + hi/lo split
#pragma unroll
    for (int mt = 0; mt < 2; mt++) {
#pragma unroll
        for (int nt = 0; nt < 8; nt++) {
            int col = bn + wn * 64 + nt * 8 + lq * 2;
            float bs0 = __ldg(&bias[col]), bs1 = __ldg(&bias[col + 1]);
#pragma unroll
            for (int half = 0; half < 2; half++) {
                int grow = bm + wm * 32 + mt * 16 + lr + half * 8;
                float v0 = fmaxf(acc[mt][nt][half * 2 + 0] + bs0, 0.0f);
                float v1 = fmaxf(acc[mt][nt][half * 2 + 1] + bs1, 0.0f);
                __nv_bfloat16 h0, l0, h1, l1;
                split_bf16(v0, h0, l0);
                split_bf16(v1, h1, l1);
                if (mode == 0) {
                    *reinterpret_cast<__nv_bfloat162*>(&out2[(size_t)grow * 512 + col]) =
                        __nv_bfloat162{h0, h1};
                    *reinterpret_cast<__nv_bfloat162*>(&out2[(size_t)grow * 512 + 256 + col]) =
                        __nv_bfloat162{l0, l1};
                } else {
                    int R = grow >> 5;
                    int m = ((grow & 31) << 8) + col;
                    *reinterpret_cast<__nv_bfloat162*>(&out2[(size_t)R * 16384 + m]) =
                        __nv_bfloat162{h0, h1};
                    *reinterpret_cast<__nv_bfloat162*>(&out2[(size_t)R * 16384 + 8192 + m]) =
                        __nv_bfloat162{l0, l1};
                }
            }
        }
    }
}

// ======================= mlp1 GEMM (split-K=8, cp.async, atomic accum) ============
__global__ __launch_bounds__(256, 2)
void mlp1_mma(const __nv_bfloat16* __restrict__ A2, const __nv_bfloat16* __restrict__ W2t,
              float* __restrict__ C) {
    extern __shared__ __nv_bfloat16 smdyn[];
    const uint32_t smbase = smem_u32(smdyn);

    const int tid = threadIdx.x;
    const int wid = tid >> 5, lane = tid & 31;
    const int wm = wid & 3, wn = wid >> 2;
    const int lr = lane >> 2, lq = lane & 3;
    const int bm = blockIdx.x * 128;
    const int bn = blockIdx.y * 128;
    const int g0 = blockIdx.z * 32;
    const int NCH = 32;

    const int r0 = tid >> 2;
    const int cb = (tid & 3) * 8;

    float acc[2][8][4];
#pragma unroll
    for (int i = 0; i < 2; i++)
#pragma unroll
        for (int j = 0; j < 8; j++)
#pragma unroll
            for (int t = 0; t < 4; t++) acc[i][j][t] = 0.0f;

    auto prefetch = [&](int i, int b) {
        int c = g0 + i;
        uint32_t sb = smbase + (uint32_t)b * STAGE_BYTES;
#pragma unroll
        for (int half = 0; half < 2; half++) {
            int r = r0 + half * 64;
            uint32_t so = (uint32_t)(r * TSTRIDE + cb) * 2;
            const __nv_bfloat16* Ap = A2 + (size_t)(bm + r) * 16384 + c * 32 + cb;
            const __nv_bfloat16* Bp = W2t + (size_t)(bn + r) * 16384 + c * 32 + cb;
            cpa16(sb + OFFB_AH + so, Ap);
            cpa16(sb + OFFB_AL + so, Ap + 8192);
            cpa16(sb + OFFB_BH + so, Bp);
            cpa16(sb + OFFB_BL + so, Bp + 8192);
        }
        CPA_COMMIT();
    };

    prefetch(0, 0);
    for (int i = 0; i < NCH; i++) {
        int b = i & 1;
        if (i + 1 < NCH) { prefetch(i + 1, b ^ 1); CPA_WAIT1(); }
        else             { CPA_WAIT0(); }
        __syncthreads();
        gemm_chunk(smbase + (uint32_t)b * STAGE_BYTES, wm, wn, lane, acc);
        __syncthreads();
    }

#pragma unroll
    for (int mt = 0; mt < 2; mt++) {
#pragma unroll
        for (int nt = 0; nt < 8; nt++) {
            int col = bn + wn * 64 + nt * 8 + lq * 2;
#pragma unroll
            for (int half = 0; half < 2; half++) {
                int row = bm + wm * 32 + mt * 16 + lr + half * 8;
                atomicAdd(&C[(size_t)row * 256 + col],     acc[mt][nt][half * 2 + 0]);
                atomicAdd(&C[(size_t)row * 256 + col + 1], acc[mt][nt][half * 2 + 1]);
            }
        }
    }
}

// ======================= tail kernels =======================
__global__ void mlp1_finalize(const float* __restrict__ M1, const float* __restrict__ b1,
                              const float* __restrict__ W2, const float* __restrict__ b2,
                              float* __restrict__ y) {
    int row = (blockIdx.x * blockDim.x + threadIdx.x) >> 5;
    int lane = threadIdx.x & 31;
    if (row >= MROW) return;
    float s = 0.0f;
    for (int c = lane; c < HD; c += 32)
        s += fmaxf(M1[row * HD + c] + b1[c], 0.0f) * W2[c];
#pragma unroll
    for (int o = 16; o; o >>= 1) s += __shfl_xor_sync(0xffffffffu, s, o);
    if (lane == 0) y[row] = s + b2[0];
}

// fused batchnorm + relu + mlp2 (single block, 256 threads)
__global__ void tail_kernel(const float* __restrict__ y, const float* __restrict__ gamma,
                            const float* __restrict__ beta,
                            const float* __restrict__ W1, const float* __restrict__ b1,
                            const float* __restrict__ W2, const float* __restrict__ b2,
                            float* __restrict__ out) {
    __shared__ float ybn[NB][HD];
    __shared__ float zs[NB][HD];
    int j = threadIdx.x;
    float v[NB];
    float m = 0.0f;
#pragma unroll
    for (int b = 0; b < NB; b++) { v[b] = y[b * HD + j]; m += v[b]; }
    m *= (1.0f / NB);
    float var = 0.0f;
#pragma unroll
    for (int b = 0; b < NB; b++) { float d = v[b] - m; var += d * d; }
    var *= (1.0f / NB);
    float inv = rsqrtf(var + 1e-5f) * gamma[j];
    float be = beta[j];
#pragma unroll
    for (int b = 0; b < NB; b++)
        ybn[b][j] = fmaxf((v[b] - m) * inv + be, 0.0f);
    __syncthreads();

    float z[NB];
#pragma unroll
    for (int b = 0; b < NB; b++) z[b] = b1[j];
    for (int hh = 0; hh < HD; hh++) {
        float w = W1[hh * HD + j];
#pragma unroll
        for (int b = 0; b < NB; b++) z[b] += ybn[b][hh] * w;
    }
#pragma unroll
    for (int b = 0; b < NB; b++) zs[b][j] = fmaxf(z[b], 0.0f);
    __syncthreads();

    if (j < NB * 8) {
        int b = j >> 3, o = j & 7;
        float s = b2[o];
        for (int jj = 0; jj < HD; jj++) s += zs[b][jj] * W2[jj * 8 + o];
        out[j] = s;
    }
}

// ======================= host launch =======================
extern "C" void kernel_launch(void* const* d_in, const int* in_sizes, int n_in,
                              void* d_out, int out_size) {
    const float* x    = (const float*)d_in[0];
    const float* g0   = (const float*)d_in[1];
    const float* g1   = (const float*)d_in[2];
    const float* g2   = (const float*)d_in[3];
    const int*   esrc = (const int*)d_in[4];
    const int*   edst = (const int*)d_in[5];
    const float* Wl0  = (const float*)d_in[6];
    const float* Wr0  = (const float*)d_in[7];
    const float* b0   = (const float*)d_in[8];
    const float* Wl1  = (const float*)d_in[9];
    const float* Wr1  = (const float*)d_in[10];
    const float* b1   = (const float*)d_in[11];
    const float* Wl2  = (const float*)d_in[12];
    const float* Wr2  = (const float*)d_in[13];
    const float* b2   = (const float*)d_in[14];
    const float* Wl3  = (const float*)d_in[15];
    const float* Wr3  = (const float*)d_in[16];
    const float* b3   = (const float*)d_in[17];
    const float* m1W1 = (const float*)d_in[18];
    const float* m1b1 = (const float*)d_in[19];
    const float* m1W2 = (const float*)d_in[20];
    const float* m1b2 = (const float*)d_in[21];
    const float* gam  = (const float*)d_in[22];
    const float* bet  = (const float*)d_in[23];
    const float* m2W1 = (const float*)d_in[24];
    const float* m2b1 = (const float*)d_in[25];
    const float* m2W2 = (const float*)d_in[26];
    const float* m2b2 = (const float*)d_in[27];

    __nv_bfloat16 *h02, *agg2, *h2A, *h2B, *m1A2, *w2, *m1w2;
    int *cnt;
    float *m1, *y;
    cudaGetSymbolAddress((void**)&h02, d_h02);
    cudaGetSymbolAddress((void**)&agg2, d_agg2);
    cudaGetSymbolAddress((void**)&h2A, d_h2A);
    cudaGetSymbolAddress((void**)&h2B, d_h2B);
    cudaGetSymbolAddress((void**)&m1A2, d_m1A2);
    cudaGetSymbolAddress((void**)&w2, d_w2);
    cudaGetSymbolAddress((void**)&m1w2, d_m1w2);
    cudaGetSymbolAddress((void**)&cnt, d_cnt);
    cudaGetSymbolAddress((void**)&m1, d_m1);
    cudaGetSymbolAddress((void**)&y, d_y);

    cudaFuncSetAttribute(sage_mma<128>, cudaFuncAttributeMaxDynamicSharedMemorySize, GEMM_SMEM_BYTES);
    cudaFuncSetAttribute(sage_mma<256>, cudaFuncAttributeMaxDynamicSharedMemorySize, GEMM_SMEM_BYTES);
    cudaFuncSetAttribute(mlp1_mma,      cudaFuncAttributeMaxDynamicSharedMemorySize, GEMM_SMEM_BYTES);

    __nv_bfloat16* wl[4] = {w2 + 0 * 256 * 512, w2 + 2 * 256 * 512, w2 + 4 * 256 * 512, w2 + 6 * 256 * 512};
    __nv_bfloat16* wr[4] = {w2 + 1 * 256 * 512, w2 + 3 * 256 * 512, w2 + 5 * 256 * 512, w2 + 7 * 256 * 512};

    // CSR build with parallel scan; launch #6 = fill_kernel for ncu capture
    zero_i<<<NN / 256, 256>>>(cnt, NN);                          // 1
    count_kernel<<<EE / 256, 256>>>(edst);                       // 2
    scanA<<<64, 1024>>>();                                       // 3
    scanB<<<1, 64>>>();                                          // 4
    scanC<<<NN / 256, 256>>>();                                  // 5
    fill_kernel<<<EE / 256, 256>>>(esrc, edst);                  // 6  <-- ncu capture
    concat2_kernel<<<(NN * 128) / 256, 256>>>(x, g0, g1, g2);    // 7

    // weight conversion
    conv_w<<<128, 256>>>(Wl0, wl[0], 128);
    conv_w<<<128, 256>>>(Wr0, wr[0], 128);
    conv_w<<<256, 256>>>(Wl1, wl[1], 256);
    conv_w<<<256, 256>>>(Wr1, wr[1], 256);
    conv_w<<<256, 256>>>(Wl2, wl[2], 256);
    conv_w<<<256, 256>>>(Wr2, wr[2], 256);
    conv_w<<<256, 256>>>(Wl3, wl[3], 256);
    conv_w<<<256, 256>>>(Wr3, wr[3], 256);
    conv_w<<<8192, 256>>>(m1W1, m1w2, 8192);

    agg_csr<128><<<NN / 8, 256>>>(h02, agg2);
    sage_mma<128><<<dim3(NN / 128, 2), 256, GEMM_SMEM_BYTES>>>(agg2, h02, wl[0], wr[0], b0, h2A, 0);
    agg_csr<256><<<NN / 8, 256>>>(h2A, agg2);
    sage_mma<256><<<dim3(NN / 128, 2), 256, GEMM_SMEM_BYTES>>>(agg2, h2A, wl[1], wr[1], b1, h2B, 0);
    agg_csr<256><<<NN / 8, 256>>>(h2B, agg2);
    sage_mma<256><<<dim3(NN / 128, 2), 256, GEMM_SMEM_BYTES>>>(agg2, h2B, wl[2], wr[2], b2, h2A, 0);
    agg_csr<256><<<NN / 8, 256>>>(h2A, agg2);
    sage_mma<256><<<dim3(NN / 128, 2), 256, GEMM_SMEM_BYTES>>>(agg2, h2A, wl[3], wr[3], b3, m1A2, 1);

    zero_f<<<(MROW * HD) / 256, 256>>>(m1, MROW * HD);
    mlp1_mma<<<dim3(MROW / 128, 2, 8), 256, GEMM_SMEM_BYTES>>>(m1A2, m1w2, m1);
    mlp1_finalize<<<MROW / 8, 256>>>(m1, m1b1, m1W2, m1b2, y);

    tail_kernel<<<1, 256>>>(y, gam, bet, m2W1, m2b1, m2W2, m2b2, (float*)d_out);
}

// round 13
// speedup vs baseline: 1.2680x; 1.0441x over previous
#include <cuda_runtime.h>
#include <cuda_bf16.h>
#include <cstdint>

#define NN   65536
#define EE   524288
#define DIN  128
#define HD   256
#define NB   8
#define MROW 2048   // NB * HD

// ======================= helpers =======================
__device__ __forceinline__ void split_bf16(float v, __nv_bfloat16& h, __nv_bfloat16& l) {
    h = __float2bfloat16(v);
    l = __float2bfloat16(v - __bfloat162float(h));
}

__device__ __forceinline__ void mma16816(float* c, const uint32_t* a, const uint32_t* b) {
    asm volatile(
        "mma.sync.aligned.m16n8k16.row.col.f32.bf16.bf16.f32 "
        "{%0,%1,%2,%3}, {%4,%5,%6,%7}, {%8,%9}, {%0,%1,%2,%3};"
        : "+f"(c[0]), "+f"(c[1]), "+f"(c[2]), "+f"(c[3])
        : "r"(a[0]), "r"(a[1]), "r"(a[2]), "r"(a[3]), "r"(b[0]), "r"(b[1]));
}

__device__ __forceinline__ void ldsm4(uint32_t* r, uint32_t addr) {
    asm volatile("ldmatrix.sync.aligned.m8n8.x4.shared.b16 {%0,%1,%2,%3}, [%4];"
        : "=r"(r[0]), "=r"(r[1]), "=r"(r[2]), "=r"(r[3]) : "r"(addr));
}

__device__ __forceinline__ uint32_t smem_u32(const void* p) {
    uint32_t a;
    asm("{ .reg .u64 t; cvta.to.shared.u64 t, %1; cvt.u32.u64 %0, t; }" : "=r"(a) : "l"(p));
    return a;
}

__device__ __forceinline__ void cpa16(uint32_t dst, const void* src) {
    asm volatile("cp.async.cg.shared.global [%0], [%1], 16;" :: "r"(dst), "l"(src));
}
#define CPA_COMMIT() asm volatile("cp.async.commit_group;" ::: "memory")
#define CPA_WAIT1()  asm volatile("cp.async.wait_group 1;" ::: "memory")
#define CPA_WAIT0()  asm volatile("cp.async.wait_group 0;" ::: "memory")

// smem tiling: 4 tiles (Ah, Al, Bh, Bl), each 128 rows x 40 bf16
#define TSTRIDE 40
#define TE (128 * TSTRIDE)
#define BUFE (4 * TE)
#define STAGE_BYTES (BUFE * 2)              // 40960
#define GEMM_SMEM_BYTES (2 * STAGE_BYTES)   // 81920
#define OFFB_AH 0
#define OFFB_AL (TE * 2)
#define OFFB_BH (2 * TE * 2)
#define OFFB_BL (3 * TE * 2)

// ======================= static device scratch =======================
__device__ __nv_bfloat16 d_h02[NN * 256];
__device__ __nv_bfloat16 d_agg2[NN * 512];
__device__ __nv_bfloat16 d_h2A[NN * 512];
__device__ __nv_bfloat16 d_h2B[NN * 512];
__device__ __nv_bfloat16 d_m1A2[(size_t)MROW * 16384];
__device__ __nv_bfloat16 d_w2[8][256 * 512];
__device__ __nv_bfloat16 d_m1w2[(size_t)256 * 16384];
__device__ int   d_cnt[NN];
__device__ int   d_off[NN + 1];
__device__ int   d_cur[NN];
__device__ int   d_csr[EE];
__device__ int   d_bsum[64];
__device__ int   d_boff[64];
__device__ float d_invcnt[NN];
__device__ float d_m1[MROW * HD];
__device__ float d_y[MROW];

// ======================= small kernels =======================
__global__ void concat2_kernel(const float* __restrict__ x, const float* __restrict__ g0,
                               const float* __restrict__ g1, const float* __restrict__ g2) {
    int i = blockIdx.x * blockDim.x + threadIdx.x;
    if (i >= NN * 128) return;
    int n = i >> 7, j = i & 127;
    float v;
    if (j < 32)       v = x[n * 32 + j];
    else if (j < 64)  v = g0[n * 32 + (j - 32)];
    else if (j < 96)  v = g1[n * 32 + (j - 64)];
    else              v = g2[n * 32 + (j - 96)];
    __nv_bfloat16 h, l; split_bf16(v, h, l);
    d_h02[n * 256 + j]       = h;
    d_h02[n * 256 + 128 + j] = l;
}

// transpose-coalesced weight conversion: W [K,256] fp32 -> out [256][2K] (hi|lo).
// 32x32 tile via smem; both global reads and writes coalesced. Block 32x8.
__global__ void conv_w_t(const float* __restrict__ W, __nv_bfloat16* __restrict__ out, int K) {
    __shared__ float tile[32][33];
    int kb = blockIdx.x * 32, nb = blockIdx.y * 32;
    int tx = threadIdx.x, ty = threadIdx.y;   // 32 x 8
#pragma unroll
    for (int i = 0; i < 4; i++) {
        int k = kb + ty + i * 8;
        tile[ty + i * 8][tx] = W[(size_t)k * 256 + nb + tx];
    }
    __syncthreads();
#pragma unroll
    for (int i = 0; i < 4; i++) {
        int n = nb + ty + i * 8;
        int k = kb + tx;
        float v = tile[tx][ty + i * 8];
        __nv_bfloat16 h, l; split_bf16(v, h, l);
        out[(size_t)n * 2 * K + k]     = h;
        out[(size_t)n * 2 * K + K + k] = l;
    }
}

__global__ void count_kernel(const int* __restrict__ dst) {
    int e = blockIdx.x * blockDim.x + threadIdx.x;
    if (e < EE) atomicAdd(&d_cnt[dst[e]], 1);
}

// -------- parallel 3-phase scan --------
__global__ void scanA() {
    __shared__ int s[1024];
    int b = blockIdx.x, t = threadIdx.x;
    int i = b * 1024 + t;
    int c = d_cnt[i];
    s[t] = c;
    __syncthreads();
    for (int o = 1; o < 1024; o <<= 1) {
        int v = (t >= o) ? s[t - o] : 0;
        __syncthreads();
        s[t] += v;
        __syncthreads();
    }
    d_off[i] = s[t] - c;
    if (t == 1023) d_bsum[b] = s[t];
    d_invcnt[i] = 1.0f / fmaxf((float)c, 1.0f);
    d_cur[i] = 0;
}

__global__ void scanB() {
    __shared__ int s[64];
    int t = threadIdx.x;
    int v = d_bsum[t];
    s[t] = v;
    __syncthreads();
    for (int o = 1; o < 64; o <<= 1) {
        int x = (t >= o) ? s[t - o] : 0;
        __syncthreads();
        s[t] += x;
        __syncthreads();
    }
    d_boff[t] = s[t] - v;
    if (t == 63) d_off[NN] = s[t];
}

__global__ void scanC() {
    int i = blockIdx.x * blockDim.x + threadIdx.x;
    if (i < NN) d_off[i] += d_boff[i >> 10];
}

__global__ void fill_kernel(const int* __restrict__ src, const int* __restrict__ dst) {
    int e = blockIdx.x * blockDim.x + threadIdx.x;
    if (e >= EE) return;
    int d = dst[e];
    int p = atomicAdd(&d_cur[d], 1);
    d_csr[d_off[d] + p] = src[e];
}

// CSR mean-aggregation: warp per node, neighbor loop unrolled x2.
template <int D>
__global__ void agg_csr(const __nv_bfloat16* __restrict__ H2,
                        __nv_bfloat16* __restrict__ out2) {
    int w = (blockIdx.x * blockDim.x + threadIdx.x) >> 5;
    int lane = threadIdx.x & 31;
    if (w >= NN) return;
    int s0 = __ldg(&d_off[w]), s1 = __ldg(&d_off[w + 1]);
    constexpr int R = D / 64;
    float a0[R], a1[R];
#pragma unroll
    for (int r = 0; r < R; r++) { a0[r] = 0.0f; a1[r] = 0.0f; }

    int p = s0;
    for (; p + 2 <= s1; p += 2) {
        int nbA = __ldg(&d_csr[p]);
        int nbB = __ldg(&d_csr[p + 1]);
        const __nv_bfloat16* baseA = H2 + (size_t)nbA * (2 * D);
        const __nv_bfloat16* baseB = H2 + (size_t)nbB * (2 * D);
#pragma unroll
        for (int r = 0; r < R; r++) {
            int c2 = (lane + r * 32) * 2;
            __nv_bfloat162 hA = *reinterpret_cast<const __nv_bfloat162*>(baseA + c2);
            __nv_bfloat162 lA = *reinterpret_cast<const __nv_bfloat162*>(baseA + D + c2);
            __nv_bfloat162 hB = *reinterpret_cast<const __nv_bfloat162*>(baseB + c2);
            __nv_bfloat162 lB = *reinterpret_cast<const __nv_bfloat162*>(baseB + D + c2);
            float2 hfA = __bfloat1622float2(hA);
            float2 lfA = __bfloat1622float2(lA);
            float2 hfB = __bfloat1622float2(hB);
            float2 lfB = __bfloat1622float2(lB);
            a0[r] += (hfA.x + lfA.x) + (hfB.x + lfB.x);
            a1[r] += (hfA.y + lfA.y) + (hfB.y + lfB.y);
        }
    }
    if (p < s1) {
        int nb = __ldg(&d_csr[p]);
        const __nv_bfloat16* base = H2 + (size_t)nb * (2 * D);
#pragma unroll
        for (int r = 0; r < R; r++) {
            int c2 = (lane + r * 32) * 2;
            __nv_bfloat162 hv = *reinterpret_cast<const __nv_bfloat162*>(base + c2);
            __nv_bfloat162 lv = *reinterpret_cast<const __nv_bfloat162*>(base + D + c2);
            float2 hf = __bfloat1622float2(hv);
            float2 lf = __bfloat1622float2(lv);
            a0[r] += hf.x + lf.x;
            a1[r] += hf.y + lf.y;
        }
    }

    float ic = d_invcnt[w];
    __nv_bfloat16* ob = out2 + (size_t)w * (2 * D);
#pragma unroll
    for (int r = 0; r < R; r++) {
        float v0 = a0[r] * ic, v1 = a1[r] * ic;
        __nv_bfloat16 h0, l0, h1, l1;
        split_bf16(v0, h0, l0);
        split_bf16(v1, h1, l1);
        int c2 = (lane + r * 32) * 2;
        *reinterpret_cast<__nv_bfloat162*>(ob + c2)     = __nv_bfloat162{h0, h1};
        *reinterpret_cast<__nv_bfloat162*>(ob + D + c2) = __nv_bfloat162{l0, l1};
    }
}

// ======================= GEMM compute core (ldmatrix, 3-term split) ===============
__device__ __forceinline__ void gemm_chunk(uint32_t stage, int wm, int wn, int lane,
                                           float acc[2][8][4]) {
    const uint32_t aBase = stage + OFFB_AH +
        (uint32_t)(((wm * 32 + (lane & 15)) * TSTRIDE + (lane >> 4) * 8) * 2);
    const uint32_t bBase = stage + OFFB_BH +
        (uint32_t)(((wn * 64 + (lane >> 4) * 8 + (lane & 7)) * TSTRIDE + ((lane >> 3) & 1) * 8) * 2);
    const uint32_t loA = OFFB_AL - OFFB_AH;
    const uint32_t loB = OFFB_BL - OFFB_BH;

#pragma unroll
    for (int kk = 0; kk < 32; kk += 16) {
        uint32_t afh[2][4], afl[2][4];
#pragma unroll
        for (int mt = 0; mt < 2; mt++) {
            uint32_t a = aBase + (uint32_t)((mt * 16 * TSTRIDE + kk) * 2);
            ldsm4(afh[mt], a);
            ldsm4(afl[mt], a + loA);
        }
#pragma unroll
        for (int np = 0; np < 4; np++) {
            uint32_t b = bBase + (uint32_t)((np * 16 * TSTRIDE + kk) * 2);
            uint32_t bh[4], bl[4];
            ldsm4(bh, b);
            ldsm4(bl, b + loB);
#pragma unroll
            for (int mt = 0; mt < 2; mt++) {
                mma16816(acc[mt][np * 2],     afh[mt], &bh[0]);
                mma16816(acc[mt][np * 2 + 1], afh[mt], &bh[2]);
                mma16816(acc[mt][np * 2],     afl[mt], &bh[0]);
                mma16816(acc[mt][np * 2 + 1], afl[mt], &bh[2]);
                mma16816(acc[mt][np * 2],     afh[mt], &bl[0]);
                mma16816(acc[mt][np * 2 + 1], afh[mt], &bl[2]);
            }
        }
    }
}

// ======================= SAGE layer GEMM (cp.async double-buffered) ===============
template <int K>
__global__ __launch_bounds__(256, 2)
void sage_mma(const __nv_bfloat16* __restrict__ agg2, const __nv_bfloat16* __restrict__ h2,
              const __nv_bfloat16* __restrict__ Wl2, const __nv_bfloat16* __restrict__ Wr2,
              const float* __restrict__ bias, __nv_bfloat16* __restrict__ out2, int mode) {
    extern __shared__ __nv_bfloat16 smdyn[];
    const uint32_t smbase = smem_u32(smdyn);

    const int tid = threadIdx.x;
    const int wid = tid >> 5, lane = tid & 31;
    const int wm = wid & 3, wn = wid >> 2;
    const int lr = lane >> 2, lq = lane & 3;
    const int bm = blockIdx.x * 128;
    const int bn = blockIdx.y * 128;
    constexpr int K2 = 2 * K;
    constexpr int CPS = K / 32;
    constexpr int NCH = 2 * CPS;

    const int r0 = tid >> 2;
    const int cb = (tid & 3) * 8;

    float acc[2][8][4];
#pragma unroll
    for (int i = 0; i < 2; i++)
#pragma unroll
        for (int j = 0; j < 8; j++)
#pragma unroll
            for (int t = 0; t < 4; t++) acc[i][j][t] = 0.0f;

    auto prefetch = [&](int ci, int b) {
        const __nv_bfloat16* Asrc = (ci < CPS) ? agg2 : h2;
        const __nv_bfloat16* Bsrc = (ci < CPS) ? Wl2 : Wr2;
        int c = ci & (CPS - 1);
        uint32_t sb = smbase + (uint32_t)b * STAGE_BYTES;
#pragma unroll
        for (int half = 0; half < 2; half++) {
            int r = r0 + half * 64;
            uint32_t so = (uint32_t)(r * TSTRIDE + cb) * 2;
            const __nv_bfloat16* Ap = Asrc + (size_t)(bm + r) * K2 + c * 32 + cb;
            const __nv_bfloat16* Bp = Bsrc + (size_t)(bn + r) * K2 + c * 32 + cb;
            cpa16(sb + OFFB_AH + so, Ap);
            cpa16(sb + OFFB_AL + so, Ap + K);
            cpa16(sb + OFFB_BH + so, Bp);
            cpa16(sb + OFFB_BL + so, Bp + K);
        }
        CPA_COMMIT();
    };

    prefetch(0, 0);
    for (int i = 0; i < NCH; i++) {
        int b = i & 1;
        if (i + 1 < NCH) { prefetch(i + 1, b ^ 1); CPA_WAIT1(); }
        else             { CPA_WAIT0(); }
        __syncthreads();
        gemm_chunk(smbase + (uint32_t)b * STAGE_BYTES, wm, wn, lane, acc);
        __syncthreads();
    }

    // epilogue: bias + relu + hi/lo split
#pragma unroll
    for (int mt = 0; mt < 2; mt++) {
#pragma unroll
        for (int nt = 0; nt < 8; nt++) {
            int col = bn + wn * 64 + nt * 8 + lq * 2;
            float bs0 = __ldg(&bias[col]), bs1 = __ldg(&bias[col + 1]);
#pragma unroll
            for (int half = 0; half < 2; half++) {
                int grow = bm + wm * 32 + mt * 16 + lr + half * 8;
                float v0 = fmaxf(acc[mt][nt][half * 2 + 0] + bs0, 0.0f);
                float v1 = fmaxf(acc[mt][nt][half * 2 + 1] + bs1, 0.0f);
                __nv_bfloat16 h0, l0, h1, l1;
                split_bf16(v0, h0, l0);
                split_bf16(v1, h1, l1);
                if (mode == 0) {
                    *reinterpret_cast<__nv_bfloat162*>(&out2[(size_t)grow * 512 + col]) =
                        __nv_bfloat162{h0, h1};
                    *reinterpret_cast<__nv_bfloat162*>(&out2[(size_t)grow * 512 + 256 + col]) =
                        __nv_bfloat162{l0, l1};
                } else {
                    int R = grow >> 5;
                    int m = ((grow & 31) << 8) + col;
                    *reinterpret_cast<__nv_bfloat162*>(&out2[(size_t)R * 16384 + m]) =
                        __nv_bfloat162{h0, h1};
                    *reinterpret_cast<__nv_bfloat162*>(&out2[(size_t)R * 16384 + 8192 + m]) =
                        __nv_bfloat162{l0, l1};
                }
            }
        }
    }
}

// ======================= mlp1 GEMM (split-K=8, cp.async, atomic accum) ============
__global__ __launch_bounds__(256, 2)
void mlp1_mma(const __nv_bfloat16* __restrict__ A2, const __nv_bfloat16* __restrict__ W2t,
              float* __restrict__ C) {
    extern __shared__ __nv_bfloat16 smdyn[];
    const uint32_t smbase = smem_u32(smdyn);

    const int tid = threadIdx.x;
    const int wid = tid >> 5, lane = tid & 31;
    const int wm = wid & 3, wn = wid >> 2;
    const int lr = lane >> 2, lq = lane & 3;
    const int bm = blockIdx.x * 128;
    const int bn = blockIdx.y * 128;
    const int g0 = blockIdx.z * 32;
    const int NCH = 32;

    const int r0 = tid >> 2;
    const int cb = (tid & 3) * 8;

    float acc[2][8][4];
#pragma unroll
    for (int i = 0; i < 2; i++)
#pragma unroll
        for (int j = 0; j < 8; j++)
#pragma unroll
            for (int t = 0; t < 4; t++) acc[i][j][t] = 0.0f;

    auto prefetch = [&](int i, int b) {
        int c = g0 + i;
        uint32_t sb = smbase + (uint32_t)b * STAGE_BYTES;
#pragma unroll
        for (int half = 0; half < 2; half++) {
            int r = r0 + half * 64;
            uint32_t so = (uint32_t)(r * TSTRIDE + cb) * 2;
            const __nv_bfloat16* Ap = A2 + (size_t)(bm + r) * 16384 + c * 32 + cb;
            const __nv_bfloat16* Bp = W2t + (size_t)(bn + r) * 16384 + c * 32 + cb;
            cpa16(sb + OFFB_AH + so, Ap);
            cpa16(sb + OFFB_AL + so, Ap + 8192);
            cpa16(sb + OFFB_BH + so, Bp);
            cpa16(sb + OFFB_BL + so, Bp + 8192);
        }
        CPA_COMMIT();
    };

    prefetch(0, 0);
    for (int i = 0; i < NCH; i++) {
        int b = i & 1;
        if (i + 1 < NCH) { prefetch(i + 1, b ^ 1); CPA_WAIT1(); }
        else             { CPA_WAIT0(); }
        __syncthreads();
        gemm_chunk(smbase + (uint32_t)b * STAGE_BYTES, wm, wn, lane, acc);
        __syncthreads();
    }

#pragma unroll
    for (int mt = 0; mt < 2; mt++) {
#pragma unroll
        for (int nt = 0; nt < 8; nt++) {
            int col = bn + wn * 64 + nt * 8 + lq * 2;
#pragma unroll
            for (int half = 0; half < 2; half++) {
                int row = bm + wm * 32 + mt * 16 + lr + half * 8;
                atomicAdd(&C[(size_t)row * 256 + col],     acc[mt][nt][half * 2 + 0]);
                atomicAdd(&C[(size_t)row * 256 + col + 1], acc[mt][nt][half * 2 + 1]);
            }
        }
    }
}

// ======================= tail kernels =======================
__global__ void mlp1_finalize(const float* __restrict__ M1, const float* __restrict__ b1,
                              const float* __restrict__ W2, const float* __restrict__ b2,
                              float* __restrict__ y) {
    int row = (blockIdx.x * blockDim.x + threadIdx.x) >> 5;
    int lane = threadIdx.x & 31;
    if (row >= MROW) return;
    float s = 0.0f;
    for (int c = lane; c < HD; c += 32)
        s += fmaxf(M1[row * HD + c] + b1[c], 0.0f) * W2[c];
#pragma unroll
    for (int o = 16; o; o >>= 1) s += __shfl_xor_sync(0xffffffffu, s, o);
    if (lane == 0) y[row] = s + b2[0];
}

// fused batchnorm + relu + mlp2 (single block, 256 threads)
__global__ void tail_kernel(const float* __restrict__ y, const float* __restrict__ gamma,
                            const float* __restrict__ beta,
                            const float* __restrict__ W1, const float* __restrict__ b1,
                            const float* __restrict__ W2, const float* __restrict__ b2,
                            float* __restrict__ out) {
    __shared__ float ybn[NB][HD];
    __shared__ float zs[NB][HD];
    int j = threadIdx.x;
    float v[NB];
    float m = 0.0f;
#pragma unroll
    for (int b = 0; b < NB; b++) { v[b] = y[b * HD + j]; m += v[b]; }
    m *= (1.0f / NB);
    float var = 0.0f;
#pragma unroll
    for (int b = 0; b < NB; b++) { float d = v[b] - m; var += d * d; }
    var *= (1.0f / NB);
    float inv = rsqrtf(var + 1e-5f) * gamma[j];
    float be = beta[j];
#pragma unroll
    for (int b = 0; b < NB; b++)
        ybn[b][j] = fmaxf((v[b] - m) * inv + be, 0.0f);
    __syncthreads();

    float z[NB];
#pragma unroll
    for (int b = 0; b < NB; b++) z[b] = b1[j];
    for (int hh = 0; hh < HD; hh++) {
        float w = W1[hh * HD + j];
#pragma unroll
        for (int b = 0; b < NB; b++) z[b] += ybn[b][hh] * w;
    }
#pragma unroll
    for (int b = 0; b < NB; b++) zs[b][j] = fmaxf(z[b], 0.0f);
    __syncthreads();

    if (j < NB * 8) {
        int b = j >> 3, o = j & 7;
        float s = b2[o];
        for (int jj = 0; jj < HD; jj++) s += zs[b][jj] * W2[jj * 8 + o];
        out[j] = s;
    }
}

// ======================= host launch =======================
extern "C" void kernel_launch(void* const* d_in, const int* in_sizes, int n_in,
                              void* d_out, int out_size) {
    const float* x    = (const float*)d_in[0];
    const float* g0   = (const float*)d_in[1];
    const float* g1   = (const float*)d_in[2];
    const float* g2   = (const float*)d_in[3];
    const int*   esrc = (const int*)d_in[4];
    const int*   edst = (const int*)d_in[5];
    const float* Wl0  = (const float*)d_in[6];
    const float* Wr0  = (const float*)d_in[7];
    const float* b0   = (const float*)d_in[8];
    const float* Wl1  = (const float*)d_in[9];
    const float* Wr1  = (const float*)d_in[10];
    const float* b1   = (const float*)d_in[11];
    const float* Wl2  = (const float*)d_in[12];
    const float* Wr2  = (const float*)d_in[13];
    const float* b2   = (const float*)d_in[14];
    const float* Wl3  = (const float*)d_in[15];
    const float* Wr3  = (const float*)d_in[16];
    const float* b3   = (const float*)d_in[17];
    const float* m1W1 = (const float*)d_in[18];
    const float* m1b1 = (const float*)d_in[19];
    const float* m1W2 = (const float*)d_in[20];
    const float* m1b2 = (const float*)d_in[21];
    const float* gam  = (const float*)d_in[22];
    const float* bet  = (const float*)d_in[23];
    const float* m2W1 = (const float*)d_in[24];
    const float* m2b1 = (const float*)d_in[25];
    const float* m2W2 = (const float*)d_in[26];
    const float* m2b2 = (const float*)d_in[27];

    __nv_bfloat16 *h02, *agg2, *h2A, *h2B, *m1A2, *w2, *m1w2;
    int *cnt;
    float *m1, *y;
    cudaGetSymbolAddress((void**)&h02, d_h02);
    cudaGetSymbolAddress((void**)&agg2, d_agg2);
    cudaGetSymbolAddress((void**)&h2A, d_h2A);
    cudaGetSymbolAddress((void**)&h2B, d_h2B);
    cudaGetSymbolAddress((void**)&m1A2, d_m1A2);
    cudaGetSymbolAddress((void**)&w2, d_w2);
    cudaGetSymbolAddress((void**)&m1w2, d_m1w2);
    cudaGetSymbolAddress((void**)&cnt, d_cnt);
    cudaGetSymbolAddress((void**)&m1, d_m1);
    cudaGetSymbolAddress((void**)&y, d_y);

    cudaFuncSetAttribute(sage_mma<128>, cudaFuncAttributeMaxDynamicSharedMemorySize, GEMM_SMEM_BYTES);
    cudaFuncSetAttribute(sage_mma<256>, cudaFuncAttributeMaxDynamicSharedMemorySize, GEMM_SMEM_BYTES);
    cudaFuncSetAttribute(mlp1_mma,      cudaFuncAttributeMaxDynamicSharedMemorySize, GEMM_SMEM_BYTES);

    __nv_bfloat16* wl[4] = {w2 + 0 * 256 * 512, w2 + 2 * 256 * 512, w2 + 4 * 256 * 512, w2 + 6 * 256 * 512};
    __nv_bfloat16* wr[4] = {w2 + 1 * 256 * 512, w2 + 3 * 256 * 512, w2 + 5 * 256 * 512, w2 + 7 * 256 * 512};

    // CSR build with parallel scan
    cudaMemsetAsync(cnt, 0, NN * sizeof(int), 0);
    count_kernel<<<EE / 256, 256>>>(edst);
    scanA<<<64, 1024>>>();
    scanB<<<1, 64>>>();
    scanC<<<NN / 256, 256>>>();
    fill_kernel<<<EE / 256, 256>>>(esrc, edst);
    concat2_kernel<<<(NN * 128) / 256, 256>>>(x, g0, g1, g2);

    // weight conversion (transpose-coalesced)
    dim3 cb32(32, 8);
    conv_w_t<<<dim3(4, 8),   cb32>>>(Wl0, wl[0], 128);
    conv_w_t<<<dim3(4, 8),   cb32>>>(Wr0, wr[0], 128);
    conv_w_t<<<dim3(8, 8),   cb32>>>(Wl1, wl[1], 256);
    conv_w_t<<<dim3(8, 8),   cb32>>>(Wr1, wr[1], 256);
    conv_w_t<<<dim3(8, 8),   cb32>>>(Wl2, wl[2], 256);
    conv_w_t<<<dim3(8, 8),   cb32>>>(Wr2, wr[2], 256);
    conv_w_t<<<dim3(8, 8),   cb32>>>(Wl3, wl[3], 256);
    conv_w_t<<<dim3(8, 8),   cb32>>>(Wr3, wr[3], 256);
    conv_w_t<<<dim3(256, 8), cb32>>>(m1W1, m1w2, 8192);

    agg_csr<128><<<NN / 8, 256>>>(h02, agg2);
    sage_mma<128><<<dim3(NN / 128, 2), 256, GEMM_SMEM_BYTES>>>(agg2, h02, wl[0], wr[0], b0, h2A, 0);
    agg_csr<256><<<NN / 8, 256>>>(h2A, agg2);
    sage_mma<256><<<dim3(NN / 128, 2), 256, GEMM_SMEM_BYTES>>>(agg2, h2A, wl[1], wr[1], b1, h2B, 0);
    agg_csr<256><<<NN / 8, 256>>>(h2B, agg2);
    sage_mma<256><<<dim3(NN / 128, 2), 256, GEMM_SMEM_BYTES>>>(agg2, h2B, wl[2], wr[2], b2, h2A, 0);
    agg_csr<256><<<NN / 8, 256>>>(h2A, agg2);
    sage_mma<256><<<dim3(NN / 128, 2), 256, GEMM_SMEM_BYTES>>>(agg2, h2A, wl[3], wr[3], b3, m1A2, 1);

    cudaMemsetAsync(m1, 0, (size_t)MROW * HD * sizeof(float), 0);
    mlp1_mma<<<dim3(MROW / 128, 2, 8), 256, GEMM_SMEM_BYTES>>>(m1A2, m1w2, m1);
    mlp1_finalize<<<MROW / 8, 256>>>(m1, m1b1, m1W2, m1b2, y);

    tail_kernel<<<1, 256>>>(y, gam, bet, m2W1, m2b1, m2W2, m2b2, (float*)d_out);
}

// round 14
// speedup vs baseline: 1.2828x; 1.0117x over previous
#include <cuda_runtime.h>
#include <cuda_bf16.h>
#include <cstdint>

#define NN   65536
#define EE   524288
#define DIN  128
#define HD   256
#define NB   8
#define MROW 2048   // NB * HD

// ======================= helpers =======================
__device__ __forceinline__ void split_bf16(float v, __nv_bfloat16& h, __nv_bfloat16& l) {
    h = __float2bfloat16(v);
    l = __float2bfloat16(v - __bfloat162float(h));
}

__device__ __forceinline__ void mma16816(float* c, const uint32_t* a, const uint32_t* b) {
    asm volatile(
        "mma.sync.aligned.m16n8k16.row.col.f32.bf16.bf16.f32 "
        "{%0,%1,%2,%3}, {%4,%5,%6,%7}, {%8,%9}, {%0,%1,%2,%3};"
        : "+f"(c[0]), "+f"(c[1]), "+f"(c[2]), "+f"(c[3])
        : "r"(a[0]), "r"(a[1]), "r"(a[2]), "r"(a[3]), "r"(b[0]), "r"(b[1]));
}

__device__ __forceinline__ void ldsm4(uint32_t* r, uint32_t addr) {
    asm volatile("ldmatrix.sync.aligned.m8n8.x4.shared.b16 {%0,%1,%2,%3}, [%4];"
        : "=r"(r[0]), "=r"(r[1]), "=r"(r[2]), "=r"(r[3]) : "r"(addr));
}

__device__ __forceinline__ uint32_t smem_u32(const void* p) {
    uint32_t a;
    asm("{ .reg .u64 t; cvta.to.shared.u64 t, %1; cvt.u32.u64 %0, t; }" : "=r"(a) : "l"(p));
    return a;
}

__device__ __forceinline__ void cpa16(uint32_t dst, const void* src) {
    asm volatile("cp.async.cg.shared.global [%0], [%1], 16;" :: "r"(dst), "l"(src));
}
#define CPA_COMMIT() asm volatile("cp.async.commit_group;" ::: "memory")
#define CPA_WAIT1()  asm volatile("cp.async.wait_group 1;" ::: "memory")
#define CPA_WAIT0()  asm volatile("cp.async.wait_group 0;" ::: "memory")

// smem tiling: 4 tiles (Ah, Al, Bh, Bl), each 128 rows x 40 bf16
#define TSTRIDE 40
#define TE (128 * TSTRIDE)
#define BUFE (4 * TE)
#define STAGE_BYTES (BUFE * 2)              // 40960
#define GEMM_SMEM_BYTES (2 * STAGE_BYTES)   // 81920
#define OFFB_AH 0
#define OFFB_AL (TE * 2)
#define OFFB_BH (2 * TE * 2)
#define OFFB_BL (3 * TE * 2)

// ======================= static device scratch =======================
__device__ __nv_bfloat16 d_h02[NN * 256];
__device__ __nv_bfloat16 d_agg2[NN * 512];
__device__ __nv_bfloat16 d_h2A[NN * 512];
__device__ __nv_bfloat16 d_h2B[NN * 512];
__device__ __nv_bfloat16 d_m1A2[(size_t)MROW * 16384];
__device__ __nv_bfloat16 d_w2[8][256 * 512];
__device__ __nv_bfloat16 d_m1w2[(size_t)256 * 16384];
__device__ int   d_cnt[NN];
__device__ int   d_off[NN + 1];
__device__ int   d_cur[NN];
__device__ int   d_csr[EE];
__device__ int   d_bsum[64];
__device__ float d_invcnt[NN];
__device__ float d_m1[MROW * HD];
__device__ float d_y[MROW];

// ======================= small kernels =======================
__global__ void concat2_kernel(const float* __restrict__ x, const float* __restrict__ g0,
                               const float* __restrict__ g1, const float* __restrict__ g2) {
    int i = blockIdx.x * blockDim.x + threadIdx.x;
    if (i >= NN * 128) return;
    int n = i >> 7, j = i & 127;
    float v;
    if (j < 32)       v = x[n * 32 + j];
    else if (j < 64)  v = g0[n * 32 + (j - 32)];
    else if (j < 96)  v = g1[n * 32 + (j - 64)];
    else              v = g2[n * 32 + (j - 96)];
    __nv_bfloat16 h, l; split_bf16(v, h, l);
    d_h02[n * 256 + j]       = h;
    d_h02[n * 256 + 128 + j] = l;
}

// All 9 weight conversions in ONE launch. Flat block id -> (matrix, 32x32 tile).
// m0-1: K=128 (32 tiles each), m2-7: K=256 (64 tiles each), m8: K=8192 (2048 tiles).
__global__ void conv_all(const float* __restrict__ W0, const float* __restrict__ W1,
                         const float* __restrict__ W2, const float* __restrict__ W3,
                         const float* __restrict__ W4, const float* __restrict__ W5,
                         const float* __restrict__ W6, const float* __restrict__ W7,
                         const float* __restrict__ W8) {
    __shared__ float tile[32][33];
    int bid = blockIdx.x;
    const float* W;
    __nv_bfloat16* out;
    int K, t;
    if (bid < 64) {
        int m = bid >> 5; t = bid & 31; K = 128;
        W = m ? W1 : W0;
        out = d_w2[m];
    } else if (bid < 448) {
        int m = 2 + ((bid - 64) >> 6); t = (bid - 64) & 63; K = 256;
        switch (m) {
            case 2: W = W2; break; case 3: W = W3; break;
            case 4: W = W4; break; case 5: W = W5; break;
            case 6: W = W6; break; default: W = W7; break;
        }
        out = d_w2[m];
    } else {
        t = bid - 448; K = 8192;
        W = W8;
        out = d_m1w2;
    }
    int tilesK = K >> 5;
    int kb = (t % tilesK) * 32;
    int nb = (t / tilesK) * 32;
    int tx = threadIdx.x, ty = threadIdx.y;   // 32 x 8
#pragma unroll
    for (int i = 0; i < 4; i++) {
        int k = kb + ty + i * 8;
        tile[ty + i * 8][tx] = W[(size_t)k * 256 + nb + tx];
    }
    __syncthreads();
#pragma unroll
    for (int i = 0; i < 4; i++) {
        int n = nb + ty + i * 8;
        int k = kb + tx;
        float v = tile[tx][ty + i * 8];
        __nv_bfloat16 h, l; split_bf16(v, h, l);
        out[(size_t)n * 2 * K + k]     = h;
        out[(size_t)n * 2 * K + K + k] = l;
    }
}

__global__ void count_kernel(const int* __restrict__ dst) {
    int e = blockIdx.x * blockDim.x + threadIdx.x;
    if (e < EE) atomicAdd(&d_cnt[dst[e]], 1);
}

// -------- parallel scan (2 kernels) --------
__global__ void scanA() {
    __shared__ int s[1024];
    int b = blockIdx.x, t = threadIdx.x;
    int i = b * 1024 + t;
    int c = d_cnt[i];
    s[t] = c;
    __syncthreads();
    for (int o = 1; o < 1024; o <<= 1) {
        int v = (t >= o) ? s[t - o] : 0;
        __syncthreads();
        s[t] += v;
        __syncthreads();
    }
    d_off[i] = s[t] - c;
    if (t == 1023) d_bsum[b] = s[t];
    d_invcnt[i] = 1.0f / fmaxf((float)c, 1.0f);
    d_cur[i] = 0;
}

// scanC: adds inter-block prefix; each 256-thread block lies inside one 1024-node
// region, so the needed prefix (over d_bsum[0 .. (blockIdx>>2)-1]) is block-constant.
__global__ void scanC() {
    __shared__ int boff;
    int i = blockIdx.x * blockDim.x + threadIdx.x;
    if (threadIdx.x == 0) {
        int lim = blockIdx.x >> 2;
        int s = 0;
        for (int j = 0; j < lim; j++) s += d_bsum[j];
        boff = s;
    }
    __syncthreads();
    d_off[i] += boff;
    if (i == 0) {
        int s = 0;
        for (int j = 0; j < 64; j++) s += d_bsum[j];
        d_off[NN] = s;
    }
}

__global__ void fill_kernel(const int* __restrict__ src, const int* __restrict__ dst) {
    int e = blockIdx.x * blockDim.x + threadIdx.x;
    if (e >= EE) return;
    int d = dst[e];
    int p = atomicAdd(&d_cur[d], 1);
    d_csr[d_off[d] + p] = src[e];
}

// CSR mean-aggregation: warp per node, neighbor loop unrolled x2.
template <int D>
__global__ void agg_csr(const __nv_bfloat16* __restrict__ H2,
                        __nv_bfloat16* __restrict__ out2) {
    int w = (blockIdx.x * blockDim.x + threadIdx.x) >> 5;
    int lane = threadIdx.x & 31;
    if (w >= NN) return;
    int s0 = __ldg(&d_off[w]), s1 = __ldg(&d_off[w + 1]);
    constexpr int R = D / 64;
    float a0[R], a1[R];
#pragma unroll
    for (int r = 0; r < R; r++) { a0[r] = 0.0f; a1[r] = 0.0f; }

    int p = s0;
    for (; p + 2 <= s1; p += 2) {
        int nbA = __ldg(&d_csr[p]);
        int nbB = __ldg(&d_csr[p + 1]);
        const __nv_bfloat16* baseA = H2 + (size_t)nbA * (2 * D);
        const __nv_bfloat16* baseB = H2 + (size_t)nbB * (2 * D);
#pragma unroll
        for (int r = 0; r < R; r++) {
            int c2 = (lane + r * 32) * 2;
            __nv_bfloat162 hA = *reinterpret_cast<const __nv_bfloat162*>(baseA + c2);
            __nv_bfloat162 lA = *reinterpret_cast<const __nv_bfloat162*>(baseA + D + c2);
            __nv_bfloat162 hB = *reinterpret_cast<const __nv_bfloat162*>(baseB + c2);
            __nv_bfloat162 lB = *reinterpret_cast<const __nv_bfloat162*>(baseB + D + c2);
            float2 hfA = __bfloat1622float2(hA);
            float2 lfA = __bfloat1622float2(lA);
            float2 hfB = __bfloat1622float2(hB);
            float2 lfB = __bfloat1622float2(lB);
            a0[r] += (hfA.x + lfA.x) + (hfB.x + lfB.x);
            a1[r] += (hfA.y + lfA.y) + (hfB.y + lfB.y);
        }
    }
    if (p < s1) {
        int nb = __ldg(&d_csr[p]);
        const __nv_bfloat16* base = H2 + (size_t)nb * (2 * D);
#pragma unroll
        for (int r = 0; r < R; r++) {
            int c2 = (lane + r * 32) * 2;
            __nv_bfloat162 hv = *reinterpret_cast<const __nv_bfloat162*>(base + c2);
            __nv_bfloat162 lv = *reinterpret_cast<const __nv_bfloat162*>(base + D + c2);
            float2 hf = __bfloat1622float2(hv);
            float2 lf = __bfloat1622float2(lv);
            a0[r] += hf.x + lf.x;
            a1[r] += hf.y + lf.y;
        }
    }

    float ic = d_invcnt[w];
    __nv_bfloat16* ob = out2 + (size_t)w * (2 * D);
#pragma unroll
    for (int r = 0; r < R; r++) {
        float v0 = a0[r] * ic, v1 = a1[r] * ic;
        __nv_bfloat16 h0, l0, h1, l1;
        split_bf16(v0, h0, l0);
        split_bf16(v1, h1, l1);
        int c2 = (lane + r * 32) * 2;
        *reinterpret_cast<__nv_bfloat162*>(ob + c2)     = __nv_bfloat162{h0, h1};
        *reinterpret_cast<__nv_bfloat162*>(ob + D + c2) = __nv_bfloat162{l0, l1};
    }
}

// ======================= GEMM compute core (ldmatrix, 3-term split) ===============
__device__ __forceinline__ void gemm_chunk(uint32_t stage, int wm, int wn, int lane,
                                           float acc[2][8][4]) {
    const uint32_t aBase = stage + OFFB_AH +
        (uint32_t)(((wm * 32 + (lane & 15)) * TSTRIDE + (lane >> 4) * 8) * 2);
    const uint32_t bBase = stage + OFFB_BH +
        (uint32_t)(((wn * 64 + (lane >> 4) * 8 + (lane & 7)) * TSTRIDE + ((lane >> 3) & 1) * 8) * 2);
    const uint32_t loA = OFFB_AL - OFFB_AH;
    const uint32_t loB = OFFB_BL - OFFB_BH;

#pragma unroll
    for (int kk = 0; kk < 32; kk += 16) {
        uint32_t afh[2][4], afl[2][4];
#pragma unroll
        for (int mt = 0; mt < 2; mt++) {
            uint32_t a = aBase + (uint32_t)((mt * 16 * TSTRIDE + kk) * 2);
            ldsm4(afh[mt], a);
            ldsm4(afl[mt], a + loA);
        }
#pragma unroll
        for (int np = 0; np < 4; np++) {
            uint32_t b = bBase + (uint32_t)((np * 16 * TSTRIDE + kk) * 2);
            uint32_t bh[4], bl[4];
            ldsm4(bh, b);
            ldsm4(bl, b + loB);
#pragma unroll
            for (int mt = 0; mt < 2; mt++) {
                mma16816(acc[mt][np * 2],     afh[mt], &bh[0]);
                mma16816(acc[mt][np * 2 + 1], afh[mt], &bh[2]);
                mma16816(acc[mt][np * 2],     afl[mt], &bh[0]);
                mma16816(acc[mt][np * 2 + 1], afl[mt], &bh[2]);
                mma16816(acc[mt][np * 2],     afh[mt], &bl[0]);
                mma16816(acc[mt][np * 2 + 1], afh[mt], &bl[2]);
            }
        }
    }
}

// ======================= SAGE layer GEMM (cp.async double-buffered) ===============
template <int K>
__global__ __launch_bounds__(256, 2)
void sage_mma(const __nv_bfloat16* __restrict__ agg2, const __nv_bfloat16* __restrict__ h2,
              const __nv_bfloat16* __restrict__ Wl2, const __nv_bfloat16* __restrict__ Wr2,
              const float* __restrict__ bias, __nv_bfloat16* __restrict__ out2, int mode) {
    extern __shared__ __nv_bfloat16 smdyn[];
    const uint32_t smbase = smem_u32(smdyn);

    const int tid = threadIdx.x;
    const int wid = tid >> 5, lane = tid & 31;
    const int wm = wid & 3, wn = wid >> 2;
    const int lr = lane >> 2, lq = lane & 3;
    const int bm = blockIdx.x * 128;
    const int bn = blockIdx.y * 128;
    constexpr int K2 = 2 * K;
    constexpr int CPS = K / 32;
    constexpr int NCH = 2 * CPS;

    const int r0 = tid >> 2;
    const int cb = (tid & 3) * 8;

    float acc[2][8][4];
#pragma unroll
    for (int i = 0; i < 2; i++)
#pragma unroll
        for (int j = 0; j < 8; j++)
#pragma unroll
            for (int t = 0; t < 4; t++) acc[i][j][t] = 0.0f;

    auto prefetch = [&](int ci, int b) {
        const __nv_bfloat16* Asrc = (ci < CPS) ? agg2 : h2;
        const __nv_bfloat16* Bsrc = (ci < CPS) ? Wl2 : Wr2;
        int c = ci & (CPS - 1);
        uint32_t sb = smbase + (uint32_t)b * STAGE_BYTES;
#pragma unroll
        for (int half = 0; half < 2; half++) {
            int r = r0 + half * 64;
            uint32_t so = (uint32_t)(r * TSTRIDE + cb) * 2;
            const __nv_bfloat16* Ap = Asrc + (size_t)(bm + r) * K2 + c * 32 + cb;
            const __nv_bfloat16* Bp = Bsrc + (size_t)(bn + r) * K2 + c * 32 + cb;
            cpa16(sb + OFFB_AH + so, Ap);
            cpa16(sb + OFFB_AL + so, Ap + K);
            cpa16(sb + OFFB_BH + so, Bp);
            cpa16(sb + OFFB_BL + so, Bp + K);
        }
        CPA_COMMIT();
    };

    prefetch(0, 0);
    for (int i = 0; i < NCH; i++) {
        int b = i & 1;
        if (i + 1 < NCH) { prefetch(i + 1, b ^ 1); CPA_WAIT1(); }
        else             { CPA_WAIT0(); }
        __syncthreads();
        gemm_chunk(smbase + (uint32_t)b * STAGE_BYTES, wm, wn, lane, acc);
        __syncthreads();
    }

    // epilogue: bias + relu + hi/lo split
#pragma unroll
    for (int mt = 0; mt < 2; mt++) {
#pragma unroll
        for (int nt = 0; nt < 8; nt++) {
            int col = bn + wn * 64 + nt * 8 + lq * 2;
            float bs0 = __ldg(&bias[col]), bs1 = __ldg(&bias[col + 1]);
#pragma unroll
            for (int half = 0; half < 2; half++) {
                int grow = bm + wm * 32 + mt * 16 + lr + half * 8;
                float v0 = fmaxf(acc[mt][nt][half * 2 + 0] + bs0, 0.0f);
                float v1 = fmaxf(acc[mt][nt][half * 2 + 1] + bs1, 0.0f);
                __nv_bfloat16 h0, l0, h1, l1;
                split_bf16(v0, h0, l0);
                split_bf16(v1, h1, l1);
                if (mode == 0) {
                    *reinterpret_cast<__nv_bfloat162*>(&out2[(size_t)grow * 512 + col]) =
                        __nv_bfloat162{h0, h1};
                    *reinterpret_cast<__nv_bfloat162*>(&out2[(size_t)grow * 512 + 256 + col]) =
                        __nv_bfloat162{l0, l1};
                } else {
                    int R = grow >> 5;
                    int m = ((grow & 31) << 8) + col;
                    *reinterpret_cast<__nv_bfloat162*>(&out2[(size_t)R * 16384 + m]) =
                        __nv_bfloat162{h0, h1};
                    *reinterpret_cast<__nv_bfloat162*>(&out2[(size_t)R * 16384 + 8192 + m]) =
                        __nv_bfloat162{l0, l1};
                }
            }
        }
    }
}

// ======================= mlp1 GEMM (split-K=8, cp.async, atomic accum) ============
__global__ __launch_bounds__(256, 2)
void mlp1_mma(const __nv_bfloat16* __restrict__ A2, const __nv_bfloat16* __restrict__ W2t,
              float* __restrict__ C) {
    extern __shared__ __nv_bfloat16 smdyn[];
    const uint32_t smbase = smem_u32(smdyn);

    const int tid = threadIdx.x;
    const int wid = tid >> 5, lane = tid & 31;
    const int wm = wid & 3, wn = wid >> 2;
    const int lr = lane >> 2, lq = lane & 3;
    const int bm = blockIdx.x * 128;
    const int bn = blockIdx.y * 128;
    const int g0 = blockIdx.z * 32;
    const int NCH = 32;

    const int r0 = tid >> 2;
    const int cb = (tid & 3) * 8;

    float acc[2][8][4];
#pragma unroll
    for (int i = 0; i < 2; i++)
#pragma unroll
        for (int j = 0; j < 8; j++)
#pragma unroll
            for (int t = 0; t < 4; t++) acc[i][j][t] = 0.0f;

    auto prefetch = [&](int i, int b) {
        int c = g0 + i;
        uint32_t sb = smbase + (uint32_t)b * STAGE_BYTES;
#pragma unroll
        for (int half = 0; half < 2; half++) {
            int r = r0 + half * 64;
            uint32_t so = (uint32_t)(r * TSTRIDE + cb) * 2;
            const __nv_bfloat16* Ap = A2 + (size_t)(bm + r) * 16384 + c * 32 + cb;
            const __nv_bfloat16* Bp = W2t + (size_t)(bn + r) * 16384 + c * 32 + cb;
            cpa16(sb + OFFB_AH + so, Ap);
            cpa16(sb + OFFB_AL + so, Ap + 8192);
            cpa16(sb + OFFB_BH + so, Bp);
            cpa16(sb + OFFB_BL + so, Bp + 8192);
        }
        CPA_COMMIT();
    };

    prefetch(0, 0);
    for (int i = 0; i < NCH; i++) {
        int b = i & 1;
        if (i + 1 < NCH) { prefetch(i + 1, b ^ 1); CPA_WAIT1(); }
        else             { CPA_WAIT0(); }
        __syncthreads();
        gemm_chunk(smbase + (uint32_t)b * STAGE_BYTES, wm, wn, lane, acc);
        __syncthreads();
    }

#pragma unroll
    for (int mt = 0; mt < 2; mt++) {
#pragma unroll
        for (int nt = 0; nt < 8; nt++) {
            int col = bn + wn * 64 + nt * 8 + lq * 2;
#pragma unroll
            for (int half = 0; half < 2; half++) {
                int row = bm + wm * 32 + mt * 16 + lr + half * 8;
                atomicAdd(&C[(size_t)row * 256 + col],     acc[mt][nt][half * 2 + 0]);
                atomicAdd(&C[(size_t)row * 256 + col + 1], acc[mt][nt][half * 2 + 1]);
            }
        }
    }
}

// ======================= tail kernels =======================
__global__ void mlp1_finalize(const float* __restrict__ M1, const float* __restrict__ b1,
                              const float* __restrict__ W2, const float* __restrict__ b2,
                              float* __restrict__ y) {
    int row = (blockIdx.x * blockDim.x + threadIdx.x) >> 5;
    int lane = threadIdx.x & 31;
    if (row >= MROW) return;
    float s = 0.0f;
    for (int c = lane; c < HD; c += 32)
        s += fmaxf(M1[row * HD + c] + b1[c], 0.0f) * W2[c];
#pragma unroll
    for (int o = 16; o; o >>= 1) s += __shfl_xor_sync(0xffffffffu, s, o);
    if (lane == 0) y[row] = s + b2[0];
}

// fused batchnorm + relu + mlp2 (single block, 256 threads)
__global__ void tail_kernel(const float* __restrict__ y, const float* __restrict__ gamma,
                            const float* __restrict__ beta,
                            const float* __restrict__ W1, const float* __restrict__ b1,
                            const float* __restrict__ W2, const float* __restrict__ b2,
                            float* __restrict__ out) {
    __shared__ float ybn[NB][HD];
    __shared__ float zs[NB][HD];
    int j = threadIdx.x;
    float v[NB];
    float m = 0.0f;
#pragma unroll
    for (int b = 0; b < NB; b++) { v[b] = y[b * HD + j]; m += v[b]; }
    m *= (1.0f / NB);
    float var = 0.0f;
#pragma unroll
    for (int b = 0; b < NB; b++) { float d = v[b] - m; var += d * d; }
    var *= (1.0f / NB);
    float inv = rsqrtf(var + 1e-5f) * gamma[j];
    float be = beta[j];
#pragma unroll
    for (int b = 0; b < NB; b++)
        ybn[b][j] = fmaxf((v[b] - m) * inv + be, 0.0f);
    __syncthreads();

    float z[NB];
#pragma unroll
    for (int b = 0; b < NB; b++) z[b] = b1[j];
    for (int hh = 0; hh < HD; hh++) {
        float w = W1[hh * HD + j];
#pragma unroll
        for (int b = 0; b < NB; b++) z[b] += ybn[b][hh] * w;
    }
#pragma unroll
    for (int b = 0; b < NB; b++) zs[b][j] = fmaxf(z[b], 0.0f);
    __syncthreads();

    if (j < NB * 8) {
        int b = j >> 3, o = j & 7;
        float s = b2[o];
        for (int jj = 0; jj < HD; jj++) s += zs[b][jj] * W2[jj * 8 + o];
        out[j] = s;
    }
}

// ======================= host launch =======================
extern "C" void kernel_launch(void* const* d_in, const int* in_sizes, int n_in,
                              void* d_out, int out_size) {
    const float* x    = (const float*)d_in[0];
    const float* g0   = (const float*)d_in[1];
    const float* g1   = (const float*)d_in[2];
    const float* g2   = (const float*)d_in[3];
    const int*   esrc = (const int*)d_in[4];
    const int*   edst = (const int*)d_in[5];
    const float* Wl0  = (const float*)d_in[6];
    const float* Wr0  = (const float*)d_in[7];
    const float* b0   = (const float*)d_in[8];
    const float* Wl1  = (const float*)d_in[9];
    const float* Wr1  = (const float*)d_in[10];
    const float* b1   = (const float*)d_in[11];
    const float* Wl2  = (const float*)d_in[12];
    const float* Wr2  = (const float*)d_in[13];
    const float* b2   = (const float*)d_in[14];
    const float* Wl3  = (const float*)d_in[15];
    const float* Wr3  = (const float*)d_in[16];
    const float* b3   = (const float*)d_in[17];
    const float* m1W1 = (const float*)d_in[18];
    const float* m1b1 = (const float*)d_in[19];
    const float* m1W2 = (const float*)d_in[20];
    const float* m1b2 = (const float*)d_in[21];
    const float* gam  = (const float*)d_in[22];
    const float* bet  = (const float*)d_in[23];
    const float* m2W1 = (const float*)d_in[24];
    const float* m2b1 = (const float*)d_in[25];
    const float* m2W2 = (const float*)d_in[26];
    const float* m2b2 = (const float*)d_in[27];

    __nv_bfloat16 *h02, *agg2, *h2A, *h2B, *m1A2, *w2, *m1w2;
    int *cnt;
    float *m1, *y;
    cudaGetSymbolAddress((void**)&h02, d_h02);
    cudaGetSymbolAddress((void**)&agg2, d_agg2);
    cudaGetSymbolAddress((void**)&h2A, d_h2A);
    cudaGetSymbolAddress((void**)&h2B, d_h2B);
    cudaGetSymbolAddress((void**)&m1A2, d_m1A2);
    cudaGetSymbolAddress((void**)&w2, d_w2);
    cudaGetSymbolAddress((void**)&m1w2, d_m1w2);
    cudaGetSymbolAddress((void**)&cnt, d_cnt);
    cudaGetSymbolAddress((void**)&m1, d_m1);
    cudaGetSymbolAddress((void**)&y, d_y);

    cudaFuncSetAttribute(sage_mma<128>, cudaFuncAttributeMaxDynamicSharedMemorySize, GEMM_SMEM_BYTES);
    cudaFuncSetAttribute(sage_mma<256>, cudaFuncAttributeMaxDynamicSharedMemorySize, GEMM_SMEM_BYTES);
    cudaFuncSetAttribute(mlp1_mma,      cudaFuncAttributeMaxDynamicSharedMemorySize, GEMM_SMEM_BYTES);

    __nv_bfloat16* wl[4] = {w2 + 0 * 256 * 512, w2 + 2 * 256 * 512, w2 + 4 * 256 * 512, w2 + 6 * 256 * 512};
    __nv_bfloat16* wr[4] = {w2 + 1 * 256 * 512, w2 + 3 * 256 * 512, w2 + 5 * 256 * 512, w2 + 7 * 256 * 512};

    // CSR build with parallel scan
    cudaMemsetAsync(cnt, 0, NN * sizeof(int), 0);
    count_kernel<<<EE / 256, 256>>>(edst);
    scanA<<<64, 1024>>>();
    scanC<<<NN / 256, 256>>>();
    fill_kernel<<<EE / 256, 256>>>(esrc, edst);
    concat2_kernel<<<(NN * 128) / 256, 256>>>(x, g0, g1, g2);

    // all weight conversions in one launch
    conv_all<<<2496, dim3(32, 8)>>>(Wl0, Wr0, Wl1, Wr1, Wl2, Wr2, Wl3, Wr3, m1W1);

    agg_csr<128><<<NN / 8, 256>>>(h02, agg2);
    sage_mma<128><<<dim3(NN / 128, 2), 256, GEMM_SMEM_BYTES>>>(agg2, h02, wl[0], wr[0], b0, h2A, 0);
    agg_csr<256><<<NN / 8, 256>>>(h2A, agg2);
    sage_mma<256><<<dim3(NN / 128, 2), 256, GEMM_SMEM_BYTES>>>(agg2, h2A, wl[1], wr[1], b1, h2B, 0);
    agg_csr<256><<<NN / 8, 256>>>(h2B, agg2);
    sage_mma<256><<<dim3(NN / 128, 2), 256, GEMM_SMEM_BYTES>>>(agg2, h2B, wl[2], wr[2], b2, h2A, 0);
    agg_csr<256><<<NN / 8, 256>>>(h2A, agg2);
    sage_mma<256><<<dim3(NN / 128, 2), 256, GEMM_SMEM_BYTES>>>(agg2, h2A, wl[3], wr[3], b3, m1A2, 1);

    cudaMemsetAsync(m1, 0, (size_t)MROW * HD * sizeof(float), 0);
    mlp1_mma<<<dim3(MROW / 128, 2, 8), 256, GEMM_SMEM_BYTES>>>(m1A2, m1w2, m1);
    mlp1_finalize<<<MROW / 8, 256>>>(m1, m1b1, m1W2, m1b2, y);

    tail_kernel<<<1, 256>>>(y, gam, bet, m2W1, m2b1, m2W2, m2b2, (float*)d_out);
}

// round 15
// speedup vs baseline: 1.3378x; 1.0428x over previous
#include <cuda_runtime.h>
#include <cuda_bf16.h>
#include <cstdint>

#define NN   65536
#define EE   524288
#define DIN  128
#define HD   256
#define NB   8
#define MROW 2048   // NB * HD

// ======================= helpers =======================
__device__ __forceinline__ void split_bf16(float v, __nv_bfloat16& h, __nv_bfloat16& l) {
    h = __float2bfloat16(v);
    l = __float2bfloat16(v - __bfloat162float(h));
}

// bf16x2-packed-word -> fp32 lanes, pure ALU (no reinterpret of memory)
__device__ __forceinline__ float bflo(uint32_t v) { return __uint_as_float(v << 16); }
__device__ __forceinline__ float bfhi(uint32_t v) { return __uint_as_float(v & 0xffff0000u); }

// pack two fp32 -> (hiWord, loWord) of the hi/lo bf16 split, bit-assembled
__device__ __forceinline__ void split_pack(float v0, float v1, uint32_t& hw, uint32_t& lw) {
    __nv_bfloat16 h0, l0, h1, l1;
    split_bf16(v0, h0, l0);
    split_bf16(v1, h1, l1);
    hw = (uint32_t)__bfloat16_as_ushort(h0) | ((uint32_t)__bfloat16_as_ushort(h1) << 16);
    lw = (uint32_t)__bfloat16_as_ushort(l0) | ((uint32_t)__bfloat16_as_ushort(l1) << 16);
}

__device__ __forceinline__ void mma16816(float* c, const uint32_t* a, const uint32_t* b) {
    asm volatile(
        "mma.sync.aligned.m16n8k16.row.col.f32.bf16.bf16.f32 "
        "{%0,%1,%2,%3}, {%4,%5,%6,%7}, {%8,%9}, {%0,%1,%2,%3};"
        : "+f"(c[0]), "+f"(c[1]), "+f"(c[2]), "+f"(c[3])
        : "r"(a[0]), "r"(a[1]), "r"(a[2]), "r"(a[3]), "r"(b[0]), "r"(b[1]));
}

__device__ __forceinline__ void ldsm4(uint32_t* r, uint32_t addr) {
    asm volatile("ldmatrix.sync.aligned.m8n8.x4.shared.b16 {%0,%1,%2,%3}, [%4];"
        : "=r"(r[0]), "=r"(r[1]), "=r"(r[2]), "=r"(r[3]) : "r"(addr));
}

__device__ __forceinline__ uint32_t smem_u32(const void* p) {
    uint32_t a;
    asm("{ .reg .u64 t; cvta.to.shared.u64 t, %1; cvt.u32.u64 %0, t; }" : "=r"(a) : "l"(p));
    return a;
}

__device__ __forceinline__ void cpa16(uint32_t dst, const void* src) {
    asm volatile("cp.async.cg.shared.global [%0], [%1], 16;" :: "r"(dst), "l"(src));
}
#define CPA_COMMIT() asm volatile("cp.async.commit_group;" ::: "memory")
#define CPA_WAIT1()  asm volatile("cp.async.wait_group 1;" ::: "memory")
#define CPA_WAIT0()  asm volatile("cp.async.wait_group 0;" ::: "memory")

// smem tiling: 4 tiles (Ah, Al, Bh, Bl), each 128 rows x 40 bf16
#define TSTRIDE 40
#define TE (128 * TSTRIDE)
#define BUFE (4 * TE)
#define STAGE_BYTES (BUFE * 2)              // 40960
#define GEMM_SMEM_BYTES (2 * STAGE_BYTES)   // 81920
#define OFFB_AH 0
#define OFFB_AL (TE * 2)
#define OFFB_BH (2 * TE * 2)
#define OFFB_BL (3 * TE * 2)

// ======================= static device scratch =======================
__device__ __nv_bfloat16 d_h02[NN * 256];
__device__ __nv_bfloat16 d_agg2[NN * 512];
__device__ __nv_bfloat16 d_h2A[NN * 512];
__device__ __nv_bfloat16 d_h2B[NN * 512];
__device__ __nv_bfloat16 d_m1A2[(size_t)MROW * 16384];
__device__ __nv_bfloat16 d_w2[8][256 * 512];
__device__ __nv_bfloat16 d_m1w2[(size_t)256 * 16384];
__device__ int   d_cnt[NN];
__device__ int   d_off[NN + 1];
__device__ int   d_cur[NN];
__device__ int   d_csr[EE];
__device__ int   d_bsum[64];
__device__ float d_invcnt[NN];
__device__ float d_m1[MROW * HD];
__device__ float d_y[MROW];

// ======================= small kernels =======================
__global__ void concat2_kernel(const float* __restrict__ x, const float* __restrict__ g0,
                               const float* __restrict__ g1, const float* __restrict__ g2) {
    int i = blockIdx.x * blockDim.x + threadIdx.x;
    if (i >= NN * 128) return;
    int n = i >> 7, j = i & 127;
    float v;
    if (j < 32)       v = x[n * 32 + j];
    else if (j < 64)  v = g0[n * 32 + (j - 32)];
    else if (j < 96)  v = g1[n * 32 + (j - 64)];
    else              v = g2[n * 32 + (j - 96)];
    __nv_bfloat16 h, l; split_bf16(v, h, l);
    d_h02[n * 256 + j]       = h;
    d_h02[n * 256 + 128 + j] = l;
}

// All 9 weight conversions in ONE launch (verified R14).
__global__ void conv_all(const float* __restrict__ W0, const float* __restrict__ W1,
                         const float* __restrict__ W2, const float* __restrict__ W3,
                         const float* __restrict__ W4, const float* __restrict__ W5,
                         const float* __restrict__ W6, const float* __restrict__ W7,
                         const float* __restrict__ W8) {
    __shared__ float tile[32][33];
    int bid = blockIdx.x;
    const float* W;
    __nv_bfloat16* out;
    int K, t;
    if (bid < 64) {
        int m = bid >> 5; t = bid & 31; K = 128;
        W = m ? W1 : W0;
        out = d_w2[m];
    } else if (bid < 448) {
        int m = 2 + ((bid - 64) >> 6); t = (bid - 64) & 63; K = 256;
        switch (m) {
            case 2: W = W2; break; case 3: W = W3; break;
            case 4: W = W4; break; case 5: W = W5; break;
            case 6: W = W6; break; default: W = W7; break;
        }
        out = d_w2[m];
    } else {
        t = bid - 448; K = 8192;
        W = W8;
        out = d_m1w2;
    }
    int tilesK = K >> 5;
    int kb = (t % tilesK) * 32;
    int nb = (t / tilesK) * 32;
    int tx = threadIdx.x, ty = threadIdx.y;
#pragma unroll
    for (int i = 0; i < 4; i++) {
        int k = kb + ty + i * 8;
        tile[ty + i * 8][tx] = W[(size_t)k * 256 + nb + tx];
    }
    __syncthreads();
#pragma unroll
    for (int i = 0; i < 4; i++) {
        int n = nb + ty + i * 8;
        int k = kb + tx;
        float v = tile[tx][ty + i * 8];
        __nv_bfloat16 h, l; split_bf16(v, h, l);
        out[(size_t)n * 2 * K + k]     = h;
        out[(size_t)n * 2 * K + K + k] = l;
    }
}

__global__ void count_kernel(const int* __restrict__ dst) {
    int e = blockIdx.x * blockDim.x + threadIdx.x;
    if (e < EE) atomicAdd(&d_cnt[dst[e]], 1);
}

// -------- parallel scan (2 kernels) --------
__global__ void scanA() {
    __shared__ int s[1024];
    int b = blockIdx.x, t = threadIdx.x;
    int i = b * 1024 + t;
    int c = d_cnt[i];
    s[t] = c;
    __syncthreads();
    for (int o = 1; o < 1024; o <<= 1) {
        int v = (t >= o) ? s[t - o] : 0;
        __syncthreads();
        s[t] += v;
        __syncthreads();
    }
    d_off[i] = s[t] - c;
    if (t == 1023) d_bsum[b] = s[t];
    d_invcnt[i] = 1.0f / fmaxf((float)c, 1.0f);
    d_cur[i] = 0;
}

__global__ void scanC() {
    __shared__ int boff;
    int i = blockIdx.x * blockDim.x + threadIdx.x;
    if (threadIdx.x == 0) {
        int lim = blockIdx.x >> 2;
        int s = 0;
        for (int j = 0; j < lim; j++) s += d_bsum[j];
        boff = s;
    }
    __syncthreads();
    d_off[i] += boff;
    if (i == 0) {
        int s = 0;
        for (int j = 0; j < 64; j++) s += d_bsum[j];
        d_off[NN] = s;
    }
}

__global__ void fill_kernel(const int* __restrict__ src, const int* __restrict__ dst) {
    int e = blockIdx.x * blockDim.x + threadIdx.x;
    if (e >= EE) return;
    int d = dst[e];
    int p = atomicAdd(&d_cur[d], 1);
    d_csr[d_off[d] + p] = src[e];
}

// CSR mean-aggregation: warp per node, wide vector loads + ALU bf16 unpack.
// Rows [hi(D) | lo(D)] bf16; lane covers V = D/32 consecutive columns.
template <int D>
__global__ void agg_csr(const __nv_bfloat16* __restrict__ H2,
                        __nv_bfloat16* __restrict__ out2) {
    int w = (blockIdx.x * blockDim.x + threadIdx.x) >> 5;
    int lane = threadIdx.x & 31;
    if (w >= NN) return;
    int s0 = __ldg(&d_off[w]), s1 = __ldg(&d_off[w + 1]);
    constexpr int V = D / 32;       // 8 (D=256) or 4 (D=128)
    constexpr int LOW = D / 2;      // lo-half offset in uint32 words
    float acc[V];
#pragma unroll
    for (int v = 0; v < V; v++) acc[v] = 0.0f;

    const uint32_t* H32 = reinterpret_cast<const uint32_t*>(H2);

    int p = s0;
    for (; p + 2 <= s1; p += 2) {
        int nbA = __ldg(&d_csr[p]);
        int nbB = __ldg(&d_csr[p + 1]);
        const uint32_t* pa = H32 + (size_t)nbA * D + lane * (V / 2);
        const uint32_t* pb = H32 + (size_t)nbB * D + lane * (V / 2);
        if (V == 8) {
            uint4 ha = *reinterpret_cast<const uint4*>(pa);
            uint4 la = *reinterpret_cast<const uint4*>(pa + LOW);
            uint4 hb = *reinterpret_cast<const uint4*>(pb);
            uint4 lb = *reinterpret_cast<const uint4*>(pb + LOW);
            acc[0] += (bflo(ha.x) + bflo(la.x)) + (bflo(hb.x) + bflo(lb.x));
            acc[1] += (bfhi(ha.x) + bfhi(la.x)) + (bfhi(hb.x) + bfhi(lb.x));
            acc[2] += (bflo(ha.y) + bflo(la.y)) + (bflo(hb.y) + bflo(lb.y));
            acc[3] += (bfhi(ha.y) + bfhi(la.y)) + (bfhi(hb.y) + bfhi(lb.y));
            acc[4] += (bflo(ha.z) + bflo(la.z)) + (bflo(hb.z) + bflo(lb.z));
            acc[5] += (bfhi(ha.z) + bfhi(la.z)) + (bfhi(hb.z) + bfhi(lb.z));
            acc[6] += (bflo(ha.w) + bflo(la.w)) + (bflo(hb.w) + bflo(lb.w));
            acc[7] += (bfhi(ha.w) + bfhi(la.w)) + (bfhi(hb.w) + bfhi(lb.w));
        } else {
            uint2 ha = *reinterpret_cast<const uint2*>(pa);
            uint2 la = *reinterpret_cast<const uint2*>(pa + LOW);
            uint2 hb = *reinterpret_cast<const uint2*>(pb);
            uint2 lb = *reinterpret_cast<const uint2*>(pb + LOW);
            acc[0] += (bflo(ha.x) + bflo(la.x)) + (bflo(hb.x) + bflo(lb.x));
            acc[1] += (bfhi(ha.x) + bfhi(la.x)) + (bfhi(hb.x) + bfhi(lb.x));
            acc[2] += (bflo(ha.y) + bflo(la.y)) + (bflo(hb.y) + bflo(lb.y));
            acc[3] += (bfhi(ha.y) + bfhi(la.y)) + (bfhi(hb.y) + bfhi(lb.y));
        }
    }
    if (p < s1) {
        int nb = __ldg(&d_csr[p]);
        const uint32_t* pa = H32 + (size_t)nb * D + lane * (V / 2);
        if (V == 8) {
            uint4 ha = *reinterpret_cast<const uint4*>(pa);
            uint4 la = *reinterpret_cast<const uint4*>(pa + LOW);
            acc[0] += bflo(ha.x) + bflo(la.x);
            acc[1] += bfhi(ha.x) + bfhi(la.x);
            acc[2] += bflo(ha.y) + bflo(la.y);
            acc[3] += bfhi(ha.y) + bfhi(la.y);
            acc[4] += bflo(ha.z) + bflo(la.z);
            acc[5] += bfhi(ha.z) + bfhi(la.z);
            acc[6] += bflo(ha.w) + bflo(la.w);
            acc[7] += bfhi(ha.w) + bfhi(la.w);
        } else {
            uint2 ha = *reinterpret_cast<const uint2*>(pa);
            uint2 la = *reinterpret_cast<const uint2*>(pa + LOW);
            acc[0] += bflo(ha.x) + bflo(la.x);
            acc[1] += bfhi(ha.x) + bfhi(la.x);
            acc[2] += bflo(ha.y) + bflo(la.y);
            acc[3] += bfhi(ha.y) + bfhi(la.y);
        }
    }

    float ic = d_invcnt[w];
    uint32_t* ob = reinterpret_cast<uint32_t*>(out2) + (size_t)w * D + lane * (V / 2);
    if (V == 8) {
        uint4 hv, lv;
        split_pack(acc[0] * ic, acc[1] * ic, hv.x, lv.x);
        split_pack(acc[2] * ic, acc[3] * ic, hv.y, lv.y);
        split_pack(acc[4] * ic, acc[5] * ic, hv.z, lv.z);
        split_pack(acc[6] * ic, acc[7] * ic, hv.w, lv.w);
        *reinterpret_cast<uint4*>(ob)       = hv;
        *reinterpret_cast<uint4*>(ob + LOW) = lv;
    } else {
        uint2 hv, lv;
        split_pack(acc[0] * ic, acc[1] * ic, hv.x, lv.x);
        split_pack(acc[2] * ic, acc[3] * ic, hv.y, lv.y);
        *reinterpret_cast<uint2*>(ob)       = hv;
        *reinterpret_cast<uint2*>(ob + LOW) = lv;
    }
}

// ======================= GEMM compute core (ldmatrix, 3-term split) ===============
__device__ __forceinline__ void gemm_chunk(uint32_t stage, int wm, int wn, int lane,
                                           float acc[2][8][4]) {
    const uint32_t aBase = stage + OFFB_AH +
        (uint32_t)(((wm * 32 + (lane & 15)) * TSTRIDE + (lane >> 4) * 8) * 2);
    const uint32_t bBase = stage + OFFB_BH +
        (uint32_t)(((wn * 64 + (lane >> 4) * 8 + (lane & 7)) * TSTRIDE + ((lane >> 3) & 1) * 8) * 2);
    const uint32_t loA = OFFB_AL - OFFB_AH;
    const uint32_t loB = OFFB_BL - OFFB_BH;

#pragma unroll
    for (int kk = 0; kk < 32; kk += 16) {
        uint32_t afh[2][4], afl[2][4];
#pragma unroll
        for (int mt = 0; mt < 2; mt++) {
            uint32_t a = aBase + (uint32_t)((mt * 16 * TSTRIDE + kk) * 2);
            ldsm4(afh[mt], a);
            ldsm4(afl[mt], a + loA);
        }
#pragma unroll
        for (int np = 0; np < 4; np++) {
            uint32_t b = bBase + (uint32_t)((np * 16 * TSTRIDE + kk) * 2);
            uint32_t bh[4], bl[4];
            ldsm4(bh, b);
            ldsm4(bl, b + loB);
#pragma unroll
            for (int mt = 0; mt < 2; mt++) {
                mma16816(acc[mt][np * 2],     afh[mt], &bh[0]);
                mma16816(acc[mt][np * 2 + 1], afh[mt], &bh[2]);
                mma16816(acc[mt][np * 2],     afl[mt], &bh[0]);
                mma16816(acc[mt][np * 2 + 1], afl[mt], &bh[2]);
                mma16816(acc[mt][np * 2],     afh[mt], &bl[0]);
                mma16816(acc[mt][np * 2 + 1], afh[mt], &bl[2]);
            }
        }
    }
}

// ======================= SAGE layer GEMM (cp.async double-buffered) ===============
template <int K>
__global__ __launch_bounds__(256, 2)
void sage_mma(const __nv_bfloat16* __restrict__ agg2, const __nv_bfloat16* __restrict__ h2,
              const __nv_bfloat16* __restrict__ Wl2, const __nv_bfloat16* __restrict__ Wr2,
              const float* __restrict__ bias, __nv_bfloat16* __restrict__ out2, int mode) {
    extern __shared__ __nv_bfloat16 smdyn[];
    const uint32_t smbase = smem_u32(smdyn);

    const int tid = threadIdx.x;
    const int wid = tid >> 5, lane = tid & 31;
    const int wm = wid & 3, wn = wid >> 2;
    const int lr = lane >> 2, lq = lane & 3;
    const int bm = blockIdx.x * 128;
    const int bn = blockIdx.y * 128;
    constexpr int K2 = 2 * K;
    constexpr int CPS = K / 32;
    constexpr int NCH = 2 * CPS;

    const int r0 = tid >> 2;
    const int cb = (tid & 3) * 8;

    float acc[2][8][4];
#pragma unroll
    for (int i = 0; i < 2; i++)
#pragma unroll
        for (int j = 0; j < 8; j++)
#pragma unroll
            for (int t = 0; t < 4; t++) acc[i][j][t] = 0.0f;

    auto prefetch = [&](int ci, int b) {
        const __nv_bfloat16* Asrc = (ci < CPS) ? agg2 : h2;
        const __nv_bfloat16* Bsrc = (ci < CPS) ? Wl2 : Wr2;
        int c = ci & (CPS - 1);
        uint32_t sb = smbase + (uint32_t)b * STAGE_BYTES;
#pragma unroll
        for (int half = 0; half < 2; half++) {
            int r = r0 + half * 64;
            uint32_t so = (uint32_t)(r * TSTRIDE + cb) * 2;
            const __nv_bfloat16* Ap = Asrc + (size_t)(bm + r) * K2 + c * 32 + cb;
            const __nv_bfloat16* Bp = Bsrc + (size_t)(bn + r) * K2 + c * 32 + cb;
            cpa16(sb + OFFB_AH + so, Ap);
            cpa16(sb + OFFB_AL + so, Ap + K);
            cpa16(sb + OFFB_BH + so, Bp);
            cpa16(sb + OFFB_BL + so, Bp + K);
        }
        CPA_COMMIT();
    };

    prefetch(0, 0);
    for (int i = 0; i < NCH; i++) {
        int b = i & 1;
        if (i + 1 < NCH) { prefetch(i + 1, b ^ 1); CPA_WAIT1(); }
        else             { CPA_WAIT0(); }
        __syncthreads();
        gemm_chunk(smbase + (uint32_t)b * STAGE_BYTES, wm, wn, lane, acc);
        __syncthreads();
    }

    // epilogue: bias + relu + hi/lo split
#pragma unroll
    for (int mt = 0; mt < 2; mt++) {
#pragma unroll
        for (int nt = 0; nt < 8; nt++) {
            int col = bn + wn * 64 + nt * 8 + lq * 2;
            float bs0 = __ldg(&bias[col]), bs1 = __ldg(&bias[col + 1]);
#pragma unroll
            for (int half = 0; half < 2; half++) {
                int grow = bm + wm * 32 + mt * 16 + lr + half * 8;
                float v0 = fmaxf(acc[mt][nt][half * 2 + 0] + bs0, 0.0f);
                float v1 = fmaxf(acc[mt][nt][half * 2 + 1] + bs1, 0.0f);
                __nv_bfloat16 h0, l0, h1, l1;
                split_bf16(v0, h0, l0);
                split_bf16(v1, h1, l1);
                if (mode == 0) {
                    *reinterpret_cast<__nv_bfloat162*>(&out2[(size_t)grow * 512 + col]) =
                        __nv_bfloat162{h0, h1};
                    *reinterpret_cast<__nv_bfloat162*>(&out2[(size_t)grow * 512 + 256 + col]) =
                        __nv_bfloat162{l0, l1};
                } else {
                    int R = grow >> 5;
                    int m = ((grow & 31) << 8) + col;
                    *reinterpret_cast<__nv_bfloat162*>(&out2[(size_t)R * 16384 + m]) =
                        __nv_bfloat162{h0, h1};
                    *reinterpret_cast<__nv_bfloat162*>(&out2[(size_t)R * 16384 + 8192 + m]) =
                        __nv_bfloat162{l0, l1};
                }
            }
        }
    }
}

// ======================= mlp1 GEMM (split-K=8, cp.async, atomic accum) ============
__global__ __launch_bounds__(256, 2)
void mlp1_mma(const __nv_bfloat16* __restrict__ A2, const __nv_bfloat16* __restrict__ W2t,
              float* __restrict__ C) {
    extern __shared__ __nv_bfloat16 smdyn[];
    const uint32_t smbase = smem_u32(smdyn);

    const int tid = threadIdx.x;
    const int wid = tid >> 5, lane = tid & 31;
    const int wm = wid & 3, wn = wid >> 2;
    const int lr = lane >> 2, lq = lane & 3;
    const int bm = blockIdx.x * 128;
    const int bn = blockIdx.y * 128;
    const int g0 = blockIdx.z * 32;
    const int NCH = 32;

    const int r0 = tid >> 2;
    const int cb = (tid & 3) * 8;

    float acc[2][8][4];
#pragma unroll
    for (int i = 0; i < 2; i++)
#pragma unroll
        for (int j = 0; j < 8; j++)
#pragma unroll
            for (int t = 0; t < 4; t++) acc[i][j][t] = 0.0f;

    auto prefetch = [&](int i, int b) {
        int c = g0 + i;
        uint32_t sb = smbase + (uint32_t)b * STAGE_BYTES;
#pragma unroll
        for (int half = 0; half < 2; half++) {
            int r = r0 + half * 64;
            uint32_t so = (uint32_t)(r * TSTRIDE + cb) * 2;
            const __nv_bfloat16* Ap = A2 + (size_t)(bm + r) * 16384 + c * 32 + cb;
            const __nv_bfloat16* Bp = W2t + (size_t)(bn + r) * 16384 + c * 32 + cb;
            cpa16(sb + OFFB_AH + so, Ap);
            cpa16(sb + OFFB_AL + so, Ap + 8192);
            cpa16(sb + OFFB_BH + so, Bp);
            cpa16(sb + OFFB_BL + so, Bp + 8192);
        }
        CPA_COMMIT();
    };

    prefetch(0, 0);
    for (int i = 0; i < NCH; i++) {
        int b = i & 1;
        if (i + 1 < NCH) { prefetch(i + 1, b ^ 1); CPA_WAIT1(); }
        else             { CPA_WAIT0(); }
        __syncthreads();
        gemm_chunk(smbase + (uint32_t)b * STAGE_BYTES, wm, wn, lane, acc);
        __syncthreads();
    }

#pragma unroll
    for (int mt = 0; mt < 2; mt++) {
#pragma unroll
        for (int nt = 0; nt < 8; nt++) {
            int col = bn + wn * 64 + nt * 8 + lq * 2;
#pragma unroll
            for (int half = 0; half < 2; half++) {
                int row = bm + wm * 32 + mt * 16 + lr + half * 8;
                atomicAdd(&C[(size_t)row * 256 + col],     acc[mt][nt][half * 2 + 0]);
                atomicAdd(&C[(size_t)row * 256 + col + 1], acc[mt][nt][half * 2 + 1]);
            }
        }
    }
}

// ======================= tail kernels =======================
__global__ void mlp1_finalize(const float* __restrict__ M1, const float* __restrict__ b1,
                              const float* __restrict__ W2, const float* __restrict__ b2,
                              float* __restrict__ y) {
    int row = (blockIdx.x * blockDim.x + threadIdx.x) >> 5;
    int lane = threadIdx.x & 31;
    if (row >= MROW) return;
    float s = 0.0f;
    for (int c = lane; c < HD; c += 32)
        s += fmaxf(M1[row * HD + c] + b1[c], 0.0f) * W2[c];
#pragma unroll
    for (int o = 16; o; o >>= 1) s += __shfl_xor_sync(0xffffffffu, s, o);
    if (lane == 0) y[row] = s + b2[0];
}

// fused batchnorm + relu + mlp2 (single block, 256 threads)
__global__ void tail_kernel(const float* __restrict__ y, const float* __restrict__ gamma,
                            const float* __restrict__ beta,
                            const float* __restrict__ W1, const float* __restrict__ b1,
                            const float* __restrict__ W2, const float* __restrict__ b2,
                            float* __restrict__ out) {
    __shared__ float ybn[NB][HD];
    __shared__ float zs[NB][HD];
    int j = threadIdx.x;
    float v[NB];
    float m = 0.0f;
#pragma unroll
    for (int b = 0; b < NB; b++) { v[b] = y[b * HD + j]; m += v[b]; }
    m *= (1.0f / NB);
    float var = 0.0f;
#pragma unroll
    for (int b = 0; b < NB; b++) { float d = v[b] - m; var += d * d; }
    var *= (1.0f / NB);
    float inv = rsqrtf(var + 1e-5f) * gamma[j];
    float be = beta[j];
#pragma unroll
    for (int b = 0; b < NB; b++)
        ybn[b][j] = fmaxf((v[b] - m) * inv + be, 0.0f);
    __syncthreads();

    float z[NB];
#pragma unroll
    for (int b = 0; b < NB; b++) z[b] = b1[j];
    for (int hh = 0; hh < HD; hh++) {
        float w = W1[hh * HD + j];
#pragma unroll
        for (int b = 0; b < NB; b++) z[b] += ybn[b][hh] * w;
    }
#pragma unroll
    for (int b = 0; b < NB; b++) zs[b][j] = fmaxf(z[b], 0.0f);
    __syncthreads();

    if (j < NB * 8) {
        int b = j >> 3, o = j & 7;
        float s = b2[o];
        for (int jj = 0; jj < HD; jj++) s += zs[b][jj] * W2[jj * 8 + o];
        out[j] = s;
    }
}

// ======================= host launch =======================
extern "C" void kernel_launch(void* const* d_in, const int* in_sizes, int n_in,
                              void* d_out, int out_size) {
    const float* x    = (const float*)d_in[0];
    const float* g0   = (const float*)d_in[1];
    const float* g1   = (const float*)d_in[2];
    const float* g2   = (const float*)d_in[3];
    const int*   esrc = (const int*)d_in[4];
    const int*   edst = (const int*)d_in[5];
    const float* Wl0  = (const float*)d_in[6];
    const float* Wr0  = (const float*)d_in[7];
    const float* b0   = (const float*)d_in[8];
    const float* Wl1  = (const float*)d_in[9];
    const float* Wr1  = (const float*)d_in[10];
    const float* b1   = (const float*)d_in[11];
    const float* Wl2  = (const float*)d_in[12];
    const float* Wr2  = (const float*)d_in[13];
    const float* b2   = (const float*)d_in[14];
    const float* Wl3  = (const float*)d_in[15];
    const float* Wr3  = (const float*)d_in[16];
    const float* b3   = (const float*)d_in[17];
    const float* m1W1 = (const float*)d_in[18];
    const float* m1b1 = (const float*)d_in[19];
    const float* m1W2 = (const float*)d_in[20];
    const float* m1b2 = (const float*)d_in[21];
    const float* gam  = (const float*)d_in[22];
    const float* bet  = (const float*)d_in[23];
    const float* m2W1 = (const float*)d_in[24];
    const float* m2b1 = (const float*)d_in[25];
    const float* m2W2 = (const float*)d_in[26];
    const float* m2b2 = (const float*)d_in[27];

    __nv_bfloat16 *h02, *agg2, *h2A, *h2B, *m1A2, *w2, *m1w2;
    int *cnt;
    float *m1, *y;
    cudaGetSymbolAddress((void**)&h02, d_h02);
    cudaGetSymbolAddress((void**)&agg2, d_agg2);
    cudaGetSymbolAddress((void**)&h2A, d_h2A);
    cudaGetSymbolAddress((void**)&h2B, d_h2B);
    cudaGetSymbolAddress((void**)&m1A2, d_m1A2);
    cudaGetSymbolAddress((void**)&w2, d_w2);
    cudaGetSymbolAddress((void**)&m1w2, d_m1w2);
    cudaGetSymbolAddress((void**)&cnt, d_cnt);
    cudaGetSymbolAddress((void**)&m1, d_m1);
    cudaGetSymbolAddress((void**)&y, d_y);

    cudaFuncSetAttribute(sage_mma<128>, cudaFuncAttributeMaxDynamicSharedMemorySize, GEMM_SMEM_BYTES);
    cudaFuncSetAttribute(sage_mma<256>, cudaFuncAttributeMaxDynamicSharedMemorySize, GEMM_SMEM_BYTES);
    cudaFuncSetAttribute(mlp1_mma,      cudaFuncAttributeMaxDynamicSharedMemorySize, GEMM_SMEM_BYTES);

    __nv_bfloat16* wl[4] = {w2 + 0 * 256 * 512, w2 + 2 * 256 * 512, w2 + 4 * 256 * 512, w2 + 6 * 256 * 512};
    __nv_bfloat16* wr[4] = {w2 + 1 * 256 * 512, w2 + 3 * 256 * 512, w2 + 5 * 256 * 512, w2 + 7 * 256 * 512};

    // CSR build with parallel scan
    cudaMemsetAsync(cnt, 0, NN * sizeof(int), 0);
    count_kernel<<<EE / 256, 256>>>(edst);
    scanA<<<64, 1024>>>();
    scanC<<<NN / 256, 256>>>();
    fill_kernel<<<EE / 256, 256>>>(esrc, edst);
    concat2_kernel<<<(NN * 128) / 256, 256>>>(x, g0, g1, g2);

    // all weight conversions in one launch
    conv_all<<<2496, dim3(32, 8)>>>(Wl0, Wr0, Wl1, Wr1, Wl2, Wr2, Wl3, Wr3, m1W1);

    agg_csr<128><<<NN / 8, 256>>>(h02, agg2);
    sage_mma<128><<<dim3(NN / 128, 2), 256, GEMM_SMEM_BYTES>>>(agg2, h02, wl[0], wr[0], b0, h2A, 0);
    agg_csr<256><<<NN / 8, 256>>>(h2A, agg2);
    sage_mma<256><<<dim3(NN / 128, 2), 256, GEMM_SMEM_BYTES>>>(agg2, h2A, wl[1], wr[1], b1, h2B, 0);
    agg_csr<256><<<NN / 8, 256>>>(h2B, agg2);
    sage_mma<256><<<dim3(NN / 128, 2), 256, GEMM_SMEM_BYTES>>>(agg2, h2B, wl[2], wr[2], b2, h2A, 0);
    agg_csr<256><<<NN / 8, 256>>>(h2A, agg2);
    sage_mma<256><<<dim3(NN / 128, 2), 256, GEMM_SMEM_BYTES>>>(agg2, h2A, wl[3], wr[3], b3, m1A2, 1);

    cudaMemsetAsync(m1, 0, (size_t)MROW * HD * sizeof(float), 0);
    mlp1_mma<<<dim3(MROW / 128, 2, 8), 256, GEMM_SMEM_BYTES>>>(m1A2, m1w2, m1);
    mlp1_finalize<<<MROW / 8, 256>>>(m1, m1b1, m1W2, m1b2, y);

    tail_kernel<<<1, 256>>>(y, gam, bet, m2W1, m2b1, m2W2, m2b2, (float*)d_out);
}

// round 16
// speedup vs baseline: 1.3408x; 1.0023x over previous
#include <cuda_runtime.h>
#include <cuda_bf16.h>
#include <cstdint>

#define NN   65536
#define EE   524288
#define DIN  128
#define HD   256
#define NB   8
#define MROW 2048   // NB * HD

// ======================= helpers =======================
__device__ __forceinline__ void split_bf16(float v, __nv_bfloat16& h, __nv_bfloat16& l) {
    h = __float2bfloat16(v);
    l = __float2bfloat16(v - __bfloat162float(h));
}

// bf16x2-packed-word -> fp32 lanes, pure ALU
__device__ __forceinline__ float bflo(uint32_t v) { return __uint_as_float(v << 16); }
__device__ __forceinline__ float bfhi(uint32_t v) { return __uint_as_float(v & 0xffff0000u); }

__device__ __forceinline__ void split_pack(float v0, float v1, uint32_t& hw, uint32_t& lw) {
    __nv_bfloat16 h0, l0, h1, l1;
    split_bf16(v0, h0, l0);
    split_bf16(v1, h1, l1);
    hw = (uint32_t)__bfloat16_as_ushort(h0) | ((uint32_t)__bfloat16_as_ushort(h1) << 16);
    lw = (uint32_t)__bfloat16_as_ushort(l0) | ((uint32_t)__bfloat16_as_ushort(l1) << 16);
}

__device__ __forceinline__ void mma16816(float* c, const uint32_t* a, const uint32_t* b) {
    asm volatile(
        "mma.sync.aligned.m16n8k16.row.col.f32.bf16.bf16.f32 "
        "{%0,%1,%2,%3}, {%4,%5,%6,%7}, {%8,%9}, {%0,%1,%2,%3};"
        : "+f"(c[0]), "+f"(c[1]), "+f"(c[2]), "+f"(c[3])
        : "r"(a[0]), "r"(a[1]), "r"(a[2]), "r"(a[3]), "r"(b[0]), "r"(b[1]));
}

__device__ __forceinline__ void ldsm4(uint32_t* r, uint32_t addr) {
    asm volatile("ldmatrix.sync.aligned.m8n8.x4.shared.b16 {%0,%1,%2,%3}, [%4];"
        : "=r"(r[0]), "=r"(r[1]), "=r"(r[2]), "=r"(r[3]) : "r"(addr));
}

__device__ __forceinline__ uint32_t smem_u32(const void* p) {
    uint32_t a;
    asm("{ .reg .u64 t; cvta.to.shared.u64 t, %1; cvt.u32.u64 %0, t; }" : "=r"(a) : "l"(p));
    return a;
}

__device__ __forceinline__ void cpa16(uint32_t dst, const void* src) {
    asm volatile("cp.async.cg.shared.global [%0], [%1], 16;" :: "r"(dst), "l"(src));
}
#define CPA_COMMIT() asm volatile("cp.async.commit_group;" ::: "memory")
#define CPA_WAIT1()  asm volatile("cp.async.wait_group 1;" ::: "memory")
#define CPA_WAIT0()  asm volatile("cp.async.wait_group 0;" ::: "memory")

// smem tiling: 4 tiles (Ah, Al, Bh, Bl), each 128 rows x 40 bf16
#define TSTRIDE 40
#define TE (128 * TSTRIDE)
#define BUFE (4 * TE)
#define STAGE_BYTES (BUFE * 2)              // 40960
#define GEMM_SMEM_BYTES (2 * STAGE_BYTES)   // 81920
#define OFFB_AH 0
#define OFFB_AL (TE * 2)
#define OFFB_BH (2 * TE * 2)
#define OFFB_BL (3 * TE * 2)

// ======================= static device scratch =======================
__device__ __nv_bfloat16 d_h02[NN * 256];
__device__ __nv_bfloat16 d_agg2[NN * 512];
__device__ __nv_bfloat16 d_h2A[NN * 512];
__device__ __nv_bfloat16 d_h2B[NN * 512];
__device__ __nv_bfloat16 d_m1A2[(size_t)MROW * 16384];
__device__ __nv_bfloat16 d_w2[8][256 * 512];
__device__ __nv_bfloat16 d_m1w2[(size_t)256 * 16384];
__device__ int   d_cnt[NN];
__device__ int   d_off[NN + 1];
__device__ int   d_cur[NN];
__device__ int   d_csr[EE];
__device__ int   d_bsum[64];
__device__ float d_invcnt[NN];
__device__ float d_m1[MROW * HD];
__device__ float d_y[MROW];

// ======================= small kernels =======================
__global__ void concat2_kernel(const float* __restrict__ x, const float* __restrict__ g0,
                               const float* __restrict__ g1, const float* __restrict__ g2) {
    int i = blockIdx.x * blockDim.x + threadIdx.x;
    if (i >= NN * 128) return;
    int n = i >> 7, j = i & 127;
    float v;
    if (j < 32)       v = x[n * 32 + j];
    else if (j < 64)  v = g0[n * 32 + (j - 32)];
    else if (j < 96)  v = g1[n * 32 + (j - 64)];
    else              v = g2[n * 32 + (j - 96)];
    __nv_bfloat16 h, l; split_bf16(v, h, l);
    d_h02[n * 256 + j]       = h;
    d_h02[n * 256 + 128 + j] = l;
}

// All 9 weight conversions in ONE launch (verified R14).
__global__ void conv_all(const float* __restrict__ W0, const float* __restrict__ W1,
                         const float* __restrict__ W2, const float* __restrict__ W3,
                         const float* __restrict__ W4, const float* __restrict__ W5,
                         const float* __restrict__ W6, const float* __restrict__ W7,
                         const float* __restrict__ W8) {
    __shared__ float tile[32][33];
    int bid = blockIdx.x;
    const float* W;
    __nv_bfloat16* out;
    int K, t;
    if (bid < 64) {
        int m = bid >> 5; t = bid & 31; K = 128;
        W = m ? W1 : W0;
        out = d_w2[m];
    } else if (bid < 448) {
        int m = 2 + ((bid - 64) >> 6); t = (bid - 64) & 63; K = 256;
        switch (m) {
            case 2: W = W2; break; case 3: W = W3; break;
            case 4: W = W4; break; case 5: W = W5; break;
            case 6: W = W6; break; default: W = W7; break;
        }
        out = d_w2[m];
    } else {
        t = bid - 448; K = 8192;
        W = W8;
        out = d_m1w2;
    }
    int tilesK = K >> 5;
    int kb = (t % tilesK) * 32;
    int nb = (t / tilesK) * 32;
    int tx = threadIdx.x, ty = threadIdx.y;
#pragma unroll
    for (int i = 0; i < 4; i++) {
        int k = kb + ty + i * 8;
        tile[ty + i * 8][tx] = W[(size_t)k * 256 + nb + tx];
    }
    __syncthreads();
#pragma unroll
    for (int i = 0; i < 4; i++) {
        int n = nb + ty + i * 8;
        int k = kb + tx;
        float v = tile[tx][ty + i * 8];
        __nv_bfloat16 h, l; split_bf16(v, h, l);
        out[(size_t)n * 2 * K + k]     = h;
        out[(size_t)n * 2 * K + K + k] = l;
    }
}

__global__ void count_kernel(const int* __restrict__ dst) {
    int e = blockIdx.x * blockDim.x + threadIdx.x;
    if (e < EE) atomicAdd(&d_cnt[dst[e]], 1);
}

// -------- parallel scan --------
__global__ void scanA() {
    __shared__ int s[1024];
    int b = blockIdx.x, t = threadIdx.x;
    int i = b * 1024 + t;
    int c = d_cnt[i];
    s[t] = c;
    __syncthreads();
    for (int o = 1; o < 1024; o <<= 1) {
        int v = (t >= o) ? s[t - o] : 0;
        __syncthreads();
        s[t] += v;
        __syncthreads();
    }
    d_off[i] = s[t] - c;
    if (t == 1023) d_bsum[b] = s[t];
    d_invcnt[i] = 1.0f / fmaxf((float)c, 1.0f);
    d_cur[i] = 0;
}

__global__ void scanC() {
    __shared__ int boff;
    int i = blockIdx.x * blockDim.x + threadIdx.x;
    if (threadIdx.x == 0) {
        int lim = blockIdx.x >> 2;
        int s = 0;
        for (int j = 0; j < lim; j++) s += d_bsum[j];
        boff = s;
    }
    __syncthreads();
    d_off[i] += boff;
    if (i == 0) {
        int s = 0;
        for (int j = 0; j < 64; j++) s += d_bsum[j];
        d_off[NN] = s;
    }
}

__global__ void fill_kernel(const int* __restrict__ src, const int* __restrict__ dst) {
    int e = blockIdx.x * blockDim.x + threadIdx.x;
    if (e >= EE) return;
    int d = dst[e];
    int p = atomicAdd(&d_cur[d], 1);
    d_csr[d_off[d] + p] = src[e];
}

// CSR mean-aggregation: warp per node, wide vector loads + ALU bf16 unpack (verified R15).
template <int D>
__global__ void agg_csr(const __nv_bfloat16* __restrict__ H2,
                        __nv_bfloat16* __restrict__ out2) {
    int w = (blockIdx.x * blockDim.x + threadIdx.x) >> 5;
    int lane = threadIdx.x & 31;
    if (w >= NN) return;
    int s0 = __ldg(&d_off[w]), s1 = __ldg(&d_off[w + 1]);
    constexpr int V = D / 32;
    constexpr int LOW = D / 2;
    float acc[V];
#pragma unroll
    for (int v = 0; v < V; v++) acc[v] = 0.0f;

    const uint32_t* H32 = reinterpret_cast<const uint32_t*>(H2);

    int p = s0;
    for (; p + 2 <= s1; p += 2) {
        int nbA = __ldg(&d_csr[p]);
        int nbB = __ldg(&d_csr[p + 1]);
        const uint32_t* pa = H32 + (size_t)nbA * D + lane * (V / 2);
        const uint32_t* pb = H32 + (size_t)nbB * D + lane * (V / 2);
        if (V == 8) {
            uint4 ha = *reinterpret_cast<const uint4*>(pa);
            uint4 la = *reinterpret_cast<const uint4*>(pa + LOW);
            uint4 hb = *reinterpret_cast<const uint4*>(pb);
            uint4 lb = *reinterpret_cast<const uint4*>(pb + LOW);
            acc[0] += (bflo(ha.x) + bflo(la.x)) + (bflo(hb.x) + bflo(lb.x));
            acc[1] += (bfhi(ha.x) + bfhi(la.x)) + (bfhi(hb.x) + bfhi(lb.x));
            acc[2] += (bflo(ha.y) + bflo(la.y)) + (bflo(hb.y) + bflo(lb.y));
            acc[3] += (bfhi(ha.y) + bfhi(la.y)) + (bfhi(hb.y) + bfhi(lb.y));
            acc[4] += (bflo(ha.z) + bflo(la.z)) + (bflo(hb.z) + bflo(lb.z));
            acc[5] += (bfhi(ha.z) + bfhi(la.z)) + (bfhi(hb.z) + bfhi(lb.z));
            acc[6] += (bflo(ha.w) + bflo(la.w)) + (bflo(hb.w) + bflo(lb.w));
            acc[7] += (bfhi(ha.w) + bfhi(la.w)) + (bfhi(hb.w) + bfhi(lb.w));
        } else {
            uint2 ha = *reinterpret_cast<const uint2*>(pa);
            uint2 la = *reinterpret_cast<const uint2*>(pa + LOW);
            uint2 hb = *reinterpret_cast<const uint2*>(pb);
            uint2 lb = *reinterpret_cast<const uint2*>(pb + LOW);
            acc[0] += (bflo(ha.x) + bflo(la.x)) + (bflo(hb.x) + bflo(lb.x));
            acc[1] += (bfhi(ha.x) + bfhi(la.x)) + (bfhi(hb.x) + bfhi(lb.x));
            acc[2] += (bflo(ha.y) + bflo(la.y)) + (bflo(hb.y) + bflo(lb.y));
            acc[3] += (bfhi(ha.y) + bfhi(la.y)) + (bfhi(hb.y) + bfhi(lb.y));
        }
    }
    if (p < s1) {
        int nb = __ldg(&d_csr[p]);
        const uint32_t* pa = H32 + (size_t)nb * D + lane * (V / 2);
        if (V == 8) {
            uint4 ha = *reinterpret_cast<const uint4*>(pa);
            uint4 la = *reinterpret_cast<const uint4*>(pa + LOW);
            acc[0] += bflo(ha.x) + bflo(la.x);
            acc[1] += bfhi(ha.x) + bfhi(la.x);
            acc[2] += bflo(ha.y) + bflo(la.y);
            acc[3] += bfhi(ha.y) + bfhi(la.y);
            acc[4] += bflo(ha.z) + bflo(la.z);
            acc[5] += bfhi(ha.z) + bfhi(la.z);
            acc[6] += bflo(ha.w) + bflo(la.w);
            acc[7] += bfhi(ha.w) + bfhi(la.w);
        } else {
            uint2 ha = *reinterpret_cast<const uint2*>(pa);
            uint2 la = *reinterpret_cast<const uint2*>(pa + LOW);
            acc[0] += bflo(ha.x) + bflo(la.x);
            acc[1] += bfhi(ha.x) + bfhi(la.x);
            acc[2] += bflo(ha.y) + bflo(la.y);
            acc[3] += bfhi(ha.y) + bfhi(la.y);
        }
    }

    float ic = d_invcnt[w];
    uint32_t* ob = reinterpret_cast<uint32_t*>(out2) + (size_t)w * D + lane * (V / 2);
    if (V == 8) {
        uint4 hv, lv;
        split_pack(acc[0] * ic, acc[1] * ic, hv.x, lv.x);
        split_pack(acc[2] * ic, acc[3] * ic, hv.y, lv.y);
        split_pack(acc[4] * ic, acc[5] * ic, hv.z, lv.z);
        split_pack(acc[6] * ic, acc[7] * ic, hv.w, lv.w);
        *reinterpret_cast<uint4*>(ob)       = hv;
        *reinterpret_cast<uint4*>(ob + LOW) = lv;
    } else {
        uint2 hv, lv;
        split_pack(acc[0] * ic, acc[1] * ic, hv.x, lv.x);
        split_pack(acc[2] * ic, acc[3] * ic, hv.y, lv.y);
        *reinterpret_cast<uint2*>(ob)       = hv;
        *reinterpret_cast<uint2*>(ob + LOW) = lv;
    }
}

// ======================= GEMM compute core (ldmatrix, 3-term split) ===============
__device__ __forceinline__ void gemm_chunk(uint32_t stage, int wm, int wn, int lane,
                                           float acc[2][8][4]) {
    const uint32_t aBase = stage + OFFB_AH +
        (uint32_t)(((wm * 32 + (lane & 15)) * TSTRIDE + (lane >> 4) * 8) * 2);
    const uint32_t bBase = stage + OFFB_BH +
        (uint32_t)(((wn * 64 + (lane >> 4) * 8 + (lane & 7)) * TSTRIDE + ((lane >> 3) & 1) * 8) * 2);
    const uint32_t loA = OFFB_AL - OFFB_AH;
    const uint32_t loB = OFFB_BL - OFFB_BH;

#pragma unroll
    for (int kk = 0; kk < 32; kk += 16) {
        uint32_t afh[2][4], afl[2][4];
#pragma unroll
        for (int mt = 0; mt < 2; mt++) {
            uint32_t a = aBase + (uint32_t)((mt * 16 * TSTRIDE + kk) * 2);
            ldsm4(afh[mt], a);
            ldsm4(afl[mt], a + loA);
        }
#pragma unroll
        for (int np = 0; np < 4; np++) {
            uint32_t b = bBase + (uint32_t)((np * 16 * TSTRIDE + kk) * 2);
            uint32_t bh[4], bl[4];
            ldsm4(bh, b);
            ldsm4(bl, b + loB);
#pragma unroll
            for (int mt = 0; mt < 2; mt++) {
                mma16816(acc[mt][np * 2],     afh[mt], &bh[0]);
                mma16816(acc[mt][np * 2 + 1], afh[mt], &bh[2]);
                mma16816(acc[mt][np * 2],     afl[mt], &bh[0]);
                mma16816(acc[mt][np * 2 + 1], afl[mt], &bh[2]);
                mma16816(acc[mt][np * 2],     afh[mt], &bl[0]);
                mma16816(acc[mt][np * 2 + 1], afh[mt], &bl[2]);
            }
        }
    }
}

// ======================= SAGE layer GEMM =======================
// grid (2, NN/128): blockIdx.x = bn (fast), blockIdx.y = bm -> adjacent CTAs share A rows.
template <int K>
__global__ __launch_bounds__(256, 2)
void sage_mma(const __nv_bfloat16* __restrict__ agg2, const __nv_bfloat16* __restrict__ h2,
              const __nv_bfloat16* __restrict__ Wl2, const __nv_bfloat16* __restrict__ Wr2,
              const float* __restrict__ bias, __nv_bfloat16* __restrict__ out2, int mode) {
    extern __shared__ __nv_bfloat16 smdyn[];
    const uint32_t smbase = smem_u32(smdyn);

    const int tid = threadIdx.x;
    const int wid = tid >> 5, lane = tid & 31;
    const int wm = wid & 3, wn = wid >> 2;
    const int lr = lane >> 2, lq = lane & 3;
    const int bm = blockIdx.y * 128;
    const int bn = blockIdx.x * 128;
    constexpr int K2 = 2 * K;
    constexpr int CPS = K / 32;
    constexpr int NCH = 2 * CPS;

    const int r0 = tid >> 2;
    const int cb = (tid & 3) * 8;

    float acc[2][8][4];
#pragma unroll
    for (int i = 0; i < 2; i++)
#pragma unroll
        for (int j = 0; j < 8; j++)
#pragma unroll
            for (int t = 0; t < 4; t++) acc[i][j][t] = 0.0f;

    auto prefetch = [&](int ci, int b) {
        const __nv_bfloat16* Asrc = (ci < CPS) ? agg2 : h2;
        const __nv_bfloat16* Bsrc = (ci < CPS) ? Wl2 : Wr2;
        int c = ci & (CPS - 1);
        uint32_t sb = smbase + (uint32_t)b * STAGE_BYTES;
#pragma unroll
        for (int half = 0; half < 2; half++) {
            int r = r0 + half * 64;
            uint32_t so = (uint32_t)(r * TSTRIDE + cb) * 2;
            const __nv_bfloat16* Ap = Asrc + (size_t)(bm + r) * K2 + c * 32 + cb;
            const __nv_bfloat16* Bp = Bsrc + (size_t)(bn + r) * K2 + c * 32 + cb;
            cpa16(sb + OFFB_AH + so, Ap);
            cpa16(sb + OFFB_AL + so, Ap + K);
            cpa16(sb + OFFB_BH + so, Bp);
            cpa16(sb + OFFB_BL + so, Bp + K);
        }
        CPA_COMMIT();
    };

    prefetch(0, 0);
    for (int i = 0; i < NCH; i++) {
        int b = i & 1;
        if (i + 1 < NCH) { prefetch(i + 1, b ^ 1); CPA_WAIT1(); }
        else             { CPA_WAIT0(); }
        __syncthreads();
        gemm_chunk(smbase + (uint32_t)b * STAGE_BYTES, wm, wn, lane, acc);
        __syncthreads();
    }

    // epilogue: bias + relu + hi/lo split
#pragma unroll
    for (int mt = 0; mt < 2; mt++) {
#pragma unroll
        for (int nt = 0; nt < 8; nt++) {
            int col = bn + wn * 64 + nt * 8 + lq * 2;
            float bs0 = __ldg(&bias[col]), bs1 = __ldg(&bias[col + 1]);
#pragma unroll
            for (int half = 0; half < 2; half++) {
                int grow = bm + wm * 32 + mt * 16 + lr + half * 8;
                float v0 = fmaxf(acc[mt][nt][half * 2 + 0] + bs0, 0.0f);
                float v1 = fmaxf(acc[mt][nt][half * 2 + 1] + bs1, 0.0f);
                __nv_bfloat16 h0, l0, h1, l1;
                split_bf16(v0, h0, l0);
                split_bf16(v1, h1, l1);
                if (mode == 0) {
                    *reinterpret_cast<__nv_bfloat162*>(&out2[(size_t)grow * 512 + col]) =
                        __nv_bfloat162{h0, h1};
                    *reinterpret_cast<__nv_bfloat162*>(&out2[(size_t)grow * 512 + 256 + col]) =
                        __nv_bfloat162{l0, l1};
                } else {
                    int R = grow >> 5;
                    int m = ((grow & 31) << 8) + col;
                    *reinterpret_cast<__nv_bfloat162*>(&out2[(size_t)R * 16384 + m]) =
                        __nv_bfloat162{h0, h1};
                    *reinterpret_cast<__nv_bfloat162*>(&out2[(size_t)R * 16384 + 8192 + m]) =
                        __nv_bfloat162{l0, l1};
                }
            }
        }
    }
}

// ======================= mlp1 GEMM (split-K=8, grid x=bn fast) =====================
__global__ __launch_bounds__(256, 2)
void mlp1_mma(const __nv_bfloat16* __restrict__ A2, const __nv_bfloat16* __restrict__ W2t,
              float* __restrict__ C) {
    extern __shared__ __nv_bfloat16 smdyn[];
    const uint32_t smbase = smem_u32(smdyn);

    const int tid = threadIdx.x;
    const int wid = tid >> 5, lane = tid & 31;
    const int wm = wid & 3, wn = wid >> 2;
    const int lr = lane >> 2, lq = lane & 3;
    const int bm = blockIdx.y * 128;
    const int bn = blockIdx.x * 128;
    const int g0 = blockIdx.z * 32;
    const int NCH = 32;

    const int r0 = tid >> 2;
    const int cb = (tid & 3) * 8;

    float acc[2][8][4];
#pragma unroll
    for (int i = 0; i < 2; i++)
#pragma unroll
        for (int j = 0; j < 8; j++)
#pragma unroll
            for (int t = 0; t < 4; t++) acc[i][j][t] = 0.0f;

    auto prefetch = [&](int i, int b) {
        int c = g0 + i;
        uint32_t sb = smbase + (uint32_t)b * STAGE_BYTES;
#pragma unroll
        for (int half = 0; half < 2; half++) {
            int r = r0 + half * 64;
            uint32_t so = (uint32_t)(r * TSTRIDE + cb) * 2;
            const __nv_bfloat16* Ap = A2 + (size_t)(bm + r) * 16384 + c * 32 + cb;
            const __nv_bfloat16* Bp = W2t + (size_t)(bn + r) * 16384 + c * 32 + cb;
            cpa16(sb + OFFB_AH + so, Ap);
            cpa16(sb + OFFB_AL + so, Ap + 8192);
            cpa16(sb + OFFB_BH + so, Bp);
            cpa16(sb + OFFB_BL + so, Bp + 8192);
        }
        CPA_COMMIT();
    };

    prefetch(0, 0);
    for (int i = 0; i < NCH; i++) {
        int b = i & 1;
        if (i + 1 < NCH) { prefetch(i + 1, b ^ 1); CPA_WAIT1(); }
        else             { CPA_WAIT0(); }
        __syncthreads();
        gemm_chunk(smbase + (uint32_t)b * STAGE_BYTES, wm, wn, lane, acc);
        __syncthreads();
    }

#pragma unroll
    for (int mt = 0; mt < 2; mt++) {
#pragma unroll
        for (int nt = 0; nt < 8; nt++) {
            int col = bn + wn * 64 + nt * 8 + lq * 2;
#pragma unroll
            for (int half = 0; half < 2; half++) {
                int row = bm + wm * 32 + mt * 16 + lr + half * 8;
                atomicAdd(&C[(size_t)row * 256 + col],     acc[mt][nt][half * 2 + 0]);
                atomicAdd(&C[(size_t)row * 256 + col + 1], acc[mt][nt][half * 2 + 1]);
            }
        }
    }
}

// ======================= tail kernels =======================
__global__ void mlp1_finalize(const float* __restrict__ M1, const float* __restrict__ b1,
                              const float* __restrict__ W2, const float* __restrict__ b2,
                              float* __restrict__ y) {
    int row = (blockIdx.x * blockDim.x + threadIdx.x) >> 5;
    int lane = threadIdx.x & 31;
    if (row >= MROW) return;
    float s = 0.0f;
    for (int c = lane; c < HD; c += 32)
        s += fmaxf(M1[row * HD + c] + b1[c], 0.0f) * W2[c];
#pragma unroll
    for (int o = 16; o; o >>= 1) s += __shfl_xor_sync(0xffffffffu, s, o);
    if (lane == 0) y[row] = s + b2[0];
}

// fused batchnorm + relu + mlp2 (single block, 256 threads)
__global__ void tail_kernel(const float* __restrict__ y, const float* __restrict__ gamma,
                            const float* __restrict__ beta,
                            const float* __restrict__ W1, const float* __restrict__ b1,
                            const float* __restrict__ W2, const float* __restrict__ b2,
                            float* __restrict__ out) {
    __shared__ float ybn[NB][HD];
    __shared__ float zs[NB][HD];
    int j = threadIdx.x;
    float v[NB];
    float m = 0.0f;
#pragma unroll
    for (int b = 0; b < NB; b++) { v[b] = y[b * HD + j]; m += v[b]; }
    m *= (1.0f / NB);
    float var = 0.0f;
#pragma unroll
    for (int b = 0; b < NB; b++) { float d = v[b] - m; var += d * d; }
    var *= (1.0f / NB);
    float inv = rsqrtf(var + 1e-5f) * gamma[j];
    float be = beta[j];
#pragma unroll
    for (int b = 0; b < NB; b++)
        ybn[b][j] = fmaxf((v[b] - m) * inv + be, 0.0f);
    __syncthreads();

    float z[NB];
#pragma unroll
    for (int b = 0; b < NB; b++) z[b] = b1[j];
    for (int hh = 0; hh < HD; hh++) {
        float w = W1[hh * HD + j];
#pragma unroll
        for (int b = 0; b < NB; b++) z[b] += ybn[b][hh] * w;
    }
#pragma unroll
    for (int b = 0; b < NB; b++) zs[b][j] = fmaxf(z[b], 0.0f);
    __syncthreads();

    if (j < NB * 8) {
        int b = j >> 3, o = j & 7;
        float s = b2[o];
        for (int jj = 0; jj < HD; jj++) s += zs[b][jj] * W2[jj * 8 + o];
        out[j] = s;
    }
}

// ======================= host launch =======================
extern "C" void kernel_launch(void* const* d_in, const int* in_sizes, int n_in,
                              void* d_out, int out_size) {
    const float* x    = (const float*)d_in[0];
    const float* g0   = (const float*)d_in[1];
    const float* g1   = (const float*)d_in[2];
    const float* g2   = (const float*)d_in[3];
    const int*   esrc = (const int*)d_in[4];
    const int*   edst = (const int*)d_in[5];
    const float* Wl0  = (const float*)d_in[6];
    const float* Wr0  = (const float*)d_in[7];
    const float* b0   = (const float*)d_in[8];
    const float* Wl1  = (const float*)d_in[9];
    const float* Wr1  = (const float*)d_in[10];
    const float* b1   = (const float*)d_in[11];
    const float* Wl2  = (const float*)d_in[12];
    const float* Wr2  = (const float*)d_in[13];
    const float* b2   = (const float*)d_in[14];
    const float* Wl3  = (const float*)d_in[15];
    const float* Wr3  = (const float*)d_in[16];
    const float* b3   = (const float*)d_in[17];
    const float* m1W1 = (const float*)d_in[18];
    const float* m1b1 = (const float*)d_in[19];
    const float* m1W2 = (const float*)d_in[20];
    const float* m1b2 = (const float*)d_in[21];
    const float* gam  = (const float*)d_in[22];
    const float* bet  = (const float*)d_in[23];
    const float* m2W1 = (const float*)d_in[24];
    const float* m2b1 = (const float*)d_in[25];
    const float* m2W2 = (const float*)d_in[26];
    const float* m2b2 = (const float*)d_in[27];

    __nv_bfloat16 *h02, *agg2, *h2A, *h2B, *m1A2, *w2, *m1w2;
    int *cnt;
    float *m1, *y;
    cudaGetSymbolAddress((void**)&h02, d_h02);
    cudaGetSymbolAddress((void**)&agg2, d_agg2);
    cudaGetSymbolAddress((void**)&h2A, d_h2A);
    cudaGetSymbolAddress((void**)&h2B, d_h2B);
    cudaGetSymbolAddress((void**)&m1A2, d_m1A2);
    cudaGetSymbolAddress((void**)&w2, d_w2);
    cudaGetSymbolAddress((void**)&m1w2, d_m1w2);
    cudaGetSymbolAddress((void**)&cnt, d_cnt);
    cudaGetSymbolAddress((void**)&m1, d_m1);
    cudaGetSymbolAddress((void**)&y, d_y);

    cudaFuncSetAttribute(sage_mma<128>, cudaFuncAttributeMaxDynamicSharedMemorySize, GEMM_SMEM_BYTES);
    cudaFuncSetAttribute(sage_mma<256>, cudaFuncAttributeMaxDynamicSharedMemorySize, GEMM_SMEM_BYTES);
    cudaFuncSetAttribute(mlp1_mma,      cudaFuncAttributeMaxDynamicSharedMemorySize, GEMM_SMEM_BYTES);

    __nv_bfloat16* wl[4] = {w2 + 0 * 256 * 512, w2 + 2 * 256 * 512, w2 + 4 * 256 * 512, w2 + 6 * 256 * 512};
    __nv_bfloat16* wr[4] = {w2 + 1 * 256 * 512, w2 + 3 * 256 * 512, w2 + 5 * 256 * 512, w2 + 7 * 256 * 512};

    // CSR build; launch order puts agg_csr<128> near capture slot
    cudaMemsetAsync(cnt, 0, NN * sizeof(int), 0);
    concat2_kernel<<<(NN * 128) / 256, 256>>>(x, g0, g1, g2);
    count_kernel<<<EE / 256, 256>>>(edst);
    scanA<<<64, 1024>>>();
    scanC<<<NN / 256, 256>>>();
    fill_kernel<<<EE / 256, 256>>>(esrc, edst);
    agg_csr<128><<<NN / 8, 256>>>(h02, agg2);

    // all weight conversions in one launch (before first sage_mma)
    conv_all<<<2496, dim3(32, 8)>>>(Wl0, Wr0, Wl1, Wr1, Wl2, Wr2, Wl3, Wr3, m1W1);

    sage_mma<128><<<dim3(2, NN / 128), 256, GEMM_SMEM_BYTES>>>(agg2, h02, wl[0], wr[0], b0, h2A, 0);
    agg_csr<256><<<NN / 8, 256>>>(h2A, agg2);
    sage_mma<256><<<dim3(2, NN / 128), 256, GEMM_SMEM_BYTES>>>(agg2, h2A, wl[1], wr[1], b1, h2B, 0);
    agg_csr<256><<<NN / 8, 256>>>(h2B, agg2);
    sage_mma<256><<<dim3(2, NN / 128), 256, GEMM_SMEM_BYTES>>>(agg2, h2B, wl[2], wr[2], b2, h2A, 0);
    agg_csr<256><<<NN / 8, 256>>>(h2A, agg2);
    sage_mma<256><<<dim3(2, NN / 128), 256, GEMM_SMEM_BYTES>>>(agg2, h2A, wl[3], wr[3], b3, m1A2, 1);

    cudaMemsetAsync(m1, 0, (size_t)MROW * HD * sizeof(float), 0);
    mlp1_mma<<<dim3(2, MROW / 128, 8), 256, GEMM_SMEM_BYTES>>>(m1A2, m1w2, m1);
    mlp1_finalize<<<MROW / 8, 256>>>(m1, m1b1, m1W2, m1b2, y);

    tail_kernel<<<1, 256>>>(y, gam, bet, m2W1, m2b1, m2W2, m2b2, (float*)d_out);
}

// round 17
// speedup vs baseline: 1.3469x; 1.0045x over previous
#include <cuda_runtime.h>
#include <cuda_bf16.h>
#include <cstdint>

#define NN   65536
#define EE   524288
#define DIN  128
#define HD   256
#define NB   8
#define MROW 2048   // NB * HD

// ======================= helpers =======================
__device__ __forceinline__ void split_bf16(float v, __nv_bfloat16& h, __nv_bfloat16& l) {
    h = __float2bfloat16(v);
    l = __float2bfloat16(v - __bfloat162float(h));
}

__device__ __forceinline__ float bflo(uint32_t v) { return __uint_as_float(v << 16); }
__device__ __forceinline__ float bfhi(uint32_t v) { return __uint_as_float(v & 0xffff0000u); }

__device__ __forceinline__ void split_pack(float v0, float v1, uint32_t& hw, uint32_t& lw) {
    __nv_bfloat16 h0, l0, h1, l1;
    split_bf16(v0, h0, l0);
    split_bf16(v1, h1, l1);
    hw = (uint32_t)__bfloat16_as_ushort(h0) | ((uint32_t)__bfloat16_as_ushort(h1) << 16);
    lw = (uint32_t)__bfloat16_as_ushort(l0) | ((uint32_t)__bfloat16_as_ushort(l1) << 16);
}

__device__ __forceinline__ void mma16816(float* c, const uint32_t* a, const uint32_t* b) {
    asm volatile(
        "mma.sync.aligned.m16n8k16.row.col.f32.bf16.bf16.f32 "
        "{%0,%1,%2,%3}, {%4,%5,%6,%7}, {%8,%9}, {%0,%1,%2,%3};"
        : "+f"(c[0]), "+f"(c[1]), "+f"(c[2]), "+f"(c[3])
        : "r"(a[0]), "r"(a[1]), "r"(a[2]), "r"(a[3]), "r"(b[0]), "r"(b[1]));
}

__device__ __forceinline__ void ldsm4(uint32_t* r, uint32_t addr) {
    asm volatile("ldmatrix.sync.aligned.m8n8.x4.shared.b16 {%0,%1,%2,%3}, [%4];"
        : "=r"(r[0]), "=r"(r[1]), "=r"(r[2]), "=r"(r[3]) : "r"(addr));
}

__device__ __forceinline__ uint32_t smem_u32(const void* p) {
    uint32_t a;
    asm("{ .reg .u64 t; cvta.to.shared.u64 t, %1; cvt.u32.u64 %0, t; }" : "=r"(a) : "l"(p));
    return a;
}

__device__ __forceinline__ void cpa16(uint32_t dst, const void* src) {
    asm volatile("cp.async.cg.shared.global [%0], [%1], 16;" :: "r"(dst), "l"(src));
}
#define CPA_COMMIT() asm volatile("cp.async.commit_group;" ::: "memory")
#define CPA_WAIT1()  asm volatile("cp.async.wait_group 1;" ::: "memory")
#define CPA_WAIT0()  asm volatile("cp.async.wait_group 0;" ::: "memory")

#define TSTRIDE 40
#define TE (128 * TSTRIDE)
#define BUFE (4 * TE)
#define STAGE_BYTES (BUFE * 2)              // 40960
#define GEMM_SMEM_BYTES (2 * STAGE_BYTES)   // 81920
#define OFFB_AH 0
#define OFFB_AL (TE * 2)
#define OFFB_BH (2 * TE * 2)
#define OFFB_BL (3 * TE * 2)

// ======================= static device scratch =======================
__device__ __nv_bfloat16 d_h02[NN * 256];
__device__ __nv_bfloat16 d_agg2[NN * 512];
__device__ __nv_bfloat16 d_h2A[NN * 512];
__device__ __nv_bfloat16 d_h2B[NN * 512];
__device__ __nv_bfloat16 d_m1A2[(size_t)MROW * 16384];
__device__ __nv_bfloat16 d_w2[8][256 * 512];
__device__ __nv_bfloat16 d_m1w2[(size_t)256 * 16384];
__device__ int   d_cnt[NN];
__device__ int   d_off[NN + 1];
__device__ int   d_cur[NN];
__device__ int   d_csr[EE];
__device__ int   d_bsum[64];
__device__ float d_invcnt[NN];
__device__ float d_m1[MROW * HD];
__device__ float d_y[MROW];

// ======================= small kernels =======================
__global__ void concat2_kernel(const float* __restrict__ x, const float* __restrict__ g0,
                               const float* __restrict__ g1, const float* __restrict__ g2) {
    int i = blockIdx.x * blockDim.x + threadIdx.x;
    if (i >= NN * 128) return;
    int n = i >> 7, j = i & 127;
    float v;
    if (j < 32)       v = x[n * 32 + j];
    else if (j < 64)  v = g0[n * 32 + (j - 32)];
    else if (j < 96)  v = g1[n * 32 + (j - 64)];
    else              v = g2[n * 32 + (j - 96)];
    __nv_bfloat16 h, l; split_bf16(v, h, l);
    d_h02[n * 256 + j]       = h;
    d_h02[n * 256 + 128 + j] = l;
}

__global__ void conv_all(const float* __restrict__ W0, const float* __restrict__ W1,
                         const float* __restrict__ W2, const float* __restrict__ W3,
                         const float* __restrict__ W4, const float* __restrict__ W5,
                         const float* __restrict__ W6, const float* __restrict__ W7,
                         const float* __restrict__ W8) {
    __shared__ float tile[32][33];
    int bid = blockIdx.x;
    const float* W;
    __nv_bfloat16* out;
    int K, t;
    if (bid < 64) {
        int m = bid >> 5; t = bid & 31; K = 128;
        W = m ? W1 : W0;
        out = d_w2[m];
    } else if (bid < 448) {
        int m = 2 + ((bid - 64) >> 6); t = (bid - 64) & 63; K = 256;
        switch (m) {
            case 2: W = W2; break; case 3: W = W3; break;
            case 4: W = W4; break; case 5: W = W5; break;
            case 6: W = W6; break; default: W = W7; break;
        }
        out = d_w2[m];
    } else {
        t = bid - 448; K = 8192;
        W = W8;
        out = d_m1w2;
    }
    int tilesK = K >> 5;
    int kb = (t % tilesK) * 32;
    int nb = (t / tilesK) * 32;
    int tx = threadIdx.x, ty = threadIdx.y;
#pragma unroll
    for (int i = 0; i < 4; i++) {
        int k = kb + ty + i * 8;
        tile[ty + i * 8][tx] = W[(size_t)k * 256 + nb + tx];
    }
    __syncthreads();
#pragma unroll
    for (int i = 0; i < 4; i++) {
        int n = nb + ty + i * 8;
        int k = kb + tx;
        float v = tile[tx][ty + i * 8];
        __nv_bfloat16 h, l; split_bf16(v, h, l);
        out[(size_t)n * 2 * K + k]     = h;
        out[(size_t)n * 2 * K + K + k] = l;
    }
}

__global__ void count_kernel(const int* __restrict__ dst) {
    int e = blockIdx.x * blockDim.x + threadIdx.x;
    if (e < EE) atomicAdd(&d_cnt[dst[e]], 1);
}

__global__ void scanA() {
    __shared__ int s[1024];
    int b = blockIdx.x, t = threadIdx.x;
    int i = b * 1024 + t;
    int c = d_cnt[i];
    s[t] = c;
    __syncthreads();
    for (int o = 1; o < 1024; o <<= 1) {
        int v = (t >= o) ? s[t - o] : 0;
        __syncthreads();
        s[t] += v;
        __syncthreads();
    }
    d_off[i] = s[t] - c;
    if (t == 1023) d_bsum[b] = s[t];
    d_invcnt[i] = 1.0f / fmaxf((float)c, 1.0f);
    d_cur[i] = 0;
}

__global__ void scanC() {
    __shared__ int boff;
    int i = blockIdx.x * blockDim.x + threadIdx.x;
    if (threadIdx.x == 0) {
        int lim = blockIdx.x >> 2;
        int s = 0;
        for (int j = 0; j < lim; j++) s += d_bsum[j];
        boff = s;
    }
    __syncthreads();
    d_off[i] += boff;
    if (i == 0) {
        int s = 0;
        for (int j = 0; j < 64; j++) s += d_bsum[j];
        d_off[NN] = s;
    }
}

__global__ void fill_kernel(const int* __restrict__ src, const int* __restrict__ dst) {
    int e = blockIdx.x * blockDim.x + threadIdx.x;
    if (e >= EE) return;
    int d = dst[e];
    int p = atomicAdd(&d_cur[d], 1);
    d_csr[d_off[d] + p] = src[e];
}

template <int D>
__global__ void agg_csr(const __nv_bfloat16* __restrict__ H2,
                        __nv_bfloat16* __restrict__ out2) {
    int w = (blockIdx.x * blockDim.x + threadIdx.x) >> 5;
    int lane = threadIdx.x & 31;
    if (w >= NN) return;
    int s0 = __ldg(&d_off[w]), s1 = __ldg(&d_off[w + 1]);
    constexpr int V = D / 32;
    constexpr int LOW = D / 2;
    float acc[V];
#pragma unroll
    for (int v = 0; v < V; v++) acc[v] = 0.0f;

    const uint32_t* H32 = reinterpret_cast<const uint32_t*>(H2);

    int p = s0;
    for (; p + 2 <= s1; p += 2) {
        int nbA = __ldg(&d_csr[p]);
        int nbB = __ldg(&d_csr[p + 1]);
        const uint32_t* pa = H32 + (size_t)nbA * D + lane * (V / 2);
        const uint32_t* pb = H32 + (size_t)nbB * D + lane * (V / 2);
        if (V == 8) {
            uint4 ha = *reinterpret_cast<const uint4*>(pa);
            uint4 la = *reinterpret_cast<const uint4*>(pa + LOW);
            uint4 hb = *reinterpret_cast<const uint4*>(pb);
            uint4 lb = *reinterpret_cast<const uint4*>(pb + LOW);
            acc[0] += (bflo(ha.x) + bflo(la.x)) + (bflo(hb.x) + bflo(lb.x));
            acc[1] += (bfhi(ha.x) + bfhi(la.x)) + (bfhi(hb.x) + bfhi(lb.x));
            acc[2] += (bflo(ha.y) + bflo(la.y)) + (bflo(hb.y) + bflo(lb.y));
            acc[3] += (bfhi(ha.y) + bfhi(la.y)) + (bfhi(hb.y) + bfhi(lb.y));
            acc[4] += (bflo(ha.z) + bflo(la.z)) + (bflo(hb.z) + bflo(lb.z));
            acc[5] += (bfhi(ha.z) + bfhi(la.z)) + (bfhi(hb.z) + bfhi(lb.z));
            acc[6] += (bflo(ha.w) + bflo(la.w)) + (bflo(hb.w) + bflo(lb.w));
            acc[7] += (bfhi(ha.w) + bfhi(la.w)) + (bfhi(hb.w) + bfhi(lb.w));
        } else {
            uint2 ha = *reinterpret_cast<const uint2*>(pa);
            uint2 la = *reinterpret_cast<const uint2*>(pa + LOW);
            uint2 hb = *reinterpret_cast<const uint2*>(pb);
            uint2 lb = *reinterpret_cast<const uint2*>(pb + LOW);
            acc[0] += (bflo(ha.x) + bflo(la.x)) + (bflo(hb.x) + bflo(lb.x));
            acc[1] += (bfhi(ha.x) + bfhi(la.x)) + (bfhi(hb.x) + bfhi(lb.x));
            acc[2] += (bflo(ha.y) + bflo(la.y)) + (bflo(hb.y) + bflo(lb.y));
            acc[3] += (bfhi(ha.y) + bfhi(la.y)) + (bfhi(hb.y) + bfhi(lb.y));
        }
    }
    if (p < s1) {
        int nb = __ldg(&d_csr[p]);
        const uint32_t* pa = H32 + (size_t)nb * D + lane * (V / 2);
        if (V == 8) {
            uint4 ha = *reinterpret_cast<const uint4*>(pa);
            uint4 la = *reinterpret_cast<const uint4*>(pa + LOW);
            acc[0] += bflo(ha.x) + bflo(la.x);
            acc[1] += bfhi(ha.x) + bfhi(la.x);
            acc[2] += bflo(ha.y) + bflo(la.y);
            acc[3] += bfhi(ha.y) + bfhi(la.y);
            acc[4] += bflo(ha.z) + bflo(la.z);
            acc[5] += bfhi(ha.z) + bfhi(la.z);
            acc[6] += bflo(ha.w) + bflo(la.w);
            acc[7] += bfhi(ha.w) + bfhi(la.w);
        } else {
            uint2 ha = *reinterpret_cast<const uint2*>(pa);
            uint2 la = *reinterpret_cast<const uint2*>(pa + LOW);
            acc[0] += bflo(ha.x) + bflo(la.x);
            acc[1] += bfhi(ha.x) + bfhi(la.x);
            acc[2] += bflo(ha.y) + bflo(la.y);
            acc[3] += bfhi(ha.y) + bfhi(la.y);
        }
    }

    float ic = d_invcnt[w];
    uint32_t* ob = reinterpret_cast<uint32_t*>(out2) + (size_t)w * D + lane * (V / 2);
    if (V == 8) {
        uint4 hv, lv;
        split_pack(acc[0] * ic, acc[1] * ic, hv.x, lv.x);
        split_pack(acc[2] * ic, acc[3] * ic, hv.y, lv.y);
        split_pack(acc[4] * ic, acc[5] * ic, hv.z, lv.z);
        split_pack(acc[6] * ic, acc[7] * ic, hv.w, lv.w);
        *reinterpret_cast<uint4*>(ob)       = hv;
        *reinterpret_cast<uint4*>(ob + LOW) = lv;
    } else {
        uint2 hv, lv;
        split_pack(acc[0] * ic, acc[1] * ic, hv.x, lv.x);
        split_pack(acc[2] * ic, acc[3] * ic, hv.y, lv.y);
        *reinterpret_cast<uint2*>(ob)       = hv;
        *reinterpret_cast<uint2*>(ob + LOW) = lv;
    }
}

// ======================= GEMM compute core =======================
__device__ __forceinline__ void gemm_chunk(uint32_t stage, int wm, int wn, int lane,
                                           float acc[2][8][4]) {
    const uint32_t aBase = stage + OFFB_AH +
        (uint32_t)(((wm * 32 + (lane & 15)) * TSTRIDE + (lane >> 4) * 8) * 2);
    const uint32_t bBase = stage + OFFB_BH +
        (uint32_t)(((wn * 64 + (lane >> 4) * 8 + (lane & 7)) * TSTRIDE + ((lane >> 3) & 1) * 8) * 2);
    const uint32_t loA = OFFB_AL - OFFB_AH;
    const uint32_t loB = OFFB_BL - OFFB_BH;

#pragma unroll
    for (int kk = 0; kk < 32; kk += 16) {
        uint32_t afh[2][4], afl[2][4];
#pragma unroll
        for (int mt = 0; mt < 2; mt++) {
            uint32_t a = aBase + (uint32_t)((mt * 16 * TSTRIDE + kk) * 2);
            ldsm4(afh[mt], a);
            ldsm4(afl[mt], a + loA);
        }
#pragma unroll
        for (int np = 0; np < 4; np++) {
            uint32_t b = bBase + (uint32_t)((np * 16 * TSTRIDE + kk) * 2);
            uint32_t bh[4], bl[4];
            ldsm4(bh, b);
            ldsm4(bl, b + loB);
#pragma unroll
            for (int mt = 0; mt < 2; mt++) {
                mma16816(acc[mt][np * 2],     afh[mt], &bh[0]);
                mma16816(acc[mt][np * 2 + 1], afh[mt], &bh[2]);
                mma16816(acc[mt][np * 2],     afl[mt], &bh[0]);
                mma16816(acc[mt][np * 2 + 1], afl[mt], &bh[2]);
                mma16816(acc[mt][np * 2],     afh[mt], &bl[0]);
                mma16816(acc[mt][np * 2 + 1], afh[mt], &bl[2]);
            }
        }
    }
}

// ======================= SAGE layer GEMM =======================
template <int K>
__global__ __launch_bounds__(256, 2)
void sage_mma(const __nv_bfloat16* __restrict__ agg2, const __nv_bfloat16* __restrict__ h2,
              const __nv_bfloat16* __restrict__ Wl2, const __nv_bfloat16* __restrict__ Wr2,
              const float* __restrict__ bias, __nv_bfloat16* __restrict__ out2, int mode) {
    extern __shared__ __nv_bfloat16 smdyn[];
    const uint32_t smbase = smem_u32(smdyn);

    const int tid = threadIdx.x;
    const int wid = tid >> 5, lane = tid & 31;
    const int wm = wid & 3, wn = wid >> 2;
    const int lr = lane >> 2, lq = lane & 3;
    const int bm = blockIdx.y * 128;
    const int bn = blockIdx.x * 128;
    constexpr int K2 = 2 * K;
    constexpr int CPS = K / 32;
    constexpr int NCH = 2 * CPS;

    const int r0 = tid >> 2;
    const int cb = (tid & 3) * 8;

    float acc[2][8][4];
#pragma unroll
    for (int i = 0; i < 2; i++)
#pragma unroll
        for (int j = 0; j < 8; j++)
#pragma unroll
            for (int t = 0; t < 4; t++) acc[i][j][t] = 0.0f;

    auto prefetch = [&](int ci, int b) {
        const __nv_bfloat16* Asrc = (ci < CPS) ? agg2 : h2;
        const __nv_bfloat16* Bsrc = (ci < CPS) ? Wl2 : Wr2;
        int c = ci & (CPS - 1);
        uint32_t sb = smbase + (uint32_t)b * STAGE_BYTES;
#pragma unroll
        for (int half = 0; half < 2; half++) {
            int r = r0 + half * 64;
            uint32_t so = (uint32_t)(r * TSTRIDE + cb) * 2;
            const __nv_bfloat16* Ap = Asrc + (size_t)(bm + r) * K2 + c * 32 + cb;
            const __nv_bfloat16* Bp = Bsrc + (size_t)(bn + r) * K2 + c * 32 + cb;
            cpa16(sb + OFFB_AH + so, Ap);
            cpa16(sb + OFFB_AL + so, Ap + K);
            cpa16(sb + OFFB_BH + so, Bp);
            cpa16(sb + OFFB_BL + so, Bp + K);
        }
        CPA_COMMIT();
    };

    prefetch(0, 0);
    for (int i = 0; i < NCH; i++) {
        int b = i & 1;
        if (i + 1 < NCH) { prefetch(i + 1, b ^ 1); CPA_WAIT1(); }
        else             { CPA_WAIT0(); }
        __syncthreads();
        gemm_chunk(smbase + (uint32_t)b * STAGE_BYTES, wm, wn, lane, acc);
        __syncthreads();
    }

#pragma unroll
    for (int mt = 0; mt < 2; mt++) {
#pragma unroll
        for (int nt = 0; nt < 8; nt++) {
            int col = bn + wn * 64 + nt * 8 + lq * 2;
            float bs0 = __ldg(&bias[col]), bs1 = __ldg(&bias[col + 1]);
#pragma unroll
            for (int half = 0; half < 2; half++) {
                int grow = bm + wm * 32 + mt * 16 + lr + half * 8;
                float v0 = fmaxf(acc[mt][nt][half * 2 + 0] + bs0, 0.0f);
                float v1 = fmaxf(acc[mt][nt][half * 2 + 1] + bs1, 0.0f);
                __nv_bfloat16 h0, l0, h1, l1;
                split_bf16(v0, h0, l0);
                split_bf16(v1, h1, l1);
                if (mode == 0) {
                    *reinterpret_cast<__nv_bfloat162*>(&out2[(size_t)grow * 512 + col]) =
                        __nv_bfloat162{h0, h1};
                    *reinterpret_cast<__nv_bfloat162*>(&out2[(size_t)grow * 512 + 256 + col]) =
                        __nv_bfloat162{l0, l1};
                } else {
                    int R = grow >> 5;
                    int m = ((grow & 31) << 8) + col;
                    *reinterpret_cast<__nv_bfloat162*>(&out2[(size_t)R * 16384 + m]) =
                        __nv_bfloat162{h0, h1};
                    *reinterpret_cast<__nv_bfloat162*>(&out2[(size_t)R * 16384 + 8192 + m]) =
                        __nv_bfloat162{l0, l1};
                }
            }
        }
    }
}

// ======================= mlp1 GEMM =======================
__global__ __launch_bounds__(256, 2)
void mlp1_mma(const __nv_bfloat16* __restrict__ A2, const __nv_bfloat16* __restrict__ W2t,
              float* __restrict__ C) {
    extern __shared__ __nv_bfloat16 smdyn[];
    const uint32_t smbase = smem_u32(smdyn);

    const int tid = threadIdx.x;
    const int wid = tid >> 5, lane = tid & 31;
    const int wm = wid & 3, wn = wid >> 2;
    const int lr = lane >> 2, lq = lane & 3;
    const int bm = blockIdx.y * 128;
    const int bn = blockIdx.x * 128;
    const int g0 = blockIdx.z * 32;
    const int NCH = 32;

    const int r0 = tid >> 2;
    const int cb = (tid & 3) * 8;

    float acc[2][8][4];
#pragma unroll
    for (int i = 0; i < 2; i++)
#pragma unroll
        for (int j = 0; j < 8; j++)
#pragma unroll
            for (int t = 0; t < 4; t++) acc[i][j][t] = 0.0f;

    auto prefetch = [&](int i, int b) {
        int c = g0 + i;
        uint32_t sb = smbase + (uint32_t)b * STAGE_BYTES;
#pragma unroll
        for (int half = 0; half < 2; half++) {
            int r = r0 + half * 64;
            uint32_t so = (uint32_t)(r * TSTRIDE + cb) * 2;
            const __nv_bfloat16* Ap = A2 + (size_t)(bm + r) * 16384 + c * 32 + cb;
            const __nv_bfloat16* Bp = W2t + (size_t)(bn + r) * 16384 + c * 32 + cb;
            cpa16(sb + OFFB_AH + so, Ap);
            cpa16(sb + OFFB_AL + so, Ap + 8192);
            cpa16(sb + OFFB_BH + so, Bp);
            cpa16(sb + OFFB_BL + so, Bp + 8192);
        }
        CPA_COMMIT();
    };

    prefetch(0, 0);
    for (int i = 0; i < NCH; i++) {
        int b = i & 1;
        if (i + 1 < NCH) { prefetch(i + 1, b ^ 1); CPA_WAIT1(); }
        else             { CPA_WAIT0(); }
        __syncthreads();
        gemm_chunk(smbase + (uint32_t)b * STAGE_BYTES, wm, wn, lane, acc);
        __syncthreads();
    }

#pragma unroll
    for (int mt = 0; mt < 2; mt++) {
#pragma unroll
        for (int nt = 0; nt < 8; nt++) {
            int col = bn + wn * 64 + nt * 8 + lq * 2;
#pragma unroll
            for (int half = 0; half < 2; half++) {
                int row = bm + wm * 32 + mt * 16 + lr + half * 8;
                atomicAdd(&C[(size_t)row * 256 + col],     acc[mt][nt][half * 2 + 0]);
                atomicAdd(&C[(size_t)row * 256 + col + 1], acc[mt][nt][half * 2 + 1]);
            }
        }
    }
}

// ======================= tail kernels =======================
__global__ void mlp1_finalize(const float* __restrict__ M1, const float* __restrict__ b1,
                              const float* __restrict__ W2, const float* __restrict__ b2,
                              float* __restrict__ y) {
    int row = (blockIdx.x * blockDim.x + threadIdx.x) >> 5;
    int lane = threadIdx.x & 31;
    if (row >= MROW) return;
    float s = 0.0f;
    for (int c = lane; c < HD; c += 32)
        s += fmaxf(M1[row * HD + c] + b1[c], 0.0f) * W2[c];
#pragma unroll
    for (int o = 16; o; o >>= 1) s += __shfl_xor_sync(0xffffffffu, s, o);
    if (lane == 0) y[row] = s + b2[0];
}

__global__ void tail_kernel(const float* __restrict__ y, const float* __restrict__ gamma,
                            const float* __restrict__ beta,
                            const float* __restrict__ W1, const float* __restrict__ b1,
                            const float* __restrict__ W2, const float* __restrict__ b2,
                            float* __restrict__ out) {
    __shared__ float ybn[NB][HD];
    __shared__ float zs[NB][HD];
    int j = threadIdx.x;
    float v[NB];
    float m = 0.0f;
#pragma unroll
    for (int b = 0; b < NB; b++) { v[b] = y[b * HD + j]; m += v[b]; }
    m *= (1.0f / NB);
    float var = 0.0f;
#pragma unroll
    for (int b = 0; b < NB; b++) { float d = v[b] - m; var += d * d; }
    var *= (1.0f / NB);
    float inv = rsqrtf(var + 1e-5f) * gamma[j];
    float be = beta[j];
#pragma unroll
    for (int b = 0; b < NB; b++)
        ybn[b][j] = fmaxf((v[b] - m) * inv + be, 0.0f);
    __syncthreads();

    float z[NB];
#pragma unroll
    for (int b = 0; b < NB; b++) z[b] = b1[j];
    for (int hh = 0; hh < HD; hh++) {
        float w = W1[hh * HD + j];
#pragma unroll
        for (int b = 0; b < NB; b++) z[b] += ybn[b][hh] * w;
    }
#pragma unroll
    for (int b = 0; b < NB; b++) zs[b][j] = fmaxf(z[b], 0.0f);
    __syncthreads();

    if (j < NB * 8) {
        int b = j >> 3, o = j & 7;
        float s = b2[o];
        for (int jj = 0; jj < HD; jj++) s += zs[b][jj] * W2[jj * 8 + o];
        out[j] = s;
    }
}

// ======================= host launch =======================
extern "C" void kernel_launch(void* const* d_in, const int* in_sizes, int n_in,
                              void* d_out, int out_size) {
    const float* x    = (const float*)d_in[0];
    const float* g0   = (const float*)d_in[1];
    const float* g1   = (const float*)d_in[2];
    const float* g2   = (const float*)d_in[3];
    const int*   esrc = (const int*)d_in[4];
    const int*   edst = (const int*)d_in[5];
    const float* Wl0  = (const float*)d_in[6];
    const float* Wr0  = (const float*)d_in[7];
    const float* b0   = (const float*)d_in[8];
    const float* Wl1  = (const float*)d_in[9];
    const float* Wr1  = (const float*)d_in[10];
    const float* b1   = (const float*)d_in[11];
    const float* Wl2  = (const float*)d_in[12];
    const float* Wr2  = (const float*)d_in[13];
    const float* b2   = (const float*)d_in[14];
    const float* Wl3  = (const float*)d_in[15];
    const float* Wr3  = (const float*)d_in[16];
    const float* b3   = (const float*)d_in[17];
    const float* m1W1 = (const float*)d_in[18];
    const float* m1b1 = (const float*)d_in[19];
    const float* m1W2 = (const float*)d_in[20];
    const float* m1b2 = (const float*)d_in[21];
    const float* gam  = (const float*)d_in[22];
    const float* bet  = (const float*)d_in[23];
    const float* m2W1 = (const float*)d_in[24];
    const float* m2b1 = (const float*)d_in[25];
    const float* m2W2 = (const float*)d_in[26];
    const float* m2b2 = (const float*)d_in[27];

    __nv_bfloat16 *h02, *agg2, *h2A, *h2B, *m1A2, *w2, *m1w2;
    int *cnt;
    float *m1, *y;
    cudaGetSymbolAddress((void**)&h02, d_h02);
    cudaGetSymbolAddress((void**)&agg2, d_agg2);
    cudaGetSymbolAddress((void**)&h2A, d_h2A);
    cudaGetSymbolAddress((void**)&h2B, d_h2B);
    cudaGetSymbolAddress((void**)&m1A2, d_m1A2);
    cudaGetSymbolAddress((void**)&w2, d_w2);
    cudaGetSymbolAddress((void**)&m1w2, d_m1w2);
    cudaGetSymbolAddress((void**)&cnt, d_cnt);
    cudaGetSymbolAddress((void**)&m1, d_m1);
    cudaGetSymbolAddress((void**)&y, d_y);

    cudaFuncSetAttribute(sage_mma<128>, cudaFuncAttributeMaxDynamicSharedMemorySize, GEMM_SMEM_BYTES);
    cudaFuncSetAttribute(sage_mma<256>, cudaFuncAttributeMaxDynamicSharedMemorySize, GEMM_SMEM_BYTES);
    cudaFuncSetAttribute(mlp1_mma,      cudaFuncAttributeMaxDynamicSharedMemorySize, GEMM_SMEM_BYTES);

    __nv_bfloat16* wl[4] = {w2 + 0 * 256 * 512, w2 + 2 * 256 * 512, w2 + 4 * 256 * 512, w2 + 6 * 256 * 512};
    __nv_bfloat16* wr[4] = {w2 + 1 * 256 * 512, w2 + 3 * 256 * 512, w2 + 5 * 256 * 512, w2 + 7 * 256 * 512};

    // ---- fork a second capture branch for independent prep work ----
    cudaStream_t s2;
    cudaStreamCreate(&s2);
    cudaEvent_t evFork, evJoin;
    cudaEventCreateWithFlags(&evFork, cudaEventDisableTiming);
    cudaEventCreateWithFlags(&evJoin, cudaEventDisableTiming);

    cudaEventRecord(evFork, 0);
    cudaStreamWaitEvent(s2, evFork, 0);

    // branch s2: independent of edge list
    concat2_kernel<<<(NN * 128) / 256, 256, 0, s2>>>(x, g0, g1, g2);
    conv_all<<<2496, dim3(32, 8), 0, s2>>>(Wl0, Wr0, Wl1, Wr1, Wl2, Wr2, Wl3, Wr3, m1W1);
    cudaMemsetAsync(m1, 0, (size_t)MROW * HD * sizeof(float), s2);
    cudaEventRecord(evJoin, s2);

    // main branch: CSR build
    cudaMemsetAsync(cnt, 0, NN * sizeof(int), 0);
    count_kernel<<<EE / 256, 256>>>(edst);
    scanA<<<64, 1024>>>();
    scanC<<<NN / 256, 256>>>();
    fill_kernel<<<EE / 256, 256>>>(esrc, edst);

    // join: everything below needs both branches
    cudaStreamWaitEvent(0, evJoin, 0);

    agg_csr<128><<<NN / 8, 256>>>(h02, agg2);
    sage_mma<128><<<dim3(2, NN / 128), 256, GEMM_SMEM_BYTES>>>(agg2, h02, wl[0], wr[0], b0, h2A, 0);
    agg_csr<256><<<NN / 8, 256>>>(h2A, agg2);
    sage_mma<256><<<dim3(2, NN / 128), 256, GEMM_SMEM_BYTES>>>(agg2, h2A, wl[1], wr[1], b1, h2B, 0);
    agg_csr<256><<<NN / 8, 256>>>(h2B, agg2);
    sage_mma<256><<<dim3(2, NN / 128), 256, GEMM_SMEM_BYTES>>>(agg2, h2B, wl[2], wr[2], b2, h2A, 0);
    agg_csr<256><<<NN / 8, 256>>>(h2A, agg2);
    sage_mma<256><<<dim3(2, NN / 128), 256, GEMM_SMEM_BYTES>>>(agg2, h2A, wl[3], wr[3], b3, m1A2, 1);

    mlp1_mma<<<dim3(2, MROW / 128, 8), 256, GEMM_SMEM_BYTES>>>(m1A2, m1w2, m1);
    mlp1_finalize<<<MROW / 8, 256>>>(m1, m1b1, m1W2, m1b2, y);

    tail_kernel<<<1, 256>>>(y, gam, bet, m2W1, m2b1, m2W2, m2b2, (float*)d_out);
}